// round 1
// baseline (speedup 1.0000x reference)
#include <cuda_runtime.h>
#include <cuda_bf16.h>
#include <math.h>

// ---------------- problem constants ----------------
#define BATCH 4
#define CIN   64
#define HH    256
#define WW    256
#define MID   128
#define HS    32
#define WSP   32
#define P     1024          // 32*32 spatial
#define LSEQ  128           // scan length (= MID channels)
#define DTR   64
#define NST   16
#define KDIM  96            // DTR + 2*NST

// ---------------- device scratch (no allocations allowed) ----------------
__device__ float g_h[BATCH*MID*P];        // residual stream (b,c,p)
__device__ float g_gn[BATCH*MID*P];
__device__ float g_xr[BATCH*2*MID*P];     // inproj output (xs | res)
__device__ float g_u[BATCH*MID*P];        // (b,l,d)
__device__ float g_xdbl[BATCH*LSEQ*KDIM];
__device__ float g_delta[BATCH*LSEQ*P];
__device__ float g_y[BATCH*LSEQ*P];
__device__ float g_co[BATCH*MID*P];       // conv_out result

__device__ __forceinline__ float silu_f(float v){ return v / (1.f + __expf(-v)); }

// ---------------- K0: stride-8 8x8 grouped conv ----------------
// grid (32 groups, 4 b), block (32,32). One thread -> 4 output channels of its group.
__global__ void k_downconv(const float* __restrict__ x, const float* __restrict__ w_in,
                           const float* __restrict__ b_in){
    int g = blockIdx.x, b = blockIdx.y;
    int tx = threadIdx.x, ty = threadIdx.y;
    __shared__ float sw[4][2][8][8];
    int tid = ty*32 + tx;
    if (tid < 512){
        int oc4 = tid >> 7;          // 0..3
        int rem = tid & 127;         // ic*64 + ky*8 + kx
        sw[oc4][rem>>6][(rem>>3)&7][rem&7] = w_in[(4*g + oc4)*128 + rem];
    }
    __syncthreads();
    float acc0=0.f, acc1=0.f, acc2=0.f, acc3=0.f;
    #pragma unroll
    for (int ic = 0; ic < 2; ic++){
        const float* xb = x + (((size_t)b*CIN + 2*g + ic)*HH + ty*8)*WW + tx*8;
        #pragma unroll
        for (int ky = 0; ky < 8; ky++){
            const float4* r = (const float4*)(xb + ky*WW);
            float4 v0 = r[0], v1 = r[1];
            float xv[8] = {v0.x,v0.y,v0.z,v0.w,v1.x,v1.y,v1.z,v1.w};
            #pragma unroll
            for (int kx = 0; kx < 8; kx++){
                float xvv = xv[kx];
                acc0 = fmaf(xvv, sw[0][ic][ky][kx], acc0);
                acc1 = fmaf(xvv, sw[1][ic][ky][kx], acc1);
                acc2 = fmaf(xvv, sw[2][ic][ky][kx], acc2);
                acc3 = fmaf(xvv, sw[3][ic][ky][kx], acc3);
            }
        }
    }
    int p = ty*32 + tx;
    g_h[(b*MID + 4*g + 0)*P + p] = acc0 + b_in[4*g+0];
    g_h[(b*MID + 4*g + 1)*P + p] = acc1 + b_in[4*g+1];
    g_h[(b*MID + 4*g + 2)*P + p] = acc2 + b_in[4*g+2];
    g_h[(b*MID + 4*g + 3)*P + p] = acc3 + b_in[4*g+3];
}

// ---------------- GroupNorm (2 groups of 64 ch) ----------------
// grid (2, 4b), block 1024
__global__ void k_groupnorm(const float* __restrict__ gamma, const float* __restrict__ beta){
    int grp = blockIdx.x, b = blockIdx.y;
    const float* base = g_h + (b*MID + grp*64)*P;
    float s = 0.f, s2 = 0.f;
    for (int i = threadIdx.x; i < 65536; i += 1024){
        float v = base[i]; s += v; s2 += v*v;
    }
    __shared__ float sh[64];
    #pragma unroll
    for (int o = 16; o; o >>= 1){
        s  += __shfl_xor_sync(0xffffffffu, s,  o);
        s2 += __shfl_xor_sync(0xffffffffu, s2, o);
    }
    int wid = threadIdx.x >> 5, lid = threadIdx.x & 31;
    if (lid == 0){ sh[wid] = s; sh[32+wid] = s2; }
    __syncthreads();
    if (threadIdx.x < 32){
        s = sh[threadIdx.x]; s2 = sh[32 + threadIdx.x];
        #pragma unroll
        for (int o = 16; o; o >>= 1){
            s  += __shfl_xor_sync(0xffffffffu, s,  o);
            s2 += __shfl_xor_sync(0xffffffffu, s2, o);
        }
        if (threadIdx.x == 0){ sh[0] = s; sh[1] = s2; }
    }
    __syncthreads();
    float mean = sh[0] * (1.f/65536.f);
    float var  = sh[1] * (1.f/65536.f) - mean*mean;
    float inv  = rsqrtf(var + 1e-5f);
    float* ob = g_gn + (b*MID + grp*64)*P;
    for (int i = threadIdx.x; i < 65536; i += 1024){
        int c = grp*64 + (i >> 10);
        ob[i] = (base[i] - mean) * inv * gamma[c] + beta[c];
    }
}

// ---------------- inproj 3x3 grouped conv (groups=64, 2 in, 4 out / group) ----------------
// grid 4*256 (b*256+oc), block 1024 (one pixel per thread)
__global__ void k_inproj(const float* __restrict__ w){
    int bc = blockIdx.x; int b = bc >> 8; int oc = bc & 255;
    int g = oc >> 2;
    __shared__ float s0[P], s1[P];
    int p = threadIdx.x;
    s0[p] = g_gn[(b*MID + 2*g    )*P + p];
    s1[p] = g_gn[(b*MID + 2*g + 1)*P + p];
    __syncthreads();
    float wr[18];
    #pragma unroll
    for (int i = 0; i < 18; i++) wr[i] = w[oc*18 + i];
    int y = p >> 5, x = p & 31;
    float acc = 0.f;
    #pragma unroll
    for (int ky = 0; ky < 3; ky++){
        int yy = y + ky - 1;
        if (yy < 0 || yy > 31) continue;
        #pragma unroll
        for (int kx = 0; kx < 3; kx++){
            int xx = x + kx - 1;
            if (xx < 0 || xx > 31) continue;
            int sp = yy*32 + xx;
            acc = fmaf(s0[sp], wr[ky*3+kx],     acc);
            acc = fmaf(s1[sp], wr[9 + ky*3+kx], acc);
        }
    }
    g_xr[(b*256 + oc)*P + p] = acc;
}

// ---------------- conv0 1x1 grouped (groups=64, 2 in, 2 out) + SiLU -> u ----------------
// grid 512 (b*128+oc), block 1024
__global__ void k_conv0(const float* __restrict__ w, const float* __restrict__ cb){
    int bc = blockIdx.x; int b = bc >> 7; int oc = bc & 127;
    int p = threadIdx.x;
    int g = oc >> 1;
    float v = g_xr[(b*256 + 2*g    )*P + p] * w[oc*2]
            + g_xr[(b*256 + 2*g + 1)*P + p] * w[oc*2+1]
            + cb[oc];
    g_u[bc*P + p] = silu_f(v);
}

// ---------------- x_dbl GEMM: (b,l,96) = u(b,l,1024) @ xproj^T(1024,96) ----------------
// grid (4 ltiles, 4 b), block 256. M-tile 32, N=96, K-tile 32.
__global__ void k_xdbl(const float* __restrict__ xproj){
    int lt = blockIdx.x, b = blockIdx.y;
    int tid = threadIdx.x;
    __shared__ float sU[32][33];
    __shared__ float sW[96][33];
    float acc[12];
    #pragma unroll
    for (int j = 0; j < 12; j++) acc[j] = 0.f;
    int m = tid >> 3, nb = (tid & 7) * 12;
    for (int kt = 0; kt < 32; kt++){
        int idx = tid;
        #pragma unroll
        for (int it = 0; it < 4; it++){
            int r = idx >> 5, c = idx & 31;
            sU[r][c] = g_u[(b*LSEQ + lt*32 + r)*P + kt*32 + c];
            idx += 256;
        }
        idx = tid;
        #pragma unroll
        for (int it = 0; it < 12; it++){
            int r = idx >> 5, c = idx & 31;
            sW[r][c] = xproj[r*P + kt*32 + c];
            idx += 256;
        }
        __syncthreads();
        #pragma unroll
        for (int kk = 0; kk < 32; kk++){
            float a = sU[m][kk];
            #pragma unroll
            for (int j = 0; j < 12; j++)
                acc[j] = fmaf(a, sW[nb+j][kk], acc[j]);
        }
        __syncthreads();
    }
    #pragma unroll
    for (int j = 0; j < 12; j++)
        g_xdbl[(b*LSEQ + lt*32 + m)*KDIM + nb + j] = acc[j];
}

// ---------------- delta proj + softplus: (b,l,1024) = xdbl[:, :, :64] @ dtw^T ----------------
// grid (16 dtiles, 2 ltiles, 4 b), block 256. tile: 64 l x 64 d, K=64.
__global__ void k_deltaproj(const float* __restrict__ dtw, const float* __restrict__ dtb){
    int dt = blockIdx.x, lt = blockIdx.y, b = blockIdx.z;
    int tid = threadIdx.x;
    __shared__ float sX[64][64];
    __shared__ float sW[64][65];
    int idx = tid;
    #pragma unroll
    for (int it = 0; it < 16; it++){
        int r = idx >> 6, c = idx & 63;
        sX[r][c] = g_xdbl[(b*LSEQ + lt*64 + r)*KDIM + c];
        sW[r][c] = dtw[(dt*64 + r)*64 + c];
        idx += 256;
    }
    __syncthreads();
    int lr = (tid >> 4) * 4, dc = (tid & 15) * 4;
    float acc[4][4] = {};
    #pragma unroll 8
    for (int k = 0; k < 64; k++){
        float a0 = sX[lr  ][k], a1 = sX[lr+1][k], a2 = sX[lr+2][k], a3 = sX[lr+3][k];
        float w0 = sW[dc  ][k], w1 = sW[dc+1][k], w2 = sW[dc+2][k], w3 = sW[dc+3][k];
        acc[0][0]=fmaf(a0,w0,acc[0][0]); acc[0][1]=fmaf(a0,w1,acc[0][1]); acc[0][2]=fmaf(a0,w2,acc[0][2]); acc[0][3]=fmaf(a0,w3,acc[0][3]);
        acc[1][0]=fmaf(a1,w0,acc[1][0]); acc[1][1]=fmaf(a1,w1,acc[1][1]); acc[1][2]=fmaf(a1,w2,acc[1][2]); acc[1][3]=fmaf(a1,w3,acc[1][3]);
        acc[2][0]=fmaf(a2,w0,acc[2][0]); acc[2][1]=fmaf(a2,w1,acc[2][1]); acc[2][2]=fmaf(a2,w2,acc[2][2]); acc[2][3]=fmaf(a2,w3,acc[2][3]);
        acc[3][0]=fmaf(a3,w0,acc[3][0]); acc[3][1]=fmaf(a3,w1,acc[3][1]); acc[3][2]=fmaf(a3,w2,acc[3][2]); acc[3][3]=fmaf(a3,w3,acc[3][3]);
    }
    #pragma unroll
    for (int i = 0; i < 4; i++){
        #pragma unroll
        for (int j = 0; j < 4; j++){
            int d = dt*64 + dc + j;
            float xv = acc[i][j] + dtb[d];
            float sp = fmaxf(xv, 0.f) + log1pf(expf(-fabsf(xv)));
            g_delta[(b*LSEQ + lt*64 + lr + i)*P + d] = sp;
        }
    }
}

// ---------------- selective scan ----------------
// grid (32 dtiles, 4 b), block 128. Thread = (d within tile of 32) x (n-quad of 4).
__global__ void k_scan(const float* __restrict__ alog, const float* __restrict__ dd){
    int dt = blockIdx.x, b = blockIdx.y;
    int tid = threadIdx.x;
    __shared__ float sB[LSEQ][16];
    __shared__ float sC[LSEQ][16];
    for (int e = tid; e < LSEQ*16; e += 128){
        int l = e >> 4, n = e & 15;
        const float* row = g_xdbl + (b*LSEQ + l)*KDIM;
        sB[l][n] = row[64 + n];
        sC[l][n] = row[80 + n];
    }
    __syncthreads();
    int d  = dt*32 + (tid >> 2);
    int ng = (tid & 3) * 4;
    float An[4], carry[4];
    #pragma unroll
    for (int j = 0; j < 4; j++){ An[j] = -expf(alog[d*16 + ng + j]); carry[j] = 0.f; }
    float Dd = dd[d];
    const float* up = g_u     + b*(LSEQ*P) + d;
    const float* dp = g_delta + b*(LSEQ*P) + d;
    float*       yp = g_y     + b*(LSEQ*P) + d;
    for (int l = 0; l < LSEQ; l++){
        float td = dp[l*P];
        float tu = up[l*P];
        float du = td * tu;
        float yv = 0.f;
        #pragma unroll
        for (int j = 0; j < 4; j++){
            float e = __expf(td * An[j]);
            carry[j] = fmaf(e, carry[j], du * sB[l][ng + j]);
            yv = fmaf(carry[j], sC[l][ng + j], yv);
        }
        yv += __shfl_xor_sync(0xffffffffu, yv, 1);
        yv += __shfl_xor_sync(0xffffffffu, yv, 2);
        if ((tid & 3) == 0) yp[l*P] = fmaf(tu, Dd, yv);
    }
}

// ---------------- gate + residual: h = y * silu(res) + h ----------------
// grid 512, block 1024
__global__ void k_combine(){
    int bc = blockIdx.x; int b = bc >> 7; int c = bc & 127;
    int p = threadIdx.x;
    float res = g_xr[(b*256 + MID + c)*P + p];
    int i = bc*P + p;
    g_h[i] = fmaf(g_y[i], silu_f(res), g_h[i]);
}

// ---------------- conv_out 1x1 grouped (groups=32, 4 in, 4 out) ----------------
// grid 512, block 1024
__global__ void k_convout(const float* __restrict__ wout, const float* __restrict__ bout){
    int bc = blockIdx.x; int b = bc >> 7; int oc = bc & 127;
    int p = threadIdx.x;
    int g = oc >> 2;
    const float* hb = g_h + (b*MID + 4*g)*P + p;
    const float* wp = wout + oc*4;
    float acc = bout[oc];
    acc = fmaf(hb[0*P], wp[0], acc);
    acc = fmaf(hb[1*P], wp[1], acc);
    acc = fmaf(hb[2*P], wp[2], acc);
    acc = fmaf(hb[3*P], wp[3], acc);
    g_co[bc*P + p] = acc;
}

// ---------------- x8 bilinear upsample (half-pixel, edge clamp) ----------------
// grid (512 bc, 256 oy), block 64; each thread writes one float4 (4 ox)
__global__ void k_upsample(float* __restrict__ out){
    int bc = blockIdx.x;
    int oy = blockIdx.y;
    __shared__ float r0[32], r1[32];
    float sy = (oy + 0.5f) * 0.125f - 0.5f;
    int iy0 = (int)floorf(sy);
    float fy = sy - (float)iy0;
    int iy0c = iy0 < 0 ? 0 : iy0;
    int iy1c = iy0 + 1 > 31 ? 31 : iy0 + 1;
    const float* src = g_co + bc*P;
    if (threadIdx.x < 32){
        r0[threadIdx.x] = src[iy0c*32 + threadIdx.x];
        r1[threadIdx.x] = src[iy1c*32 + threadIdx.x];
    }
    __syncthreads();
    int ox0 = threadIdx.x * 4;
    float v[4];
    #pragma unroll
    for (int j = 0; j < 4; j++){
        int ox = ox0 + j;
        float sx = (ox + 0.5f) * 0.125f - 0.5f;
        int ix0 = (int)floorf(sx);
        float fx = sx - (float)ix0;
        int ix0c = ix0 < 0 ? 0 : ix0;
        int ix1c = ix0 + 1 > 31 ? 31 : ix0 + 1;
        float t = r0[ix0c] + (r0[ix1c] - r0[ix0c]) * fx;
        float bm = r1[ix0c] + (r1[ix1c] - r1[ix0c]) * fx;
        v[j] = t + (bm - t) * fy;
    }
    float4 o4 = make_float4(v[0], v[1], v[2], v[3]);
    *(float4*)(out + ((size_t)bc*256 + oy)*256 + ox0) = o4;
}

// ---------------- host orchestration ----------------
static void mamba_block(const float* gng, const float* gnb, const float* ipw,
                        const float* cw, const float* cb, const float* xpw,
                        const float* dtw, const float* dtb,
                        const float* alog, const float* ddv){
    k_groupnorm<<<dim3(2,4), 1024>>>(gng, gnb);
    k_inproj<<<1024, 1024>>>(ipw);
    k_conv0<<<512, 1024>>>(cw, cb);
    k_xdbl<<<dim3(4,4), 256>>>(xpw);
    k_deltaproj<<<dim3(16,2,4), 256>>>(dtw, dtb);
    k_scan<<<dim3(32,4), 128>>>(alog, ddv);
    k_combine<<<512, 1024>>>();
}

extern "C" void kernel_launch(void* const* d_in, const int* in_sizes, int n_in,
                              void* d_out, int out_size){
    const float* x     = (const float*)d_in[0];
    const float* w_in  = (const float*)d_in[1];
    const float* b_in  = (const float*)d_in[2];
    const float* w_out = (const float*)d_in[23];
    const float* b_out = (const float*)d_in[24];
    float* out = (float*)d_out;

    k_downconv<<<dim3(32,4), dim3(32,32)>>>(x, w_in, b_in);

    mamba_block((const float*)d_in[3],  (const float*)d_in[4],  (const float*)d_in[5],
                (const float*)d_in[6],  (const float*)d_in[7],  (const float*)d_in[8],
                (const float*)d_in[9],  (const float*)d_in[10], (const float*)d_in[11],
                (const float*)d_in[12]);

    mamba_block((const float*)d_in[13], (const float*)d_in[14], (const float*)d_in[15],
                (const float*)d_in[16], (const float*)d_in[17], (const float*)d_in[18],
                (const float*)d_in[19], (const float*)d_in[20], (const float*)d_in[21],
                (const float*)d_in[22]);

    k_convout<<<512, 1024>>>(w_out, b_out);
    k_upsample<<<dim3(512,256), 64>>>(out);
}

// round 2
// speedup vs baseline: 2.2230x; 2.2230x over previous
#include <cuda_runtime.h>
#include <cuda_bf16.h>
#include <math.h>

// ---------------- problem constants ----------------
#define BATCH 4
#define CIN   64
#define HH    256
#define WW    256
#define MID   128
#define P     1024          // 32*32 spatial
#define LSEQ  128           // scan length (= MID channels)
#define DTR   64
#define NST   16
#define KDIM  96            // DTR + 2*NST

// ---------------- device scratch ----------------
__device__ float g_h[BATCH*MID*P];        // residual stream (b,c,p)
__device__ float g_gn[BATCH*MID*P];
__device__ float g_u[BATCH*MID*P];        // (b,l,d) post conv0+silu
__device__ float g_res[BATCH*MID*P];      // silu(res)
__device__ float g_xdbl[BATCH*LSEQ*KDIM]; // atomic-accumulated
__device__ float g_delta[BATCH*LSEQ*P];
__device__ float g_y[BATCH*LSEQ*P];

__device__ __forceinline__ float silu_f(float v){ return v / (1.f + __expf(-v)); }

// ---------------- K0: stride-8 8x8 grouped conv ----------------
__global__ void k_downconv(const float* __restrict__ x, const float* __restrict__ w_in,
                           const float* __restrict__ b_in){
    int g = blockIdx.x, b = blockIdx.y;
    int tx = threadIdx.x, ty = threadIdx.y;
    __shared__ float sw[4][2][8][8];
    int tid = ty*32 + tx;
    if (tid < 512){
        int oc4 = tid >> 7;
        int rem = tid & 127;
        sw[oc4][rem>>6][(rem>>3)&7][rem&7] = w_in[(4*g + oc4)*128 + rem];
    }
    __syncthreads();
    float acc0=0.f, acc1=0.f, acc2=0.f, acc3=0.f;
    #pragma unroll
    for (int ic = 0; ic < 2; ic++){
        const float* xb = x + (((size_t)b*CIN + 2*g + ic)*HH + ty*8)*WW + tx*8;
        #pragma unroll
        for (int ky = 0; ky < 8; ky++){
            const float4* r = (const float4*)(xb + ky*WW);
            float4 v0 = r[0], v1 = r[1];
            float xv[8] = {v0.x,v0.y,v0.z,v0.w,v1.x,v1.y,v1.z,v1.w};
            #pragma unroll
            for (int kx = 0; kx < 8; kx++){
                float xvv = xv[kx];
                acc0 = fmaf(xvv, sw[0][ic][ky][kx], acc0);
                acc1 = fmaf(xvv, sw[1][ic][ky][kx], acc1);
                acc2 = fmaf(xvv, sw[2][ic][ky][kx], acc2);
                acc3 = fmaf(xvv, sw[3][ic][ky][kx], acc3);
            }
        }
    }
    int p = ty*32 + tx;
    g_h[(b*MID + 4*g + 0)*P + p] = acc0 + b_in[4*g+0];
    g_h[(b*MID + 4*g + 1)*P + p] = acc1 + b_in[4*g+1];
    g_h[(b*MID + 4*g + 2)*P + p] = acc2 + b_in[4*g+2];
    g_h[(b*MID + 4*g + 3)*P + p] = acc3 + b_in[4*g+3];
}

// ---------------- GroupNorm (2 groups of 64 ch) + zero xdbl accumulator ----------------
// grid (2, 4b), block 1024
__global__ void k_groupnorm(const float* __restrict__ gamma, const float* __restrict__ beta){
    int grp = blockIdx.x, b = blockIdx.y;
    // zero 1/8 of the xdbl atomic accumulator (49152 floats / 8 = 6144)
    {
        int bz = b*2 + grp;
        float* z = g_xdbl + bz*6144;
        #pragma unroll
        for (int i = 0; i < 6; i++) z[i*1024 + threadIdx.x] = 0.f;
    }
    const float4* base4 = (const float4*)(g_h + (b*MID + grp*64)*P);
    float s = 0.f, s2 = 0.f;
    #pragma unroll 4
    for (int i = threadIdx.x; i < 16384; i += 1024){
        float4 v = base4[i];
        s  += v.x + v.y + v.z + v.w;
        s2 += v.x*v.x + v.y*v.y + v.z*v.z + v.w*v.w;
    }
    __shared__ float sh[64];
    #pragma unroll
    for (int o = 16; o; o >>= 1){
        s  += __shfl_xor_sync(0xffffffffu, s,  o);
        s2 += __shfl_xor_sync(0xffffffffu, s2, o);
    }
    int wid = threadIdx.x >> 5, lid = threadIdx.x & 31;
    if (lid == 0){ sh[wid] = s; sh[32+wid] = s2; }
    __syncthreads();
    if (threadIdx.x < 32){
        s = sh[threadIdx.x]; s2 = sh[32 + threadIdx.x];
        #pragma unroll
        for (int o = 16; o; o >>= 1){
            s  += __shfl_xor_sync(0xffffffffu, s,  o);
            s2 += __shfl_xor_sync(0xffffffffu, s2, o);
        }
        if (threadIdx.x == 0){ sh[0] = s; sh[1] = s2; }
    }
    __syncthreads();
    float mean = sh[0] * (1.f/65536.f);
    float var  = sh[1] * (1.f/65536.f) - mean*mean;
    float inv  = rsqrtf(var + 1e-5f);
    float4* ob4 = (float4*)(g_gn + (b*MID + grp*64)*P);
    #pragma unroll 4
    for (int i = threadIdx.x; i < 16384; i += 1024){
        int c = grp*64 + (i >> 8);
        float ga = gamma[c]*inv, be = beta[c] - mean*ga;
        float4 v = base4[i];
        v.x = v.x*ga + be; v.y = v.y*ga + be; v.z = v.z*ga + be; v.w = v.w*ga + be;
        ob4[i] = v;
    }
}

// ---------------- inproj 3x3 grouped conv fused with conv0(1x1)+SiLU / gate SiLU ----------------
// grid (64 groups, 4 b), block 1024 (one pixel per thread). Group g -> inproj oc 4g..4g+3.
__global__ void k_inproj_fused(const float* __restrict__ w, const float* __restrict__ cw,
                               const float* __restrict__ cb){
    int g = blockIdx.x, b = blockIdx.y;
    __shared__ float s0[P], s1[P];
    __shared__ float sW[4][18];
    int p = threadIdx.x;
    s0[p] = g_gn[(b*MID + 2*g    )*P + p];
    s1[p] = g_gn[(b*MID + 2*g + 1)*P + p];
    if (p < 72) ((float*)sW)[p] = w[g*72 + p];
    __syncthreads();
    int y = p >> 5, x = p & 31;
    float acc[4] = {0.f,0.f,0.f,0.f};
    #pragma unroll
    for (int ky = 0; ky < 3; ky++){
        int yy = y + ky - 1;
        if (yy < 0 || yy > 31) continue;
        #pragma unroll
        for (int kx = 0; kx < 3; kx++){
            int xx = x + kx - 1;
            if (xx < 0 || xx > 31) continue;
            int sp = yy*32 + xx;
            float v0 = s0[sp], v1 = s1[sp];
            #pragma unroll
            for (int j = 0; j < 4; j++){
                acc[j] = fmaf(v0, sW[j][ky*3+kx],     acc[j]);
                acc[j] = fmaf(v1, sW[j][9 + ky*3+kx], acc[j]);
            }
        }
    }
    if (g < 32){
        // xs channels c = 4g+j ; conv0 group (2g + j>>1) mixes pairs (acc0,acc1) and (acc2,acc3)
        #pragma unroll
        for (int j = 0; j < 4; j++){
            int c = 4*g + j;
            float lo = (j < 2) ? acc[0] : acc[2];
            float hi = (j < 2) ? acc[1] : acc[3];
            float v = fmaf(lo, cw[c*2], fmaf(hi, cw[c*2+1], cb[c]));
            g_u[(b*MID + c)*P + p] = silu_f(v);
        }
    } else {
        #pragma unroll
        for (int j = 0; j < 4; j++){
            int c = 4*g + j - 128;
            g_res[(b*MID + c)*P + p] = silu_f(acc[j]);
        }
    }
}

// ---------------- x_dbl GEMM, K-split x8 with atomic epilogue ----------------
// grid (4 lt, 4 b, 8 ks), block 256. Tile: 32 l x 96 n, K-chunk 128 (4 sub-tiles of 32).
__global__ void k_xdbl(const float* __restrict__ xproj){
    int lt = blockIdx.x, b = blockIdx.y, ks = blockIdx.z;
    int tid = threadIdx.x;
    __shared__ float sU[32][33];
    __shared__ float sW[32][100];   // [k][n], padded (4-aligned for float4 reads)
    float acc[12];
    #pragma unroll
    for (int j = 0; j < 12; j++) acc[j] = 0.f;
    int m = tid >> 3, nb = (tid & 7) * 12;
    for (int kt = 0; kt < 4; kt++){
        int kbase = ks*128 + kt*32;
        {
            int idx = tid;
            #pragma unroll
            for (int it = 0; it < 4; it++){
                int r = idx >> 5, c = idx & 31;
                sU[r][c] = g_u[(b*LSEQ + lt*32 + r)*P + kbase + c];
                idx += 256;
            }
            idx = tid;
            #pragma unroll
            for (int it = 0; it < 12; it++){
                int r = idx >> 5, c = idx & 31;     // r = n row, c = k col
                sW[c][r] = xproj[r*P + kbase + c];
                idx += 256;
            }
        }
        __syncthreads();
        #pragma unroll
        for (int kk = 0; kk < 32; kk++){
            float a = sU[m][kk];
            float4 w0 = *(const float4*)&sW[kk][nb];
            float4 w1 = *(const float4*)&sW[kk][nb+4];
            float4 w2 = *(const float4*)&sW[kk][nb+8];
            acc[0]=fmaf(a,w0.x,acc[0]); acc[1]=fmaf(a,w0.y,acc[1]); acc[2]=fmaf(a,w0.z,acc[2]); acc[3]=fmaf(a,w0.w,acc[3]);
            acc[4]=fmaf(a,w1.x,acc[4]); acc[5]=fmaf(a,w1.y,acc[5]); acc[6]=fmaf(a,w1.z,acc[6]); acc[7]=fmaf(a,w1.w,acc[7]);
            acc[8]=fmaf(a,w2.x,acc[8]); acc[9]=fmaf(a,w2.y,acc[9]); acc[10]=fmaf(a,w2.z,acc[10]); acc[11]=fmaf(a,w2.w,acc[11]);
        }
        __syncthreads();
    }
    float* dst = g_xdbl + (b*LSEQ + lt*32 + m)*KDIM + nb;
    #pragma unroll
    for (int j = 0; j < 12; j++) atomicAdd(dst + j, acc[j]);
}

// ---------------- delta proj + softplus ----------------
// grid (16 dt, 2 lt, 4 b), block 256. tile: 64 l x 64 d, K=64.
__global__ void k_deltaproj(const float* __restrict__ dtw, const float* __restrict__ dtb){
    int dt = blockIdx.x, lt = blockIdx.y, b = blockIdx.z;
    int tid = threadIdx.x;
    __shared__ float sX[64][64];
    __shared__ float sW[64][65];
    int idx = tid;
    #pragma unroll
    for (int it = 0; it < 16; it++){
        int r = idx >> 6, c = idx & 63;
        sX[r][c] = g_xdbl[(b*LSEQ + lt*64 + r)*KDIM + c];
        sW[r][c] = dtw[(dt*64 + r)*64 + c];
        idx += 256;
    }
    __syncthreads();
    int lr = (tid >> 4) * 4, dc = (tid & 15) * 4;
    float acc[4][4] = {};
    #pragma unroll 8
    for (int k = 0; k < 64; k++){
        float a0 = sX[lr  ][k], a1 = sX[lr+1][k], a2 = sX[lr+2][k], a3 = sX[lr+3][k];
        float w0 = sW[dc  ][k], w1 = sW[dc+1][k], w2 = sW[dc+2][k], w3 = sW[dc+3][k];
        acc[0][0]=fmaf(a0,w0,acc[0][0]); acc[0][1]=fmaf(a0,w1,acc[0][1]); acc[0][2]=fmaf(a0,w2,acc[0][2]); acc[0][3]=fmaf(a0,w3,acc[0][3]);
        acc[1][0]=fmaf(a1,w0,acc[1][0]); acc[1][1]=fmaf(a1,w1,acc[1][1]); acc[1][2]=fmaf(a1,w2,acc[1][2]); acc[1][3]=fmaf(a1,w3,acc[1][3]);
        acc[2][0]=fmaf(a2,w0,acc[2][0]); acc[2][1]=fmaf(a2,w1,acc[2][1]); acc[2][2]=fmaf(a2,w2,acc[2][2]); acc[2][3]=fmaf(a2,w3,acc[2][3]);
        acc[3][0]=fmaf(a3,w0,acc[3][0]); acc[3][1]=fmaf(a3,w1,acc[3][1]); acc[3][2]=fmaf(a3,w2,acc[3][2]); acc[3][3]=fmaf(a3,w3,acc[3][3]);
    }
    #pragma unroll
    for (int i = 0; i < 4; i++){
        #pragma unroll
        for (int j = 0; j < 4; j++){
            int d = dt*64 + dc + j;
            float xv = acc[i][j] + dtb[d];
            float sp = fmaxf(xv, 0.f) + __logf(1.f + __expf(-fabsf(xv)));
            g_delta[(b*LSEQ + lt*64 + lr + i)*P + d] = sp;
        }
    }
}

// ---------------- selective scan (SMEM-staged) ----------------
// grid (32 dt, 4 b), block 128. Thread = (d in tile of 32) x (n-quad of 4).
__global__ void k_scan(const float* __restrict__ alog, const float* __restrict__ dd){
    int dt = blockIdx.x, b = blockIdx.y;
    int tid = threadIdx.x;
    __shared__ float sB[LSEQ][16];
    __shared__ float sC[LSEQ][16];
    __shared__ float sD[LSEQ][32];
    __shared__ float sUt[LSEQ][32];
    __shared__ float sY[LSEQ][32];
    for (int e = tid; e < LSEQ*16; e += 128){
        int l = e >> 4, n = e & 15;
        const float* row = g_xdbl + (b*LSEQ + l)*KDIM;
        sB[l][n] = row[64 + n];
        sC[l][n] = row[80 + n];
    }
    for (int e = tid; e < LSEQ*32; e += 128){
        int l = e >> 5, dj = e & 31;
        sD [l][dj] = g_delta[(b*LSEQ + l)*P + dt*32 + dj];
        sUt[l][dj] = g_u    [(b*LSEQ + l)*P + dt*32 + dj];
    }
    __syncthreads();
    int dloc = tid >> 2;
    int d  = dt*32 + dloc;
    int ng = (tid & 3) * 4;
    float An[4], carry[4];
    #pragma unroll
    for (int j = 0; j < 4; j++){ An[j] = -expf(alog[d*16 + ng + j]); carry[j] = 0.f; }
    float Dd = dd[d];
    #pragma unroll 4
    for (int l = 0; l < LSEQ; l++){
        float td = sD[l][dloc];
        float tu = sUt[l][dloc];
        float du = td * tu;
        float yv = 0.f;
        #pragma unroll
        for (int j = 0; j < 4; j++){
            float e = __expf(td * An[j]);
            carry[j] = fmaf(e, carry[j], du * sB[l][ng + j]);
            yv = fmaf(carry[j], sC[l][ng + j], yv);
        }
        yv += __shfl_xor_sync(0xffffffffu, yv, 1);
        yv += __shfl_xor_sync(0xffffffffu, yv, 2);
        if ((tid & 3) == 0) sY[l][dloc] = fmaf(tu, Dd, yv);
    }
    __syncthreads();
    for (int e = tid; e < LSEQ*32; e += 128){
        int l = e >> 5, dj = e & 31;
        g_y[(b*LSEQ + l)*P + dt*32 + dj] = sY[l][dj];
    }
}

// ---------------- gate + residual (float4) ----------------
// grid 128, block 1024: one float4 per thread over 512K floats
__global__ void k_combine(){
    int i = blockIdx.x*1024 + threadIdx.x;
    float4 h = ((const float4*)g_h)[i];
    float4 y = ((const float4*)g_y)[i];
    float4 r = ((const float4*)g_res)[i];
    h.x = fmaf(y.x, r.x, h.x);
    h.y = fmaf(y.y, r.y, h.y);
    h.z = fmaf(y.z, r.z, h.z);
    h.w = fmaf(y.w, r.w, h.w);
    ((float4*)g_h)[i] = h;
}

// ---------------- conv_out 1x1 grouped fused with x8 bilinear upsample ----------------
// grid (128 oc, 4 b), block 256
__global__ void k_convout_up(const float* __restrict__ wout, const float* __restrict__ bout,
                             float* __restrict__ out){
    int oc = blockIdx.x, b = blockIdx.y;
    int g = oc >> 2;
    int tid = threadIdx.x;
    __shared__ float sCo[1024];
    const float* hb = g_h + (size_t)(b*MID + 4*g)*P;
    float w0 = wout[oc*4], w1 = wout[oc*4+1], w2 = wout[oc*4+2], w3 = wout[oc*4+3];
    float bias = bout[oc];
    float4 a = ((const float4*)hb)[tid];
    float4 c1 = ((const float4*)(hb+P))[tid];
    float4 c2 = ((const float4*)(hb+2*P))[tid];
    float4 c3 = ((const float4*)(hb+3*P))[tid];
    float4 r;
    r.x = bias + a.x*w0 + c1.x*w1 + c2.x*w2 + c3.x*w3;
    r.y = bias + a.y*w0 + c1.y*w1 + c2.y*w2 + c3.y*w3;
    r.z = bias + a.z*w0 + c1.z*w1 + c2.z*w2 + c3.z*w3;
    r.w = bias + a.w*w0 + c1.w*w1 + c2.w*w2 + c3.w*w3;
    ((float4*)sCo)[tid] = r;
    __syncthreads();

    int rx = tid & 63, ry = tid >> 6;
    int ox0 = rx * 4;
    float fx[4]; int ix0[4], ix1[4];
    #pragma unroll
    for (int j = 0; j < 4; j++){
        float sx = (ox0 + j + 0.5f) * 0.125f - 0.5f;
        int i0 = (int)floorf(sx);
        fx[j] = sx - (float)i0;
        ix0[j] = i0 < 0 ? 0 : i0;
        ix1[j] = (i0 + 1 > 31) ? 31 : i0 + 1;
    }
    float* obase = out + ((size_t)(b*MID + oc))*256*256;
    #pragma unroll 4
    for (int t = 0; t < 64; t++){
        int oy = t*4 + ry;
        float sy = (oy + 0.5f) * 0.125f - 0.5f;
        int iy = (int)floorf(sy);
        float fy = sy - (float)iy;
        int iy0 = iy < 0 ? 0 : iy;
        int iy1 = (iy + 1 > 31) ? 31 : iy + 1;
        const float* r0 = sCo + iy0*32;
        const float* r1 = sCo + iy1*32;
        float4 v;
        float t0, t1;
        t0 = r0[ix0[0]] + (r0[ix1[0]] - r0[ix0[0]]) * fx[0];
        t1 = r1[ix0[0]] + (r1[ix1[0]] - r1[ix0[0]]) * fx[0];
        v.x = t0 + (t1 - t0) * fy;
        t0 = r0[ix0[1]] + (r0[ix1[1]] - r0[ix0[1]]) * fx[1];
        t1 = r1[ix0[1]] + (r1[ix1[1]] - r1[ix0[1]]) * fx[1];
        v.y = t0 + (t1 - t0) * fy;
        t0 = r0[ix0[2]] + (r0[ix1[2]] - r0[ix0[2]]) * fx[2];
        t1 = r1[ix0[2]] + (r1[ix1[2]] - r1[ix0[2]]) * fx[2];
        v.z = t0 + (t1 - t0) * fy;
        t0 = r0[ix0[3]] + (r0[ix1[3]] - r0[ix0[3]]) * fx[3];
        t1 = r1[ix0[3]] + (r1[ix1[3]] - r1[ix0[3]]) * fx[3];
        v.w = t0 + (t1 - t0) * fy;
        ((float4*)(obase + oy*256))[rx] = v;
    }
}

// ---------------- host orchestration ----------------
static void mamba_block(const float* gng, const float* gnb, const float* ipw,
                        const float* cw, const float* cb, const float* xpw,
                        const float* dtw, const float* dtb,
                        const float* alog, const float* ddv){
    k_groupnorm<<<dim3(2,4), 1024>>>(gng, gnb);
    k_inproj_fused<<<dim3(64,4), 1024>>>(ipw, cw, cb);
    k_xdbl<<<dim3(4,4,8), 256>>>(xpw);
    k_deltaproj<<<dim3(16,2,4), 256>>>(dtw, dtb);
    k_scan<<<dim3(32,4), 128>>>(alog, ddv);
    k_combine<<<128, 1024>>>();
}

extern "C" void kernel_launch(void* const* d_in, const int* in_sizes, int n_in,
                              void* d_out, int out_size){
    const float* x     = (const float*)d_in[0];
    const float* w_in  = (const float*)d_in[1];
    const float* b_in  = (const float*)d_in[2];
    const float* w_out = (const float*)d_in[23];
    const float* b_out = (const float*)d_in[24];
    float* out = (float*)d_out;

    k_downconv<<<dim3(32,4), dim3(32,32)>>>(x, w_in, b_in);

    mamba_block((const float*)d_in[3],  (const float*)d_in[4],  (const float*)d_in[5],
                (const float*)d_in[6],  (const float*)d_in[7],  (const float*)d_in[8],
                (const float*)d_in[9],  (const float*)d_in[10], (const float*)d_in[11],
                (const float*)d_in[12]);

    mamba_block((const float*)d_in[13], (const float*)d_in[14], (const float*)d_in[15],
                (const float*)d_in[16], (const float*)d_in[17], (const float*)d_in[18],
                (const float*)d_in[19], (const float*)d_in[20], (const float*)d_in[21],
                (const float*)d_in[22]);

    k_convout_up<<<dim3(128,4), 256>>>(w_out, b_out, out);
}

// round 3
// speedup vs baseline: 2.4573x; 1.1054x over previous
#include <cuda_runtime.h>
#include <cuda_bf16.h>
#include <math.h>

// ---------------- problem constants ----------------
#define BATCH 4
#define CIN   64
#define HH    256
#define WW    256
#define MID   128
#define P     1024          // 32*32 spatial
#define LSEQ  128           // scan length (= MID channels)
#define NST   16
#define KDIM  96            // DTR + 2*NST

// ---------------- device scratch ----------------
__device__ float  g_h[BATCH*MID*P];          // residual stream (b,c,p)
__device__ float  g_u[BATCH*MID*P];          // (b,l,d) post conv0+silu
__device__ float  g_res[BATCH*MID*P];        // silu(res)
__device__ float  g_xdbl[2][BATCH*LSEQ*KDIM];// atomic-accumulated, double buffered
__device__ float  g_delta[BATCH*LSEQ*P];
__device__ float2 g_gnp0[BATCH*2*16];        // downconv GN partials (s, s2)
__device__ float2 g_gnp1[BATCH*2*32];        // scan GN partials

__device__ __forceinline__ float silu_f(float v){ return v / (1.f + __expf(-v)); }

// ---------------- K0: stride-8 8x8 grouped conv + GN0 partial stats + zero xdbl[0] ----------------
// grid (32 groups, 4 b), block (32,32)
__global__ void k_downconv(const float* __restrict__ x, const float* __restrict__ w_in,
                           const float* __restrict__ b_in){
    int g = blockIdx.x, b = blockIdx.y;
    int tx = threadIdx.x, ty = threadIdx.y;
    int tid = ty*32 + tx;
    // zero my slice of g_xdbl[0] (49152 floats / 128 blocks = 384)
    {
        int base = (b*32 + g)*384;
        if (tid < 384) g_xdbl[0][base + tid] = 0.f;
    }
    __shared__ float sw[4][2][8][8];
    if (tid < 512){
        int oc4 = tid >> 7;
        int rem = tid & 127;
        sw[oc4][rem>>6][(rem>>3)&7][rem&7] = w_in[(4*g + oc4)*128 + rem];
    }
    __syncthreads();
    float acc0=0.f, acc1=0.f, acc2=0.f, acc3=0.f;
    #pragma unroll
    for (int ic = 0; ic < 2; ic++){
        const float* xb = x + (((size_t)b*CIN + 2*g + ic)*HH + ty*8)*WW + tx*8;
        #pragma unroll
        for (int ky = 0; ky < 8; ky++){
            const float4* r = (const float4*)(xb + ky*WW);
            float4 v0 = r[0], v1 = r[1];
            float xv[8] = {v0.x,v0.y,v0.z,v0.w,v1.x,v1.y,v1.z,v1.w};
            #pragma unroll
            for (int kx = 0; kx < 8; kx++){
                float xvv = xv[kx];
                acc0 = fmaf(xvv, sw[0][ic][ky][kx], acc0);
                acc1 = fmaf(xvv, sw[1][ic][ky][kx], acc1);
                acc2 = fmaf(xvv, sw[2][ic][ky][kx], acc2);
                acc3 = fmaf(xvv, sw[3][ic][ky][kx], acc3);
            }
        }
    }
    acc0 += b_in[4*g+0]; acc1 += b_in[4*g+1]; acc2 += b_in[4*g+2]; acc3 += b_in[4*g+3];
    int p = ty*32 + tx;
    g_h[(b*MID + 4*g + 0)*P + p] = acc0;
    g_h[(b*MID + 4*g + 1)*P + p] = acc1;
    g_h[(b*MID + 4*g + 2)*P + p] = acc2;
    g_h[(b*MID + 4*g + 3)*P + p] = acc3;
    // GN0 partial stats (channels 4g..4g+3 all in group g>>4)
    float s  = acc0 + acc1 + acc2 + acc3;
    float s2 = acc0*acc0 + acc1*acc1 + acc2*acc2 + acc3*acc3;
    __shared__ float red[64];
    #pragma unroll
    for (int o = 16; o; o >>= 1){
        s  += __shfl_xor_sync(0xffffffffu, s,  o);
        s2 += __shfl_xor_sync(0xffffffffu, s2, o);
    }
    int wid = tid >> 5, lid = tid & 31;
    if (lid == 0){ red[wid] = s; red[32+wid] = s2; }
    __syncthreads();
    if (tid < 32){
        s = red[tid]; s2 = red[32+tid];
        #pragma unroll
        for (int o = 16; o; o >>= 1){
            s  += __shfl_xor_sync(0xffffffffu, s,  o);
            s2 += __shfl_xor_sync(0xffffffffu, s2, o);
        }
        if (tid == 0){
            int grp = g >> 4;
            g_gnp0[(b*2 + grp)*16 + (g & 15)] = make_float2(s, s2);
        }
    }
}

// ---------------- inproj: GN-apply + 3x3 grouped conv + conv0(1x1)+SiLU / gate SiLU ----------------
// grid (64 groups, 4 b), block 1024
__global__ void k_inproj(const float* __restrict__ w, const float* __restrict__ cw,
                         const float* __restrict__ cb, const float* __restrict__ gamma,
                         const float* __restrict__ beta, int blk){
    int g = blockIdx.x, b = blockIdx.y;
    int grp = g >> 5;
    __shared__ float s0[P], s1[P];
    __shared__ float sW[4][18];
    __shared__ float sMI[2];
    int p = threadIdx.x;
    if (p < 32){
        int npart = blk ? 32 : 16;
        float2 v = make_float2(0.f, 0.f);
        if (p < npart) v = blk ? g_gnp1[(b*2+grp)*32 + p] : g_gnp0[(b*2+grp)*16 + p];
        float s = v.x, s2 = v.y;
        #pragma unroll
        for (int o = 16; o; o >>= 1){
            s  += __shfl_xor_sync(0xffffffffu, s,  o);
            s2 += __shfl_xor_sync(0xffffffffu, s2, o);
        }
        if (p == 0){
            float mean = s * (1.f/65536.f);
            float var  = s2 * (1.f/65536.f) - mean*mean;
            sMI[0] = mean;
            sMI[1] = rsqrtf(var + 1e-5f);
        }
    }
    if (p < 72) ((float*)sW)[p] = w[g*72 + p];
    __syncthreads();
    float mean = sMI[0], inv = sMI[1];
    int c0 = 2*g, c1 = 2*g + 1;
    float ga0 = gamma[c0]*inv, be0 = beta[c0] - mean*ga0;
    float ga1 = gamma[c1]*inv, be1 = beta[c1] - mean*ga1;
    s0[p] = g_h[(b*MID + c0)*P + p]*ga0 + be0;
    s1[p] = g_h[(b*MID + c1)*P + p]*ga1 + be1;
    __syncthreads();
    int y = p >> 5, x = p & 31;
    float acc[4] = {0.f,0.f,0.f,0.f};
    #pragma unroll
    for (int ky = 0; ky < 3; ky++){
        int yy = y + ky - 1;
        if (yy < 0 || yy > 31) continue;
        #pragma unroll
        for (int kx = 0; kx < 3; kx++){
            int xx = x + kx - 1;
            if (xx < 0 || xx > 31) continue;
            int sp = yy*32 + xx;
            float v0 = s0[sp], v1 = s1[sp];
            #pragma unroll
            for (int j = 0; j < 4; j++){
                acc[j] = fmaf(v0, sW[j][ky*3+kx],     acc[j]);
                acc[j] = fmaf(v1, sW[j][9 + ky*3+kx], acc[j]);
            }
        }
    }
    if (g < 32){
        #pragma unroll
        for (int j = 0; j < 4; j++){
            int c = 4*g + j;
            float lo = (j < 2) ? acc[0] : acc[2];
            float hi = (j < 2) ? acc[1] : acc[3];
            float v = fmaf(lo, cw[c*2], fmaf(hi, cw[c*2+1], cb[c]));
            g_u[(b*MID + c)*P + p] = silu_f(v);
        }
    } else {
        #pragma unroll
        for (int j = 0; j < 4; j++){
            int c = 4*g + j - 128;
            g_res[(b*MID + c)*P + p] = silu_f(acc[j]);
        }
    }
}

// ---------------- x_dbl GEMM, K-split x16 with atomic epilogue ----------------
// grid (4 lt, 4 b, 16 ks), block 256. Tile: 32 l x 96 n, K-chunk 64 (2 sub-tiles of 32).
__global__ void k_xdbl(const float* __restrict__ xproj, int blk){
    int lt = blockIdx.x, b = blockIdx.y, ks = blockIdx.z;
    int tid = threadIdx.x;
    __shared__ float sU[32][33];
    __shared__ float sW[32][100];   // [k][n]
    float acc[12];
    #pragma unroll
    for (int j = 0; j < 12; j++) acc[j] = 0.f;
    int m = tid >> 3, nb = (tid & 7) * 12;
    #pragma unroll
    for (int kt = 0; kt < 2; kt++){
        int kbase = ks*64 + kt*32;
        {
            int idx = tid;
            #pragma unroll
            for (int it = 0; it < 4; it++){
                int r = idx >> 5, c = idx & 31;
                sU[r][c] = g_u[(b*LSEQ + lt*32 + r)*P + kbase + c];
                idx += 256;
            }
            idx = tid;
            #pragma unroll
            for (int it = 0; it < 12; it++){
                int r = idx >> 5, c = idx & 31;
                sW[c][r] = xproj[r*P + kbase + c];
                idx += 256;
            }
        }
        __syncthreads();
        #pragma unroll
        for (int kk = 0; kk < 32; kk++){
            float a = sU[m][kk];
            float4 w0 = *(const float4*)&sW[kk][nb];
            float4 w1 = *(const float4*)&sW[kk][nb+4];
            float4 w2 = *(const float4*)&sW[kk][nb+8];
            acc[0]=fmaf(a,w0.x,acc[0]); acc[1]=fmaf(a,w0.y,acc[1]); acc[2]=fmaf(a,w0.z,acc[2]); acc[3]=fmaf(a,w0.w,acc[3]);
            acc[4]=fmaf(a,w1.x,acc[4]); acc[5]=fmaf(a,w1.y,acc[5]); acc[6]=fmaf(a,w1.z,acc[6]); acc[7]=fmaf(a,w1.w,acc[7]);
            acc[8]=fmaf(a,w2.x,acc[8]); acc[9]=fmaf(a,w2.y,acc[9]); acc[10]=fmaf(a,w2.z,acc[10]); acc[11]=fmaf(a,w2.w,acc[11]);
        }
        __syncthreads();
    }
    float* dst = g_xdbl[blk] + (b*LSEQ + lt*32 + m)*KDIM + nb;
    #pragma unroll
    for (int j = 0; j < 12; j++) atomicAdd(dst + j, acc[j]);
}

// ---------------- delta proj + softplus ----------------
// grid (16 dt, 4 lt, 4 b), block 256. tile: 32 l x 64 d, K=64. 2l x 4d per thread.
__global__ void k_deltaproj(const float* __restrict__ dtw, const float* __restrict__ dtb, int blk){
    int dt = blockIdx.x, lt = blockIdx.y, b = blockIdx.z;
    int tid = threadIdx.x;
    __shared__ float sX[32][64];
    __shared__ float sW[64][65];    // [k][d]
    {
        int idx = tid;
        #pragma unroll
        for (int it = 0; it < 8; it++){
            int r = idx >> 6, c = idx & 63;
            sX[r][c] = g_xdbl[blk][(b*LSEQ + lt*32 + r)*KDIM + c];
            idx += 256;
        }
        idx = tid;
        #pragma unroll
        for (int it = 0; it < 16; it++){
            int r = idx >> 6, c = idx & 63;   // r = d row, c = k col
            sW[c][r] = dtw[(dt*64 + r)*64 + c];
            idx += 256;
        }
    }
    __syncthreads();
    int lr = (tid >> 4) * 2, dc = (tid & 15) * 4;
    float acc[2][4] = {};
    #pragma unroll 8
    for (int k = 0; k < 64; k++){
        float a0 = sX[lr  ][k], a1 = sX[lr+1][k];
        float w0 = sW[k][dc], w1 = sW[k][dc+1], w2 = sW[k][dc+2], w3 = sW[k][dc+3];
        acc[0][0]=fmaf(a0,w0,acc[0][0]); acc[0][1]=fmaf(a0,w1,acc[0][1]); acc[0][2]=fmaf(a0,w2,acc[0][2]); acc[0][3]=fmaf(a0,w3,acc[0][3]);
        acc[1][0]=fmaf(a1,w0,acc[1][0]); acc[1][1]=fmaf(a1,w1,acc[1][1]); acc[1][2]=fmaf(a1,w2,acc[1][2]); acc[1][3]=fmaf(a1,w3,acc[1][3]);
    }
    float b0 = dtb[dt*64+dc], b1 = dtb[dt*64+dc+1], b2 = dtb[dt*64+dc+2], b3 = dtb[dt*64+dc+3];
    #pragma unroll
    for (int i = 0; i < 2; i++){
        float4 o;
        float xv;
        xv = acc[i][0] + b0; o.x = fmaxf(xv,0.f) + __logf(1.f + __expf(-fabsf(xv)));
        xv = acc[i][1] + b1; o.y = fmaxf(xv,0.f) + __logf(1.f + __expf(-fabsf(xv)));
        xv = acc[i][2] + b2; o.z = fmaxf(xv,0.f) + __logf(1.f + __expf(-fabsf(xv)));
        xv = acc[i][3] + b3; o.w = fmaxf(xv,0.f) + __logf(1.f + __expf(-fabsf(xv)));
        *(float4*)&g_delta[(b*LSEQ + lt*32 + lr + i)*P + dt*64 + dc] = o;
    }
}

// ---------------- selective scan + gate/residual combine + GN1 partial stats ----------------
// grid (32 dt, 4 b), block 128. Thread = (d in tile of 32) x (n-quad of 4).
__global__ void k_scan(const float* __restrict__ alog, const float* __restrict__ dd, int blk){
    int dt = blockIdx.x, b = blockIdx.y;
    int tid = threadIdx.x;
    // zero my slice of g_xdbl[1] for the next mamba block
    if (blk == 0){
        int base = (b*32 + dt)*384;
        #pragma unroll
        for (int i = 0; i < 3; i++) g_xdbl[1][base + i*128 + tid] = 0.f;
    }
    __shared__ float sB[LSEQ][16];
    __shared__ float sC[LSEQ][16];
    __shared__ float sD[LSEQ][32];
    __shared__ float sUt[LSEQ][32];
    __shared__ float sY[LSEQ][32];
    for (int e = tid; e < LSEQ*16; e += 128){
        int l = e >> 4, n = e & 15;
        const float* row = g_xdbl[blk] + (b*LSEQ + l)*KDIM;
        sB[l][n] = row[64 + n];
        sC[l][n] = row[80 + n];
    }
    for (int e = tid; e < LSEQ*32; e += 128){
        int l = e >> 5, dj = e & 31;
        sD [l][dj] = g_delta[(b*LSEQ + l)*P + dt*32 + dj];
        sUt[l][dj] = g_u    [(b*LSEQ + l)*P + dt*32 + dj];
    }
    __syncthreads();
    int dloc = tid >> 2;
    int d  = dt*32 + dloc;
    int ng = (tid & 3) * 4;
    float An[4], carry[4];
    #pragma unroll
    for (int j = 0; j < 4; j++){ An[j] = -expf(alog[d*16 + ng + j]); carry[j] = 0.f; }
    float Dd = dd[d];
    #pragma unroll 4
    for (int l = 0; l < LSEQ; l++){
        float td = sD[l][dloc];
        float tu = sUt[l][dloc];
        float du = td * tu;
        float yv = 0.f;
        #pragma unroll
        for (int j = 0; j < 4; j++){
            float e = __expf(td * An[j]);
            carry[j] = fmaf(e, carry[j], du * sB[l][ng + j]);
            yv = fmaf(carry[j], sC[l][ng + j], yv);
        }
        yv += __shfl_xor_sync(0xffffffffu, yv, 1);
        yv += __shfl_xor_sync(0xffffffffu, yv, 2);
        if ((tid & 3) == 0) sY[l][dloc] = fmaf(tu, Dd, yv);
    }
    __syncthreads();
    // combine: h += y * silu(res); accumulate GN1 partial stats per group
    float s[2] = {0.f, 0.f}, s2[2] = {0.f, 0.f};
    for (int e = tid; e < LSEQ*32; e += 128){
        int l = e >> 5, dj = e & 31;
        int idx = (b*LSEQ + l)*P + dt*32 + dj;
        float h = fmaf(sY[l][dj], g_res[idx], g_h[idx]);
        g_h[idx] = h;
        int grp = l >> 6;
        s[grp] += h; s2[grp] += h*h;
    }
    if (blk == 0){
        __shared__ float red[4][4];
        #pragma unroll
        for (int o = 16; o; o >>= 1){
            s[0]  += __shfl_xor_sync(0xffffffffu, s[0],  o);
            s[1]  += __shfl_xor_sync(0xffffffffu, s[1],  o);
            s2[0] += __shfl_xor_sync(0xffffffffu, s2[0], o);
            s2[1] += __shfl_xor_sync(0xffffffffu, s2[1], o);
        }
        int wid = tid >> 5;
        if ((tid & 31) == 0){
            red[wid][0] = s[0]; red[wid][1] = s2[0];
            red[wid][2] = s[1]; red[wid][3] = s2[1];
        }
        __syncthreads();
        if (tid == 0){
            float a0=0,a1=0,a2=0,a3=0;
            #pragma unroll
            for (int i2 = 0; i2 < 4; i2++){ a0+=red[i2][0]; a1+=red[i2][1]; a2+=red[i2][2]; a3+=red[i2][3]; }
            g_gnp1[(b*2 + 0)*32 + dt] = make_float2(a0, a1);
            g_gnp1[(b*2 + 1)*32 + dt] = make_float2(a2, a3);
        }
    }
}

// ---------------- conv_out 1x1 grouped fused with x8 bilinear upsample ----------------
// grid (128 oc, 4 b), block 256
__global__ void k_convout_up(const float* __restrict__ wout, const float* __restrict__ bout,
                             float* __restrict__ out){
    int oc = blockIdx.x, b = blockIdx.y;
    int g = oc >> 2;
    int tid = threadIdx.x;
    __shared__ float sCo[1024];
    const float* hb = g_h + (size_t)(b*MID + 4*g)*P;
    float w0 = wout[oc*4], w1 = wout[oc*4+1], w2 = wout[oc*4+2], w3 = wout[oc*4+3];
    float bias = bout[oc];
    float4 a = ((const float4*)hb)[tid];
    float4 c1 = ((const float4*)(hb+P))[tid];
    float4 c2 = ((const float4*)(hb+2*P))[tid];
    float4 c3 = ((const float4*)(hb+3*P))[tid];
    float4 r;
    r.x = bias + a.x*w0 + c1.x*w1 + c2.x*w2 + c3.x*w3;
    r.y = bias + a.y*w0 + c1.y*w1 + c2.y*w2 + c3.y*w3;
    r.z = bias + a.z*w0 + c1.z*w1 + c2.z*w2 + c3.z*w3;
    r.w = bias + a.w*w0 + c1.w*w1 + c2.w*w2 + c3.w*w3;
    ((float4*)sCo)[tid] = r;
    __syncthreads();

    int rx = tid & 63, ry = tid >> 6;
    int ox0 = rx * 4;
    float fx[4]; int ix0[4], ix1[4];
    #pragma unroll
    for (int j = 0; j < 4; j++){
        float sx = (ox0 + j + 0.5f) * 0.125f - 0.5f;
        int i0 = (int)floorf(sx);
        fx[j] = sx - (float)i0;
        ix0[j] = i0 < 0 ? 0 : i0;
        ix1[j] = (i0 + 1 > 31) ? 31 : i0 + 1;
    }
    float* obase = out + ((size_t)(b*MID + oc))*256*256;
    #pragma unroll 4
    for (int t = 0; t < 64; t++){
        int oy = t*4 + ry;
        float sy = (oy + 0.5f) * 0.125f - 0.5f;
        int iy = (int)floorf(sy);
        float fy = sy - (float)iy;
        int iy0 = iy < 0 ? 0 : iy;
        int iy1 = (iy + 1 > 31) ? 31 : iy + 1;
        const float* r0 = sCo + iy0*32;
        const float* r1 = sCo + iy1*32;
        float4 v;
        float t0, t1;
        t0 = r0[ix0[0]] + (r0[ix1[0]] - r0[ix0[0]]) * fx[0];
        t1 = r1[ix0[0]] + (r1[ix1[0]] - r1[ix0[0]]) * fx[0];
        v.x = t0 + (t1 - t0) * fy;
        t0 = r0[ix0[1]] + (r0[ix1[1]] - r0[ix0[1]]) * fx[1];
        t1 = r1[ix0[1]] + (r1[ix1[1]] - r1[ix0[1]]) * fx[1];
        v.y = t0 + (t1 - t0) * fy;
        t0 = r0[ix0[2]] + (r0[ix1[2]] - r0[ix0[2]]) * fx[2];
        t1 = r1[ix0[2]] + (r1[ix1[2]] - r1[ix0[2]]) * fx[2];
        v.z = t0 + (t1 - t0) * fy;
        t0 = r0[ix0[3]] + (r0[ix1[3]] - r0[ix0[3]]) * fx[3];
        t1 = r1[ix0[3]] + (r1[ix1[3]] - r1[ix0[3]]) * fx[3];
        v.w = t0 + (t1 - t0) * fy;
        ((float4*)(obase + oy*256))[rx] = v;
    }
}

// ---------------- host orchestration ----------------
static void mamba_block(int blk, const float* gng, const float* gnb, const float* ipw,
                        const float* cw, const float* cb, const float* xpw,
                        const float* dtw, const float* dtb,
                        const float* alog, const float* ddv){
    k_inproj<<<dim3(64,4), 1024>>>(ipw, cw, cb, gng, gnb, blk);
    k_xdbl<<<dim3(4,4,16), 256>>>(xpw, blk);
    k_deltaproj<<<dim3(16,4,4), 256>>>(dtw, dtb, blk);
    k_scan<<<dim3(32,4), 128>>>(alog, ddv, blk);
}

extern "C" void kernel_launch(void* const* d_in, const int* in_sizes, int n_in,
                              void* d_out, int out_size){
    const float* x     = (const float*)d_in[0];
    const float* w_in  = (const float*)d_in[1];
    const float* b_in  = (const float*)d_in[2];
    const float* w_out = (const float*)d_in[23];
    const float* b_out = (const float*)d_in[24];
    float* out = (float*)d_out;

    k_downconv<<<dim3(32,4), dim3(32,32)>>>(x, w_in, b_in);

    mamba_block(0,
                (const float*)d_in[3],  (const float*)d_in[4],  (const float*)d_in[5],
                (const float*)d_in[6],  (const float*)d_in[7],  (const float*)d_in[8],
                (const float*)d_in[9],  (const float*)d_in[10], (const float*)d_in[11],
                (const float*)d_in[12]);

    mamba_block(1,
                (const float*)d_in[13], (const float*)d_in[14], (const float*)d_in[15],
                (const float*)d_in[16], (const float*)d_in[17], (const float*)d_in[18],
                (const float*)d_in[19], (const float*)d_in[20], (const float*)d_in[21],
                (const float*)d_in[22]);

    k_convout_up<<<dim3(128,4), 256>>>(w_out, b_out, out);
}

// round 4
// speedup vs baseline: 2.7622x; 1.1241x over previous
#include <cuda_runtime.h>
#include <cuda_bf16.h>
#include <math.h>

// ---------------- problem constants ----------------
#define BATCH 4
#define CIN   64
#define HH    256
#define WW    256
#define MID   128
#define P     1024          // 32*32 spatial (= d_model for the scan)
#define LSEQ  128           // scan length (= MID channels)
#define NST   16
#define KDIM  96            // DTRANK(64) + 2*NST

// ---------------- device scratch ----------------
__device__ float  g_h[BATCH*MID*P];          // residual stream (b,c,p)
__device__ float  g_u[BATCH*MID*P];          // (b,l,d) post conv0+silu
__device__ float  g_res[BATCH*MID*P];        // silu(res)
__device__ __align__(16) float g_xdbl[BATCH*LSEQ*KDIM]; // direct-stored (no atomics)
__device__ float2 g_gnp0[BATCH*2*16];        // downconv GN partials (s, s2)
__device__ float2 g_gnp1[BATCH*2*32];        // scan GN partials

__device__ __forceinline__ float silu_f(float v){ return v / (1.f + __expf(-v)); }

// ---------------- K0: stride-8 8x8 grouped conv + GN0 partial stats ----------------
// grid (32 groups, 4 b), block (32,32)
__global__ void k_downconv(const float* __restrict__ x, const float* __restrict__ w_in,
                           const float* __restrict__ b_in){
    int g = blockIdx.x, b = blockIdx.y;
    int tx = threadIdx.x, ty = threadIdx.y;
    int tid = ty*32 + tx;
    __shared__ float sw[4][2][8][8];
    if (tid < 512){
        int oc4 = tid >> 7;
        int rem = tid & 127;
        sw[oc4][rem>>6][(rem>>3)&7][rem&7] = w_in[(4*g + oc4)*128 + rem];
    }
    __syncthreads();
    float acc0=0.f, acc1=0.f, acc2=0.f, acc3=0.f;
    #pragma unroll
    for (int ic = 0; ic < 2; ic++){
        const float* xb = x + (((size_t)b*CIN + 2*g + ic)*HH + ty*8)*WW + tx*8;
        #pragma unroll
        for (int ky = 0; ky < 8; ky++){
            const float4* r = (const float4*)(xb + ky*WW);
            float4 v0 = r[0], v1 = r[1];
            float xv[8] = {v0.x,v0.y,v0.z,v0.w,v1.x,v1.y,v1.z,v1.w};
            #pragma unroll
            for (int kx = 0; kx < 8; kx++){
                float xvv = xv[kx];
                acc0 = fmaf(xvv, sw[0][ic][ky][kx], acc0);
                acc1 = fmaf(xvv, sw[1][ic][ky][kx], acc1);
                acc2 = fmaf(xvv, sw[2][ic][ky][kx], acc2);
                acc3 = fmaf(xvv, sw[3][ic][ky][kx], acc3);
            }
        }
    }
    acc0 += b_in[4*g+0]; acc1 += b_in[4*g+1]; acc2 += b_in[4*g+2]; acc3 += b_in[4*g+3];
    int p = ty*32 + tx;
    g_h[(b*MID + 4*g + 0)*P + p] = acc0;
    g_h[(b*MID + 4*g + 1)*P + p] = acc1;
    g_h[(b*MID + 4*g + 2)*P + p] = acc2;
    g_h[(b*MID + 4*g + 3)*P + p] = acc3;
    float s  = acc0 + acc1 + acc2 + acc3;
    float s2 = acc0*acc0 + acc1*acc1 + acc2*acc2 + acc3*acc3;
    __shared__ float red[64];
    #pragma unroll
    for (int o = 16; o; o >>= 1){
        s  += __shfl_xor_sync(0xffffffffu, s,  o);
        s2 += __shfl_xor_sync(0xffffffffu, s2, o);
    }
    int wid = tid >> 5, lid = tid & 31;
    if (lid == 0){ red[wid] = s; red[32+wid] = s2; }
    __syncthreads();
    if (tid < 32){
        s = red[tid]; s2 = red[32+tid];
        #pragma unroll
        for (int o = 16; o; o >>= 1){
            s  += __shfl_xor_sync(0xffffffffu, s,  o);
            s2 += __shfl_xor_sync(0xffffffffu, s2, o);
        }
        if (tid == 0){
            int grp = g >> 4;
            g_gnp0[(b*2 + grp)*16 + (g & 15)] = make_float2(s, s2);
        }
    }
}

// ---------------- inproj: GN-apply + 3x3 conv + conv0+SiLU + x_dbl rows / gate SiLU ----------------
// grid (64 groups, 4 b), block 1024. Block owns all 1024 pixels of its 4 channels, so it
// computes its 4 complete x_dbl rows (K=1024 reduction fully in-block, no atomics).
__global__ void k_inproj(const float* __restrict__ w, const float* __restrict__ cw,
                         const float* __restrict__ cb, const float* __restrict__ gamma,
                         const float* __restrict__ beta, const float* __restrict__ xproj,
                         int blk){
    int g = blockIdx.x, b = blockIdx.y;
    int grp = g >> 5;
    __shared__ float s0[P], s1[P];
    __shared__ float sU[4][P];
    __shared__ float sW[4][18];
    __shared__ float sMI[2];
    int p = threadIdx.x;
    if (p < 32){
        int npart = blk ? 32 : 16;
        float2 v = make_float2(0.f, 0.f);
        if (p < npart) v = blk ? g_gnp1[(b*2+grp)*32 + p] : g_gnp0[(b*2+grp)*16 + p];
        float s = v.x, s2 = v.y;
        #pragma unroll
        for (int o = 16; o; o >>= 1){
            s  += __shfl_xor_sync(0xffffffffu, s,  o);
            s2 += __shfl_xor_sync(0xffffffffu, s2, o);
        }
        if (p == 0){
            float mean = s * (1.f/65536.f);
            float var  = s2 * (1.f/65536.f) - mean*mean;
            sMI[0] = mean;
            sMI[1] = rsqrtf(var + 1e-5f);
        }
    }
    if (p < 72) ((float*)sW)[p] = w[g*72 + p];
    __syncthreads();
    float mean = sMI[0], inv = sMI[1];
    int c0 = 2*g, c1 = 2*g + 1;
    float ga0 = gamma[c0]*inv, be0 = beta[c0] - mean*ga0;
    float ga1 = gamma[c1]*inv, be1 = beta[c1] - mean*ga1;
    s0[p] = g_h[(b*MID + c0)*P + p]*ga0 + be0;
    s1[p] = g_h[(b*MID + c1)*P + p]*ga1 + be1;
    __syncthreads();
    int y = p >> 5, x = p & 31;
    float acc[4] = {0.f,0.f,0.f,0.f};
    #pragma unroll
    for (int ky = 0; ky < 3; ky++){
        int yy = y + ky - 1;
        if (yy < 0 || yy > 31) continue;
        #pragma unroll
        for (int kx = 0; kx < 3; kx++){
            int xx = x + kx - 1;
            if (xx < 0 || xx > 31) continue;
            int sp = yy*32 + xx;
            float v0 = s0[sp], v1 = s1[sp];
            #pragma unroll
            for (int j = 0; j < 4; j++){
                acc[j] = fmaf(v0, sW[j][ky*3+kx],     acc[j]);
                acc[j] = fmaf(v1, sW[j][9 + ky*3+kx], acc[j]);
            }
        }
    }
    if (g >= 32){
        #pragma unroll
        for (int j = 0; j < 4; j++){
            int c = 4*g + j - 128;
            g_res[(b*MID + c)*P + p] = silu_f(acc[j]);
        }
        return;
    }
    // conv0 (1x1, groups pair channels) + SiLU -> u ; keep in smem for x_dbl
    #pragma unroll
    for (int j = 0; j < 4; j++){
        int c = 4*g + j;
        float lo = (j < 2) ? acc[0] : acc[2];
        float hi = (j < 2) ? acc[1] : acc[3];
        float v = fmaf(lo, cw[c*2], fmaf(hi, cw[c*2+1], cb[c]));
        float uv = silu_f(v);
        g_u[(b*MID + c)*P + p] = uv;
        sU[j][p] = uv;
    }
    __syncthreads();
    // x_dbl rows: warp w handles k = 3w..3w+2 over all 1024 pixels
    int warp = p >> 5, lane = p & 31;
    const float* xp0 = xproj + (warp*3 + 0)*P;
    const float* xp1 = xproj + (warp*3 + 1)*P;
    const float* xp2 = xproj + (warp*3 + 2)*P;
    float a00=0,a01=0,a02=0, a10=0,a11=0,a12=0, a20=0,a21=0,a22=0, a30=0,a31=0,a32=0;
    #pragma unroll 4
    for (int i = 0; i < 32; i++){
        int px = i*32 + lane;
        float w0 = xp0[px], w1 = xp1[px], w2 = xp2[px];
        float u0 = sU[0][px], u1 = sU[1][px], u2 = sU[2][px], u3 = sU[3][px];
        a00 = fmaf(u0,w0,a00); a01 = fmaf(u0,w1,a01); a02 = fmaf(u0,w2,a02);
        a10 = fmaf(u1,w0,a10); a11 = fmaf(u1,w1,a11); a12 = fmaf(u1,w2,a12);
        a20 = fmaf(u2,w0,a20); a21 = fmaf(u2,w1,a21); a22 = fmaf(u2,w2,a22);
        a30 = fmaf(u3,w0,a30); a31 = fmaf(u3,w1,a31); a32 = fmaf(u3,w2,a32);
    }
    #pragma unroll
    for (int o = 16; o; o >>= 1){
        a00 += __shfl_xor_sync(0xffffffffu, a00, o); a01 += __shfl_xor_sync(0xffffffffu, a01, o);
        a02 += __shfl_xor_sync(0xffffffffu, a02, o); a10 += __shfl_xor_sync(0xffffffffu, a10, o);
        a11 += __shfl_xor_sync(0xffffffffu, a11, o); a12 += __shfl_xor_sync(0xffffffffu, a12, o);
        a20 += __shfl_xor_sync(0xffffffffu, a20, o); a21 += __shfl_xor_sync(0xffffffffu, a21, o);
        a22 += __shfl_xor_sync(0xffffffffu, a22, o); a30 += __shfl_xor_sync(0xffffffffu, a30, o);
        a31 += __shfl_xor_sync(0xffffffffu, a31, o); a32 += __shfl_xor_sync(0xffffffffu, a32, o);
    }
    if (lane == 0){
        int k = warp*3;
        float* r0 = g_xdbl + (b*LSEQ + 4*g + 0)*KDIM + k;
        float* r1 = g_xdbl + (b*LSEQ + 4*g + 1)*KDIM + k;
        float* r2 = g_xdbl + (b*LSEQ + 4*g + 2)*KDIM + k;
        float* r3 = g_xdbl + (b*LSEQ + 4*g + 3)*KDIM + k;
        r0[0]=a00; r0[1]=a01; r0[2]=a02;
        r1[0]=a10; r1[1]=a11; r1[2]=a12;
        r2[0]=a20; r2[1]=a21; r2[2]=a22;
        r3[0]=a30; r3[1]=a31; r3[2]=a32;
    }
}

// ---------------- fused: delta GEMM + softplus + selective scan + combine + GN1 stats ----------------
// grid (32 dt, 4 b), block 256, dynamic smem.
// SMEM layout (floats):
//   sXd   [128][68]  : xdbl[:, 0:64]          off 0      (8704)
//   sW    [64][33]   : dtw[d][k] -> [k][dloc] off 8704   (2112)
//   sB2   [128][8] f2                          off 10816  (2048)
//   sC2   [128][8] f2                          off 12864  (2048)
//   sDelta[128][33]                            off 14912  (4224)
//   sUt   [128][33]                            off 19136  (4224)
//   sY    [128][33]                            off 23360  (4224)
#define SCAN_SMEM_FLOATS 27584
#define SCAN_SMEM_BYTES  (SCAN_SMEM_FLOATS*4)
__global__ void k_scan(const float* __restrict__ dtw, const float* __restrict__ dtb,
                       const float* __restrict__ alog, const float* __restrict__ dd, int blk){
    extern __shared__ float sm[];
    float*  sXd = sm;
    float*  sW  = sm + 8704;
    float2* sB2 = (float2*)(sm + 10816);
    float2* sC2 = (float2*)(sm + 12864);
    float*  sDelta = sm + 14912;
    float*  sUt    = sm + 19136;
    float*  sY     = sm + 23360;

    int dt = blockIdx.x, b = blockIdx.y;
    int tid = threadIdx.x;

    // loads
    for (int idx = tid; idx < 128*64; idx += 256){
        int l = idx >> 6, k = idx & 63;
        sXd[l*68 + k] = g_xdbl[(b*LSEQ + l)*KDIM + k];
    }
    for (int idx = tid; idx < 128*8; idx += 256){
        int l = idx >> 3, j = idx & 7;
        const float* row = g_xdbl + (b*LSEQ + l)*KDIM;
        sB2[l*8 + j] = *(const float2*)(row + 64 + 2*j);
        sC2[l*8 + j] = *(const float2*)(row + 80 + 2*j);
    }
    for (int idx = tid; idx < 32*64; idx += 256){
        int dl = idx >> 6, r = idx & 63;
        sW[r*33 + dl] = dtw[(dt*32 + dl)*64 + r];
    }
    for (int idx = tid; idx < 128*32; idx += 256){
        int l = idx >> 5, dj = idx & 31;
        sUt[l*33 + dj] = g_u[(b*LSEQ + l)*P + dt*32 + dj];
    }
    __syncthreads();

    // delta GEMM: 128l x 32d, K=64; thread = (lq = tid>>5 -> 16 l) x (dloc = tid&31)
    {
        int dloc = tid & 31, lbase = (tid >> 5) << 4;
        float acc[16];
        #pragma unroll
        for (int l = 0; l < 16; l++) acc[l] = 0.f;
        #pragma unroll
        for (int k0 = 0; k0 < 64; k0 += 16){
            float wv[16];
            #pragma unroll
            for (int j = 0; j < 16; j++) wv[j] = sW[(k0+j)*33 + dloc];
            #pragma unroll
            for (int l = 0; l < 16; l++){
                const float4* row = (const float4*)(sXd + (lbase+l)*68 + k0);
                float4 x0 = row[0], x1 = row[1], x2 = row[2], x3 = row[3];
                float a = acc[l];
                a = fmaf(x0.x,wv[0],a);  a = fmaf(x0.y,wv[1],a);  a = fmaf(x0.z,wv[2],a);  a = fmaf(x0.w,wv[3],a);
                a = fmaf(x1.x,wv[4],a);  a = fmaf(x1.y,wv[5],a);  a = fmaf(x1.z,wv[6],a);  a = fmaf(x1.w,wv[7],a);
                a = fmaf(x2.x,wv[8],a);  a = fmaf(x2.y,wv[9],a);  a = fmaf(x2.z,wv[10],a); a = fmaf(x2.w,wv[11],a);
                a = fmaf(x3.x,wv[12],a); a = fmaf(x3.y,wv[13],a); a = fmaf(x3.z,wv[14],a); a = fmaf(x3.w,wv[15],a);
                acc[l] = a;
            }
        }
        float bias = dtb[dt*32 + dloc];
        #pragma unroll
        for (int l = 0; l < 16; l++){
            float xv = acc[l] + bias;
            sDelta[(lbase+l)*33 + dloc] = fmaxf(xv, 0.f) + __logf(1.f + __expf(-fabsf(xv)));
        }
    }
    __syncthreads();

    // scan: thread = (dl2 = tid>>3) x (n pair = (tid&7)*2)
    {
        int dl2 = tid >> 3;
        int nj  = (tid & 7) * 2;
        int d = dt*32 + dl2;
        float An0 = -expf(alog[d*16 + nj]);
        float An1 = -expf(alog[d*16 + nj + 1]);
        float Dd = dd[d];
        float cr0 = 0.f, cr1 = 0.f;
        #pragma unroll 4
        for (int l = 0; l < LSEQ; l++){
            float td = sDelta[l*33 + dl2];
            float tu = sUt[l*33 + dl2];
            float du = td * tu;
            float2 Bv = sB2[l*8 + (nj>>1)];
            float2 Cv = sC2[l*8 + (nj>>1)];
            cr0 = fmaf(__expf(td*An0), cr0, du*Bv.x);
            cr1 = fmaf(__expf(td*An1), cr1, du*Bv.y);
            float yv = fmaf(cr0, Cv.x, cr1*Cv.y);
            yv += __shfl_xor_sync(0xffffffffu, yv, 1);
            yv += __shfl_xor_sync(0xffffffffu, yv, 2);
            yv += __shfl_xor_sync(0xffffffffu, yv, 4);
            if ((tid & 7) == 0) sY[l*33 + dl2] = fmaf(tu, Dd, yv);
        }
    }
    __syncthreads();

    // combine h += y*silu(res) and GN1 partial stats
    float s0 = 0.f, q0 = 0.f, s1 = 0.f, q1 = 0.f;
    for (int e = tid; e < 128*32; e += 256){
        int l = e >> 5, dj = e & 31;
        int idx = (b*LSEQ + l)*P + dt*32 + dj;
        float h = fmaf(sY[l*33 + dj], g_res[idx], g_h[idx]);
        g_h[idx] = h;
        if (l < 64){ s0 += h; q0 += h*h; } else { s1 += h; q1 += h*h; }
    }
    if (blk == 0){
        #pragma unroll
        for (int o = 16; o; o >>= 1){
            s0 += __shfl_xor_sync(0xffffffffu, s0, o);
            q0 += __shfl_xor_sync(0xffffffffu, q0, o);
            s1 += __shfl_xor_sync(0xffffffffu, s1, o);
            q1 += __shfl_xor_sync(0xffffffffu, q1, o);
        }
        int wid = tid >> 5;
        if ((tid & 31) == 0){
            sXd[wid*4+0] = s0; sXd[wid*4+1] = q0; sXd[wid*4+2] = s1; sXd[wid*4+3] = q1;
        }
        __syncthreads();
        if (tid == 0){
            float S0=0,Q0=0,S1=0,Q1=0;
            #pragma unroll
            for (int i = 0; i < 8; i++){ S0+=sXd[i*4]; Q0+=sXd[i*4+1]; S1+=sXd[i*4+2]; Q1+=sXd[i*4+3]; }
            g_gnp1[(b*2 + 0)*32 + dt] = make_float2(S0, Q0);
            g_gnp1[(b*2 + 1)*32 + dt] = make_float2(S1, Q1);
        }
    }
}

// ---------------- conv_out 1x1 grouped fused with x8 bilinear upsample ----------------
// grid (128 oc, 4 b), block 256
__global__ void k_convout_up(const float* __restrict__ wout, const float* __restrict__ bout,
                             float* __restrict__ out){
    int oc = blockIdx.x, b = blockIdx.y;
    int g = oc >> 2;
    int tid = threadIdx.x;
    __shared__ float sCo[1024];
    const float* hb = g_h + (size_t)(b*MID + 4*g)*P;
    float w0 = wout[oc*4], w1 = wout[oc*4+1], w2 = wout[oc*4+2], w3 = wout[oc*4+3];
    float bias = bout[oc];
    float4 a = ((const float4*)hb)[tid];
    float4 c1 = ((const float4*)(hb+P))[tid];
    float4 c2 = ((const float4*)(hb+2*P))[tid];
    float4 c3 = ((const float4*)(hb+3*P))[tid];
    float4 r;
    r.x = bias + a.x*w0 + c1.x*w1 + c2.x*w2 + c3.x*w3;
    r.y = bias + a.y*w0 + c1.y*w1 + c2.y*w2 + c3.y*w3;
    r.z = bias + a.z*w0 + c1.z*w1 + c2.z*w2 + c3.z*w3;
    r.w = bias + a.w*w0 + c1.w*w1 + c2.w*w2 + c3.w*w3;
    ((float4*)sCo)[tid] = r;
    __syncthreads();

    int rx = tid & 63, ry = tid >> 6;
    int ox0 = rx * 4;
    float fx[4]; int ix0[4], ix1[4];
    #pragma unroll
    for (int j = 0; j < 4; j++){
        float sx = (ox0 + j + 0.5f) * 0.125f - 0.5f;
        int i0 = (int)floorf(sx);
        fx[j] = sx - (float)i0;
        ix0[j] = i0 < 0 ? 0 : i0;
        ix1[j] = (i0 + 1 > 31) ? 31 : i0 + 1;
    }
    float* obase = out + ((size_t)(b*MID + oc))*256*256;
    #pragma unroll 4
    for (int t = 0; t < 64; t++){
        int oy = t*4 + ry;
        float sy = (oy + 0.5f) * 0.125f - 0.5f;
        int iy = (int)floorf(sy);
        float fy = sy - (float)iy;
        int iy0 = iy < 0 ? 0 : iy;
        int iy1 = (iy + 1 > 31) ? 31 : iy + 1;
        const float* r0 = sCo + iy0*32;
        const float* r1 = sCo + iy1*32;
        float4 v;
        float t0, t1;
        t0 = r0[ix0[0]] + (r0[ix1[0]] - r0[ix0[0]]) * fx[0];
        t1 = r1[ix0[0]] + (r1[ix1[0]] - r1[ix0[0]]) * fx[0];
        v.x = t0 + (t1 - t0) * fy;
        t0 = r0[ix0[1]] + (r0[ix1[1]] - r0[ix0[1]]) * fx[1];
        t1 = r1[ix0[1]] + (r1[ix1[1]] - r1[ix0[1]]) * fx[1];
        v.y = t0 + (t1 - t0) * fy;
        t0 = r0[ix0[2]] + (r0[ix1[2]] - r0[ix0[2]]) * fx[2];
        t1 = r1[ix0[2]] + (r1[ix1[2]] - r1[ix0[2]]) * fx[2];
        v.z = t0 + (t1 - t0) * fy;
        t0 = r0[ix0[3]] + (r0[ix1[3]] - r0[ix0[3]]) * fx[3];
        t1 = r1[ix0[3]] + (r1[ix1[3]] - r1[ix0[3]]) * fx[3];
        v.w = t0 + (t1 - t0) * fy;
        ((float4*)(obase + oy*256))[rx] = v;
    }
}

// ---------------- host orchestration ----------------
extern "C" void kernel_launch(void* const* d_in, const int* in_sizes, int n_in,
                              void* d_out, int out_size){
    const float* x     = (const float*)d_in[0];
    const float* w_in  = (const float*)d_in[1];
    const float* b_in  = (const float*)d_in[2];
    const float* w_out = (const float*)d_in[23];
    const float* b_out = (const float*)d_in[24];
    float* out = (float*)d_out;

    cudaFuncSetAttribute(k_scan, cudaFuncAttributeMaxDynamicSharedMemorySize, SCAN_SMEM_BYTES);

    k_downconv<<<dim3(32,4), dim3(32,32)>>>(x, w_in, b_in);

    // mamba block 0
    k_inproj<<<dim3(64,4), 1024>>>((const float*)d_in[5], (const float*)d_in[6],
                                   (const float*)d_in[7], (const float*)d_in[3],
                                   (const float*)d_in[4], (const float*)d_in[8], 0);
    k_scan<<<dim3(32,4), 256, SCAN_SMEM_BYTES>>>((const float*)d_in[9], (const float*)d_in[10],
                                                 (const float*)d_in[11], (const float*)d_in[12], 0);
    // mamba block 1
    k_inproj<<<dim3(64,4), 1024>>>((const float*)d_in[15], (const float*)d_in[16],
                                   (const float*)d_in[17], (const float*)d_in[13],
                                   (const float*)d_in[14], (const float*)d_in[18], 1);
    k_scan<<<dim3(32,4), 256, SCAN_SMEM_BYTES>>>((const float*)d_in[19], (const float*)d_in[20],
                                                 (const float*)d_in[21], (const float*)d_in[22], 1);

    k_convout_up<<<dim3(128,4), 256>>>(w_out, b_out, out);
}

// round 5
// speedup vs baseline: 2.9568x; 1.0704x over previous
#include <cuda_runtime.h>
#include <cuda_bf16.h>
#include <math.h>

// ---------------- problem constants ----------------
#define BATCH 4
#define CIN   64
#define HH    256
#define WW    256
#define MID   128
#define P     1024          // 32*32 spatial (= d_model for the scan)
#define LSEQ  128           // scan length (= MID channels)
#define NST   16
#define KDIM  96            // DTRANK(64) + 2*NST

// ---------------- device scratch ----------------
__device__ float  g_h[BATCH*MID*P];          // residual stream (b,c,p)
__device__ float  g_u[BATCH*MID*P];          // (b,l,d) post conv0+silu
__device__ float  g_res[BATCH*MID*P];        // silu(res)
__device__ __align__(16) float g_xdbl[BATCH*LSEQ*KDIM]; // direct-stored (no atomics)
__device__ float2 g_gnp0[BATCH*2*16];        // downconv GN partials (s, s2)
__device__ float2 g_gnp1[BATCH*2*32];        // scan GN partials

__device__ __forceinline__ float silu_f(float v){ return v / (1.f + __expf(-v)); }

// ---------------- K0: stride-8 8x8 grouped conv + GN0 partial stats ----------------
// grid (32 groups, 4 b), block (32,32)
__global__ void k_downconv(const float* __restrict__ x, const float* __restrict__ w_in,
                           const float* __restrict__ b_in){
    int g = blockIdx.x, b = blockIdx.y;
    int tx = threadIdx.x, ty = threadIdx.y;
    int tid = ty*32 + tx;
    __shared__ float sw[4][2][8][8];
    if (tid < 512){
        int oc4 = tid >> 7;
        int rem = tid & 127;
        sw[oc4][rem>>6][(rem>>3)&7][rem&7] = w_in[(4*g + oc4)*128 + rem];
    }
    __syncthreads();
    float acc0=0.f, acc1=0.f, acc2=0.f, acc3=0.f;
    #pragma unroll
    for (int ic = 0; ic < 2; ic++){
        const float* xb = x + (((size_t)b*CIN + 2*g + ic)*HH + ty*8)*WW + tx*8;
        #pragma unroll
        for (int ky = 0; ky < 8; ky++){
            const float4* r = (const float4*)(xb + ky*WW);
            float4 v0 = r[0], v1 = r[1];
            float xv[8] = {v0.x,v0.y,v0.z,v0.w,v1.x,v1.y,v1.z,v1.w};
            #pragma unroll
            for (int kx = 0; kx < 8; kx++){
                float xvv = xv[kx];
                acc0 = fmaf(xvv, sw[0][ic][ky][kx], acc0);
                acc1 = fmaf(xvv, sw[1][ic][ky][kx], acc1);
                acc2 = fmaf(xvv, sw[2][ic][ky][kx], acc2);
                acc3 = fmaf(xvv, sw[3][ic][ky][kx], acc3);
            }
        }
    }
    acc0 += b_in[4*g+0]; acc1 += b_in[4*g+1]; acc2 += b_in[4*g+2]; acc3 += b_in[4*g+3];
    int p = ty*32 + tx;
    g_h[(b*MID + 4*g + 0)*P + p] = acc0;
    g_h[(b*MID + 4*g + 1)*P + p] = acc1;
    g_h[(b*MID + 4*g + 2)*P + p] = acc2;
    g_h[(b*MID + 4*g + 3)*P + p] = acc3;
    float s  = acc0 + acc1 + acc2 + acc3;
    float s2 = acc0*acc0 + acc1*acc1 + acc2*acc2 + acc3*acc3;
    __shared__ float red[64];
    #pragma unroll
    for (int o = 16; o; o >>= 1){
        s  += __shfl_xor_sync(0xffffffffu, s,  o);
        s2 += __shfl_xor_sync(0xffffffffu, s2, o);
    }
    int wid = tid >> 5, lid = tid & 31;
    if (lid == 0){ red[wid] = s; red[32+wid] = s2; }
    __syncthreads();
    if (tid < 32){
        s = red[tid]; s2 = red[32+tid];
        #pragma unroll
        for (int o = 16; o; o >>= 1){
            s  += __shfl_xor_sync(0xffffffffu, s,  o);
            s2 += __shfl_xor_sync(0xffffffffu, s2, o);
        }
        if (tid == 0){
            int grp = g >> 4;
            g_gnp0[(b*2 + grp)*16 + (g & 15)] = make_float2(s, s2);
        }
    }
}

// ---------------- inproj: GN-apply + 3x3 conv + conv0+SiLU + x_dbl rows / gate SiLU ----------------
// grid (64 groups, 4 b), block 1024.
__global__ void k_inproj(const float* __restrict__ w, const float* __restrict__ cw,
                         const float* __restrict__ cb, const float* __restrict__ gamma,
                         const float* __restrict__ beta, const float* __restrict__ xproj,
                         int blk){
    int g = blockIdx.x, b = blockIdx.y;
    int grp = g >> 5;
    __shared__ float s0[P], s1[P];
    __shared__ __align__(16) float sU[4][P];
    __shared__ float sW[4][18];
    __shared__ float sMI[2];
    int p = threadIdx.x;
    if (p < 32){
        int npart = blk ? 32 : 16;
        float2 v = make_float2(0.f, 0.f);
        if (p < npart) v = blk ? g_gnp1[(b*2+grp)*32 + p] : g_gnp0[(b*2+grp)*16 + p];
        float s = v.x, s2 = v.y;
        #pragma unroll
        for (int o = 16; o; o >>= 1){
            s  += __shfl_xor_sync(0xffffffffu, s,  o);
            s2 += __shfl_xor_sync(0xffffffffu, s2, o);
        }
        if (p == 0){
            float mean = s * (1.f/65536.f);
            float var  = s2 * (1.f/65536.f) - mean*mean;
            sMI[0] = mean;
            sMI[1] = rsqrtf(var + 1e-5f);
        }
    }
    if (p < 72) ((float*)sW)[p] = w[g*72 + p];
    __syncthreads();
    float mean = sMI[0], inv = sMI[1];
    int c0 = 2*g, c1 = 2*g + 1;
    float ga0 = gamma[c0]*inv, be0 = beta[c0] - mean*ga0;
    float ga1 = gamma[c1]*inv, be1 = beta[c1] - mean*ga1;
    s0[p] = g_h[(b*MID + c0)*P + p]*ga0 + be0;
    s1[p] = g_h[(b*MID + c1)*P + p]*ga1 + be1;
    __syncthreads();
    int y = p >> 5, x = p & 31;
    float acc[4] = {0.f,0.f,0.f,0.f};
    #pragma unroll
    for (int ky = 0; ky < 3; ky++){
        int yy = y + ky - 1;
        if (yy < 0 || yy > 31) continue;
        #pragma unroll
        for (int kx = 0; kx < 3; kx++){
            int xx = x + kx - 1;
            if (xx < 0 || xx > 31) continue;
            int sp = yy*32 + xx;
            float v0 = s0[sp], v1 = s1[sp];
            #pragma unroll
            for (int j = 0; j < 4; j++){
                acc[j] = fmaf(v0, sW[j][ky*3+kx],     acc[j]);
                acc[j] = fmaf(v1, sW[j][9 + ky*3+kx], acc[j]);
            }
        }
    }
    if (g >= 32){
        #pragma unroll
        for (int j = 0; j < 4; j++){
            int c = 4*g + j - 128;
            g_res[(b*MID + c)*P + p] = silu_f(acc[j]);
        }
        return;
    }
    // conv0 (1x1, groups pair channels) + SiLU -> u ; keep in smem for x_dbl
    #pragma unroll
    for (int j = 0; j < 4; j++){
        int c = 4*g + j;
        float lo = (j < 2) ? acc[0] : acc[2];
        float hi = (j < 2) ? acc[1] : acc[3];
        float v = fmaf(lo, cw[c*2], fmaf(hi, cw[c*2+1], cb[c]));
        float uv = silu_f(v);
        g_u[(b*MID + c)*P + p] = uv;
        sU[j][p] = uv;
    }
    __syncthreads();
    // x_dbl rows: warp w handles k = 3w..3w+2 over all 1024 pixels, float4-vectorized
    int warp = p >> 5, lane = p & 31;
    const float4* xp0 = (const float4*)(xproj + (warp*3 + 0)*P);
    const float4* xp1 = (const float4*)(xproj + (warp*3 + 1)*P);
    const float4* xp2 = (const float4*)(xproj + (warp*3 + 2)*P);
    const float4* u0p = (const float4*)sU[0];
    const float4* u1p = (const float4*)sU[1];
    const float4* u2p = (const float4*)sU[2];
    const float4* u3p = (const float4*)sU[3];
    float a00=0,a01=0,a02=0, a10=0,a11=0,a12=0, a20=0,a21=0,a22=0, a30=0,a31=0,a32=0;
    #pragma unroll
    for (int i = 0; i < 8; i++){
        int px = i*32 + lane;
        float4 w0 = xp0[px], w1 = xp1[px], w2 = xp2[px];
        float4 u0 = u0p[px], u1 = u1p[px], u2 = u2p[px], u3 = u3p[px];
        a00 = fmaf(u0.x,w0.x,a00); a00 = fmaf(u0.y,w0.y,a00); a00 = fmaf(u0.z,w0.z,a00); a00 = fmaf(u0.w,w0.w,a00);
        a01 = fmaf(u0.x,w1.x,a01); a01 = fmaf(u0.y,w1.y,a01); a01 = fmaf(u0.z,w1.z,a01); a01 = fmaf(u0.w,w1.w,a01);
        a02 = fmaf(u0.x,w2.x,a02); a02 = fmaf(u0.y,w2.y,a02); a02 = fmaf(u0.z,w2.z,a02); a02 = fmaf(u0.w,w2.w,a02);
        a10 = fmaf(u1.x,w0.x,a10); a10 = fmaf(u1.y,w0.y,a10); a10 = fmaf(u1.z,w0.z,a10); a10 = fmaf(u1.w,w0.w,a10);
        a11 = fmaf(u1.x,w1.x,a11); a11 = fmaf(u1.y,w1.y,a11); a11 = fmaf(u1.z,w1.z,a11); a11 = fmaf(u1.w,w1.w,a11);
        a12 = fmaf(u1.x,w2.x,a12); a12 = fmaf(u1.y,w2.y,a12); a12 = fmaf(u1.z,w2.z,a12); a12 = fmaf(u1.w,w2.w,a12);
        a20 = fmaf(u2.x,w0.x,a20); a20 = fmaf(u2.y,w0.y,a20); a20 = fmaf(u2.z,w0.z,a20); a20 = fmaf(u2.w,w0.w,a20);
        a21 = fmaf(u2.x,w1.x,a21); a21 = fmaf(u2.y,w1.y,a21); a21 = fmaf(u2.z,w1.z,a21); a21 = fmaf(u2.w,w1.w,a21);
        a22 = fmaf(u2.x,w2.x,a22); a22 = fmaf(u2.y,w2.y,a22); a22 = fmaf(u2.z,w2.z,a22); a22 = fmaf(u2.w,w2.w,a22);
        a30 = fmaf(u3.x,w0.x,a30); a30 = fmaf(u3.y,w0.y,a30); a30 = fmaf(u3.z,w0.z,a30); a30 = fmaf(u3.w,w0.w,a30);
        a31 = fmaf(u3.x,w1.x,a31); a31 = fmaf(u3.y,w1.y,a31); a31 = fmaf(u3.z,w1.z,a31); a31 = fmaf(u3.w,w1.w,a31);
        a32 = fmaf(u3.x,w2.x,a32); a32 = fmaf(u3.y,w2.y,a32); a32 = fmaf(u3.z,w2.z,a32); a32 = fmaf(u3.w,w2.w,a32);
    }
    #pragma unroll
    for (int o = 16; o; o >>= 1){
        a00 += __shfl_xor_sync(0xffffffffu, a00, o); a01 += __shfl_xor_sync(0xffffffffu, a01, o);
        a02 += __shfl_xor_sync(0xffffffffu, a02, o); a10 += __shfl_xor_sync(0xffffffffu, a10, o);
        a11 += __shfl_xor_sync(0xffffffffu, a11, o); a12 += __shfl_xor_sync(0xffffffffu, a12, o);
        a20 += __shfl_xor_sync(0xffffffffu, a20, o); a21 += __shfl_xor_sync(0xffffffffu, a21, o);
        a22 += __shfl_xor_sync(0xffffffffu, a22, o); a30 += __shfl_xor_sync(0xffffffffu, a30, o);
        a31 += __shfl_xor_sync(0xffffffffu, a31, o); a32 += __shfl_xor_sync(0xffffffffu, a32, o);
    }
    if (lane == 0){
        int k = warp*3;
        float* r0 = g_xdbl + (b*LSEQ + 4*g + 0)*KDIM + k;
        float* r1 = g_xdbl + (b*LSEQ + 4*g + 1)*KDIM + k;
        float* r2 = g_xdbl + (b*LSEQ + 4*g + 2)*KDIM + k;
        float* r3 = g_xdbl + (b*LSEQ + 4*g + 3)*KDIM + k;
        r0[0]=a00; r0[1]=a01; r0[2]=a02;
        r1[0]=a10; r1[1]=a11; r1[2]=a12;
        r2[0]=a20; r2[1]=a21; r2[2]=a22;
        r3[0]=a30; r3[1]=a31; r3[2]=a32;
    }
}

// ---------------- fused: delta GEMM + softplus + selective scan + combine + GN1 stats ----------------
// grid (32 dt, 4 b), block 256, dynamic smem.
#define SCAN_SMEM_FLOATS 27584
#define SCAN_SMEM_BYTES  (SCAN_SMEM_FLOATS*4)
__global__ void k_scan(const float* __restrict__ dtw, const float* __restrict__ dtb,
                       const float* __restrict__ alog, const float* __restrict__ dd, int blk){
    extern __shared__ float sm[];
    float*  sXd = sm;                    // [128][68]
    float*  sW  = sm + 8704;             // [64][33]
    float2* sB2 = (float2*)(sm + 10816); // [128][8]
    float2* sC2 = (float2*)(sm + 12864); // [128][8]
    float*  sDelta = sm + 14912;         // [128][33]
    float*  sUt    = sm + 19136;         // [128][33]
    float*  sY     = sm + 23360;         // [128][33]

    int dt = blockIdx.x, b = blockIdx.y;
    int tid = threadIdx.x;

    for (int idx = tid; idx < 128*64; idx += 256){
        int l = idx >> 6, k = idx & 63;
        sXd[l*68 + k] = g_xdbl[(b*LSEQ + l)*KDIM + k];
    }
    for (int idx = tid; idx < 128*8; idx += 256){
        int l = idx >> 3, j = idx & 7;
        const float* row = g_xdbl + (b*LSEQ + l)*KDIM;
        sB2[l*8 + j] = *(const float2*)(row + 64 + 2*j);
        sC2[l*8 + j] = *(const float2*)(row + 80 + 2*j);
    }
    for (int idx = tid; idx < 32*64; idx += 256){
        int dl = idx >> 6, r = idx & 63;
        sW[r*33 + dl] = dtw[(dt*32 + dl)*64 + r];
    }
    for (int idx = tid; idx < 128*32; idx += 256){
        int l = idx >> 5, dj = idx & 31;
        sUt[l*33 + dj] = g_u[(b*LSEQ + l)*P + dt*32 + dj];
    }
    __syncthreads();

    {
        int dloc = tid & 31, lbase = (tid >> 5) << 4;
        float acc[16];
        #pragma unroll
        for (int l = 0; l < 16; l++) acc[l] = 0.f;
        #pragma unroll
        for (int k0 = 0; k0 < 64; k0 += 16){
            float wv[16];
            #pragma unroll
            for (int j = 0; j < 16; j++) wv[j] = sW[(k0+j)*33 + dloc];
            #pragma unroll
            for (int l = 0; l < 16; l++){
                const float4* row = (const float4*)(sXd + (lbase+l)*68 + k0);
                float4 x0 = row[0], x1 = row[1], x2 = row[2], x3 = row[3];
                float a = acc[l];
                a = fmaf(x0.x,wv[0],a);  a = fmaf(x0.y,wv[1],a);  a = fmaf(x0.z,wv[2],a);  a = fmaf(x0.w,wv[3],a);
                a = fmaf(x1.x,wv[4],a);  a = fmaf(x1.y,wv[5],a);  a = fmaf(x1.z,wv[6],a);  a = fmaf(x1.w,wv[7],a);
                a = fmaf(x2.x,wv[8],a);  a = fmaf(x2.y,wv[9],a);  a = fmaf(x2.z,wv[10],a); a = fmaf(x2.w,wv[11],a);
                a = fmaf(x3.x,wv[12],a); a = fmaf(x3.y,wv[13],a); a = fmaf(x3.z,wv[14],a); a = fmaf(x3.w,wv[15],a);
                acc[l] = a;
            }
        }
        float bias = dtb[dt*32 + dloc];
        #pragma unroll
        for (int l = 0; l < 16; l++){
            float xv = acc[l] + bias;
            sDelta[(lbase+l)*33 + dloc] = fmaxf(xv, 0.f) + __logf(1.f + __expf(-fabsf(xv)));
        }
    }
    __syncthreads();

    {
        int dl2 = tid >> 3;
        int nj  = (tid & 7) * 2;
        int d = dt*32 + dl2;
        float An0 = -expf(alog[d*16 + nj]);
        float An1 = -expf(alog[d*16 + nj + 1]);
        float Dd = dd[d];
        float cr0 = 0.f, cr1 = 0.f;
        #pragma unroll 4
        for (int l = 0; l < LSEQ; l++){
            float td = sDelta[l*33 + dl2];
            float tu = sUt[l*33 + dl2];
            float du = td * tu;
            float2 Bv = sB2[l*8 + (nj>>1)];
            float2 Cv = sC2[l*8 + (nj>>1)];
            cr0 = fmaf(__expf(td*An0), cr0, du*Bv.x);
            cr1 = fmaf(__expf(td*An1), cr1, du*Bv.y);
            float yv = fmaf(cr0, Cv.x, cr1*Cv.y);
            yv += __shfl_xor_sync(0xffffffffu, yv, 1);
            yv += __shfl_xor_sync(0xffffffffu, yv, 2);
            yv += __shfl_xor_sync(0xffffffffu, yv, 4);
            if ((tid & 7) == 0) sY[l*33 + dl2] = fmaf(tu, Dd, yv);
        }
    }
    __syncthreads();

    float s0 = 0.f, q0 = 0.f, s1 = 0.f, q1 = 0.f;
    for (int e = tid; e < 128*32; e += 256){
        int l = e >> 5, dj = e & 31;
        int idx = (b*LSEQ + l)*P + dt*32 + dj;
        float h = fmaf(sY[l*33 + dj], g_res[idx], g_h[idx]);
        g_h[idx] = h;
        if (l < 64){ s0 += h; q0 += h*h; } else { s1 += h; q1 += h*h; }
    }
    if (blk == 0){
        #pragma unroll
        for (int o = 16; o; o >>= 1){
            s0 += __shfl_xor_sync(0xffffffffu, s0, o);
            q0 += __shfl_xor_sync(0xffffffffu, q0, o);
            s1 += __shfl_xor_sync(0xffffffffu, s1, o);
            q1 += __shfl_xor_sync(0xffffffffu, q1, o);
        }
        int wid = tid >> 5;
        if ((tid & 31) == 0){
            sXd[wid*4+0] = s0; sXd[wid*4+1] = q0; sXd[wid*4+2] = s1; sXd[wid*4+3] = q1;
        }
        __syncthreads();
        if (tid == 0){
            float S0=0,Q0=0,S1=0,Q1=0;
            #pragma unroll
            for (int i = 0; i < 8; i++){ S0+=sXd[i*4]; Q0+=sXd[i*4+1]; S1+=sXd[i*4+2]; Q1+=sXd[i*4+3]; }
            g_gnp1[(b*2 + 0)*32 + dt] = make_float2(S0, Q0);
            g_gnp1[(b*2 + 1)*32 + dt] = make_float2(S1, Q1);
        }
    }
}

// ---------------- conv_out 1x1 grouped fused with x8 bilinear upsample ----------------
// grid (128 oc, 4 b), block 256
__global__ void k_convout_up(const float* __restrict__ wout, const float* __restrict__ bout,
                             float* __restrict__ out){
    int oc = blockIdx.x, b = blockIdx.y;
    int g = oc >> 2;
    int tid = threadIdx.x;
    __shared__ float sCo[1024];
    const float* hb = g_h + (size_t)(b*MID + 4*g)*P;
    float w0 = wout[oc*4], w1 = wout[oc*4+1], w2 = wout[oc*4+2], w3 = wout[oc*4+3];
    float bias = bout[oc];
    float4 a = ((const float4*)hb)[tid];
    float4 c1 = ((const float4*)(hb+P))[tid];
    float4 c2 = ((const float4*)(hb+2*P))[tid];
    float4 c3 = ((const float4*)(hb+3*P))[tid];
    float4 r;
    r.x = bias + a.x*w0 + c1.x*w1 + c2.x*w2 + c3.x*w3;
    r.y = bias + a.y*w0 + c1.y*w1 + c2.y*w2 + c3.y*w3;
    r.z = bias + a.z*w0 + c1.z*w1 + c2.z*w2 + c3.z*w3;
    r.w = bias + a.w*w0 + c1.w*w1 + c2.w*w2 + c3.w*w3;
    ((float4*)sCo)[tid] = r;
    __syncthreads();

    int rx = tid & 63, ry = tid >> 6;
    int ox0 = rx * 4;
    float fx[4]; int ix0[4], ix1[4];
    #pragma unroll
    for (int j = 0; j < 4; j++){
        float sx = (ox0 + j + 0.5f) * 0.125f - 0.5f;
        int i0 = (int)floorf(sx);
        fx[j] = sx - (float)i0;
        ix0[j] = i0 < 0 ? 0 : i0;
        ix1[j] = (i0 + 1 > 31) ? 31 : i0 + 1;
    }
    float* obase = out + ((size_t)(b*MID + oc))*256*256;
    #pragma unroll 4
    for (int t = 0; t < 64; t++){
        int oy = t*4 + ry;
        float sy = (oy + 0.5f) * 0.125f - 0.5f;
        int iy = (int)floorf(sy);
        float fy = sy - (float)iy;
        int iy0 = iy < 0 ? 0 : iy;
        int iy1 = (iy + 1 > 31) ? 31 : iy + 1;
        const float* r0 = sCo + iy0*32;
        const float* r1 = sCo + iy1*32;
        float4 v;
        float t0, t1;
        t0 = r0[ix0[0]] + (r0[ix1[0]] - r0[ix0[0]]) * fx[0];
        t1 = r1[ix0[0]] + (r1[ix1[0]] - r1[ix0[0]]) * fx[0];
        v.x = t0 + (t1 - t0) * fy;
        t0 = r0[ix0[1]] + (r0[ix1[1]] - r0[ix0[1]]) * fx[1];
        t1 = r1[ix0[1]] + (r1[ix1[1]] - r1[ix0[1]]) * fx[1];
        v.y = t0 + (t1 - t0) * fy;
        t0 = r0[ix0[2]] + (r0[ix1[2]] - r0[ix0[2]]) * fx[2];
        t1 = r1[ix0[2]] + (r1[ix1[2]] - r1[ix0[2]]) * fx[2];
        v.z = t0 + (t1 - t0) * fy;
        t0 = r0[ix0[3]] + (r0[ix1[3]] - r0[ix0[3]]) * fx[3];
        t1 = r1[ix0[3]] + (r1[ix1[3]] - r1[ix0[3]]) * fx[3];
        v.w = t0 + (t1 - t0) * fy;
        ((float4*)(obase + oy*256))[rx] = v;
    }
}

// ---------------- host orchestration ----------------
extern "C" void kernel_launch(void* const* d_in, const int* in_sizes, int n_in,
                              void* d_out, int out_size){
    const float* x     = (const float*)d_in[0];
    const float* w_in  = (const float*)d_in[1];
    const float* b_in  = (const float*)d_in[2];
    const float* w_out = (const float*)d_in[23];
    const float* b_out = (const float*)d_in[24];
    float* out = (float*)d_out;

    cudaFuncSetAttribute(k_scan, cudaFuncAttributeMaxDynamicSharedMemorySize, SCAN_SMEM_BYTES);

    k_downconv<<<dim3(32,4), dim3(32,32)>>>(x, w_in, b_in);

    // mamba block 0
    k_inproj<<<dim3(64,4), 1024>>>((const float*)d_in[5], (const float*)d_in[6],
                                   (const float*)d_in[7], (const float*)d_in[3],
                                   (const float*)d_in[4], (const float*)d_in[8], 0);
    k_scan<<<dim3(32,4), 256, SCAN_SMEM_BYTES>>>((const float*)d_in[9], (const float*)d_in[10],
                                                 (const float*)d_in[11], (const float*)d_in[12], 0);
    // mamba block 1
    k_inproj<<<dim3(64,4), 1024>>>((const float*)d_in[15], (const float*)d_in[16],
                                   (const float*)d_in[17], (const float*)d_in[13],
                                   (const float*)d_in[14], (const float*)d_in[18], 1);
    k_scan<<<dim3(32,4), 256, SCAN_SMEM_BYTES>>>((const float*)d_in[19], (const float*)d_in[20],
                                                 (const float*)d_in[21], (const float*)d_in[22], 1);

    k_convout_up<<<dim3(128,4), 256>>>(w_out, b_out, out);
}

// round 6
// speedup vs baseline: 3.2782x; 1.1087x over previous
#include <cuda_runtime.h>
#include <cuda_bf16.h>
#include <math.h>

// ---------------- problem constants ----------------
#define BATCH 4
#define CIN   64
#define HH    256
#define WW    256
#define MID   128
#define P     1024          // 32*32 spatial (= d_model for the scan)
#define LSEQ  128           // scan length (= MID channels)
#define NST   16
#define KDIM  96            // DTRANK(64) + 2*NST

// ---------------- device scratch ----------------
__device__ float  g_h[BATCH*MID*P];          // residual stream (b,c,p)
__device__ float  g_u[BATCH*MID*P];          // (b,l,d) post conv0+silu
__device__ float  g_res[BATCH*MID*P];        // silu(res)
__device__ __align__(16) float g_xdbl[BATCH*LSEQ*KDIM]; // direct-stored (no atomics)
__device__ float2 g_gnp0[BATCH*2*16];        // downconv GN partials (s, s2)
__device__ float2 g_gnp1[BATCH*2*32];        // scan GN partials

__device__ __forceinline__ float silu_f(float v){ return v / (1.f + __expf(-v)); }

// ---------------- K0: stride-8 8x8 grouped conv + GN0 partial stats ----------------
// grid (32 groups, 4 b), block (32,32)
__global__ void k_downconv(const float* __restrict__ x, const float* __restrict__ w_in,
                           const float* __restrict__ b_in){
    int g = blockIdx.x, b = blockIdx.y;
    int tx = threadIdx.x, ty = threadIdx.y;
    int tid = ty*32 + tx;
    __shared__ float sw[4][2][8][8];
    if (tid < 512){
        int oc4 = tid >> 7;
        int rem = tid & 127;
        sw[oc4][rem>>6][(rem>>3)&7][rem&7] = w_in[(4*g + oc4)*128 + rem];
    }
    __syncthreads();
    float acc0=0.f, acc1=0.f, acc2=0.f, acc3=0.f;
    #pragma unroll
    for (int ic = 0; ic < 2; ic++){
        const float* xb = x + (((size_t)b*CIN + 2*g + ic)*HH + ty*8)*WW + tx*8;
        #pragma unroll
        for (int ky = 0; ky < 8; ky++){
            const float4* r = (const float4*)(xb + ky*WW);
            float4 v0 = r[0], v1 = r[1];
            float xv[8] = {v0.x,v0.y,v0.z,v0.w,v1.x,v1.y,v1.z,v1.w};
            #pragma unroll
            for (int kx = 0; kx < 8; kx++){
                float xvv = xv[kx];
                acc0 = fmaf(xvv, sw[0][ic][ky][kx], acc0);
                acc1 = fmaf(xvv, sw[1][ic][ky][kx], acc1);
                acc2 = fmaf(xvv, sw[2][ic][ky][kx], acc2);
                acc3 = fmaf(xvv, sw[3][ic][ky][kx], acc3);
            }
        }
    }
    acc0 += b_in[4*g+0]; acc1 += b_in[4*g+1]; acc2 += b_in[4*g+2]; acc3 += b_in[4*g+3];
    int p = ty*32 + tx;
    g_h[(b*MID + 4*g + 0)*P + p] = acc0;
    g_h[(b*MID + 4*g + 1)*P + p] = acc1;
    g_h[(b*MID + 4*g + 2)*P + p] = acc2;
    g_h[(b*MID + 4*g + 3)*P + p] = acc3;
    float s  = acc0 + acc1 + acc2 + acc3;
    float s2 = acc0*acc0 + acc1*acc1 + acc2*acc2 + acc3*acc3;
    __shared__ float red[64];
    #pragma unroll
    for (int o = 16; o; o >>= 1){
        s  += __shfl_xor_sync(0xffffffffu, s,  o);
        s2 += __shfl_xor_sync(0xffffffffu, s2, o);
    }
    int wid = tid >> 5, lid = tid & 31;
    if (lid == 0){ red[wid] = s; red[32+wid] = s2; }
    __syncthreads();
    if (tid < 32){
        s = red[tid]; s2 = red[32+tid];
        #pragma unroll
        for (int o = 16; o; o >>= 1){
            s  += __shfl_xor_sync(0xffffffffu, s,  o);
            s2 += __shfl_xor_sync(0xffffffffu, s2, o);
        }
        if (tid == 0){
            int grp = g >> 4;
            g_gnp0[(b*2 + grp)*16 + (g & 15)] = make_float2(s, s2);
        }
    }
}

// ---------------- inproj (balanced): per block = one xs group + one gate group ----------------
// grid (32, 4b), block 1024. Block g: xs inproj-group g (ch 2g,2g+1 -> oc 4g..4g+3 -> u),
// gate inproj-group g+32 (ch 64+2g,65+2g -> res), then x_dbl GEMM for rows 4g..4g+3.
__global__ void __launch_bounds__(1024, 1)
k_inproj(const float* __restrict__ w, const float* __restrict__ cw,
         const float* __restrict__ cb, const float* __restrict__ gamma,
         const float* __restrict__ beta, const float* __restrict__ xproj,
         int blk){
    int g = blockIdx.x, b = blockIdx.y;
    __shared__ float s0[P], s1[P], s2[P], s3[P];
    __shared__ __align__(16) float sU[4][P];
    __shared__ float sW[8][18];
    __shared__ float sMI[4];
    int p = threadIdx.x;
    int wq = p >> 5, lane = p & 31;
    // prologue: warp 0 -> GN group 0 stats, warp 1 -> GN group 1 stats
    if (wq < 2){
        int npart = blk ? 32 : 16;
        float2 v = make_float2(0.f, 0.f);
        if (lane < npart) v = blk ? g_gnp1[(b*2+wq)*32 + lane] : g_gnp0[(b*2+wq)*16 + lane];
        float s = v.x, s2v = v.y;
        #pragma unroll
        for (int o = 16; o; o >>= 1){
            s   += __shfl_xor_sync(0xffffffffu, s,   o);
            s2v += __shfl_xor_sync(0xffffffffu, s2v, o);
        }
        if (lane == 0){
            float mean = s * (1.f/65536.f);
            float var  = s2v * (1.f/65536.f) - mean*mean;
            sMI[wq*2]   = mean;
            sMI[wq*2+1] = rsqrtf(var + 1e-5f);
        }
    }
    if (p >= 64 && p < 136) ((float*)sW)[p-64]     = w[g*72 + (p-64)];
    if (p >= 160 && p < 232) ((float*)sW)[72 + (p-160)] = w[(g+32)*72 + (p-160)];
    __syncthreads();
    {
        float m0 = sMI[0], i0 = sMI[1], m1 = sMI[2], i1 = sMI[3];
        int cx0 = 2*g, cx1 = 2*g+1, cg0 = 64+2*g, cg1 = 65+2*g;
        float ga, be;
        ga = gamma[cx0]*i0; be = beta[cx0] - m0*ga;  s0[p] = g_h[(b*MID + cx0)*P + p]*ga + be;
        ga = gamma[cx1]*i0; be = beta[cx1] - m0*ga;  s1[p] = g_h[(b*MID + cx1)*P + p]*ga + be;
        ga = gamma[cg0]*i1; be = beta[cg0] - m1*ga;  s2[p] = g_h[(b*MID + cg0)*P + p]*ga + be;
        ga = gamma[cg1]*i1; be = beta[cg1] - m1*ga;  s3[p] = g_h[(b*MID + cg1)*P + p]*ga + be;
    }
    __syncthreads();
    int y = p >> 5, x = p & 31;
    float acc[8] = {0.f,0.f,0.f,0.f,0.f,0.f,0.f,0.f};
    #pragma unroll
    for (int ky = 0; ky < 3; ky++){
        int yy = y + ky - 1;
        if (yy < 0 || yy > 31) continue;
        #pragma unroll
        for (int kx = 0; kx < 3; kx++){
            int xx = x + kx - 1;
            if (xx < 0 || xx > 31) continue;
            int sp = yy*32 + xx;
            float v0 = s0[sp], v1 = s1[sp], v2 = s2[sp], v3 = s3[sp];
            int t = ky*3 + kx;
            #pragma unroll
            for (int j = 0; j < 4; j++){
                acc[j]   = fmaf(v0, sW[j][t],       acc[j]);
                acc[j]   = fmaf(v1, sW[j][9+t],     acc[j]);
                acc[4+j] = fmaf(v2, sW[4+j][t],     acc[4+j]);
                acc[4+j] = fmaf(v3, sW[4+j][9+t],   acc[4+j]);
            }
        }
    }
    // gate: silu -> res
    #pragma unroll
    for (int j = 0; j < 4; j++){
        int c = 4*g + j;
        g_res[(b*MID + c)*P + p] = silu_f(acc[4+j]);
    }
    // xs: conv0 (1x1 pairs) + SiLU -> u (global + smem)
    #pragma unroll
    for (int j = 0; j < 4; j++){
        int c = 4*g + j;
        float lo = (j < 2) ? acc[0] : acc[2];
        float hi = (j < 2) ? acc[1] : acc[3];
        float v = fmaf(lo, cw[c*2], fmaf(hi, cw[c*2+1], cb[c]));
        float uv = silu_f(v);
        g_u[(b*MID + c)*P + p] = uv;
        sU[j][p] = uv;
    }
    __syncthreads();
    // x_dbl rows 4g..4g+3: warp w handles k = 3w..3w+2, float4-vectorized
    const float4* xp0 = (const float4*)(xproj + (wq*3 + 0)*P);
    const float4* xp1 = (const float4*)(xproj + (wq*3 + 1)*P);
    const float4* xp2 = (const float4*)(xproj + (wq*3 + 2)*P);
    const float4* u0p = (const float4*)sU[0];
    const float4* u1p = (const float4*)sU[1];
    const float4* u2p = (const float4*)sU[2];
    const float4* u3p = (const float4*)sU[3];
    float a00=0,a01=0,a02=0, a10=0,a11=0,a12=0, a20=0,a21=0,a22=0, a30=0,a31=0,a32=0;
    #pragma unroll
    for (int i = 0; i < 8; i++){
        int px = i*32 + lane;
        float4 w0 = xp0[px], w1 = xp1[px], w2 = xp2[px];
        float4 u0 = u0p[px], u1 = u1p[px], u2 = u2p[px], u3 = u3p[px];
        a00 = fmaf(u0.x,w0.x,a00); a00 = fmaf(u0.y,w0.y,a00); a00 = fmaf(u0.z,w0.z,a00); a00 = fmaf(u0.w,w0.w,a00);
        a01 = fmaf(u0.x,w1.x,a01); a01 = fmaf(u0.y,w1.y,a01); a01 = fmaf(u0.z,w1.z,a01); a01 = fmaf(u0.w,w1.w,a01);
        a02 = fmaf(u0.x,w2.x,a02); a02 = fmaf(u0.y,w2.y,a02); a02 = fmaf(u0.z,w2.z,a02); a02 = fmaf(u0.w,w2.w,a02);
        a10 = fmaf(u1.x,w0.x,a10); a10 = fmaf(u1.y,w0.y,a10); a10 = fmaf(u1.z,w0.z,a10); a10 = fmaf(u1.w,w0.w,a10);
        a11 = fmaf(u1.x,w1.x,a11); a11 = fmaf(u1.y,w1.y,a11); a11 = fmaf(u1.z,w1.z,a11); a11 = fmaf(u1.w,w1.w,a11);
        a12 = fmaf(u1.x,w2.x,a12); a12 = fmaf(u1.y,w2.y,a12); a12 = fmaf(u1.z,w2.z,a12); a12 = fmaf(u1.w,w2.w,a12);
        a20 = fmaf(u2.x,w0.x,a20); a20 = fmaf(u2.y,w0.y,a20); a20 = fmaf(u2.z,w0.z,a20); a20 = fmaf(u2.w,w0.w,a20);
        a21 = fmaf(u2.x,w1.x,a21); a21 = fmaf(u2.y,w1.y,a21); a21 = fmaf(u2.z,w1.z,a21); a21 = fmaf(u2.w,w1.w,a21);
        a22 = fmaf(u2.x,w2.x,a22); a22 = fmaf(u2.y,w2.y,a22); a22 = fmaf(u2.z,w2.z,a22); a22 = fmaf(u2.w,w2.w,a22);
        a30 = fmaf(u3.x,w0.x,a30); a30 = fmaf(u3.y,w0.y,a30); a30 = fmaf(u3.z,w0.z,a30); a30 = fmaf(u3.w,w0.w,a30);
        a31 = fmaf(u3.x,w1.x,a31); a31 = fmaf(u3.y,w1.y,a31); a31 = fmaf(u3.z,w1.z,a31); a31 = fmaf(u3.w,w1.w,a31);
        a32 = fmaf(u3.x,w2.x,a32); a32 = fmaf(u3.y,w2.y,a32); a32 = fmaf(u3.z,w2.z,a32); a32 = fmaf(u3.w,w2.w,a32);
    }
    #pragma unroll
    for (int o = 16; o; o >>= 1){
        a00 += __shfl_xor_sync(0xffffffffu, a00, o); a01 += __shfl_xor_sync(0xffffffffu, a01, o);
        a02 += __shfl_xor_sync(0xffffffffu, a02, o); a10 += __shfl_xor_sync(0xffffffffu, a10, o);
        a11 += __shfl_xor_sync(0xffffffffu, a11, o); a12 += __shfl_xor_sync(0xffffffffu, a12, o);
        a20 += __shfl_xor_sync(0xffffffffu, a20, o); a21 += __shfl_xor_sync(0xffffffffu, a21, o);
        a22 += __shfl_xor_sync(0xffffffffu, a22, o); a30 += __shfl_xor_sync(0xffffffffu, a30, o);
        a31 += __shfl_xor_sync(0xffffffffu, a31, o); a32 += __shfl_xor_sync(0xffffffffu, a32, o);
    }
    if (lane == 0){
        int k = wq*3;
        float* r0 = g_xdbl + (b*LSEQ + 4*g + 0)*KDIM + k;
        float* r1 = g_xdbl + (b*LSEQ + 4*g + 1)*KDIM + k;
        float* r2 = g_xdbl + (b*LSEQ + 4*g + 2)*KDIM + k;
        float* r3 = g_xdbl + (b*LSEQ + 4*g + 3)*KDIM + k;
        r0[0]=a00; r0[1]=a01; r0[2]=a02;
        r1[0]=a10; r1[1]=a11; r1[2]=a12;
        r2[0]=a20; r2[1]=a21; r2[2]=a22;
        r3[0]=a30; r3[1]=a31; r3[2]=a32;
    }
}

// ---------------- fused: delta GEMM + softplus + selective scan + combine + GN1 stats ----------------
// grid (32 dt, 4 b), block 512, dynamic smem. sY overlays sXd (dead after GEMM).
#define SCAN_SMEM_FLOATS 23360
#define SCAN_SMEM_BYTES  (SCAN_SMEM_FLOATS*4)
__global__ void __launch_bounds__(512, 1)
k_scan(const float* __restrict__ dtw, const float* __restrict__ dtb,
       const float* __restrict__ alog, const float* __restrict__ dd, int blk){
    extern __shared__ float sm[];
    float*  sXd = sm;                    // [128][68]; later sY [128][33]
    float*  sW  = sm + 8704;             // [64][33]; later GN scratch
    float*  sB  = sm + 10816;            // [128][16]
    float*  sC  = sm + 12864;            // [128][16]
    float*  sDelta = sm + 14912;         // [128][33]
    float*  sUt    = sm + 19136;         // [128][33]
    float*  sY     = sm;                 // overlay

    int dt = blockIdx.x, b = blockIdx.y;
    int tid = threadIdx.x;

    for (int idx = tid; idx < 128*64; idx += 512){
        int l = idx >> 6, k = idx & 63;
        sXd[l*68 + k] = g_xdbl[(b*LSEQ + l)*KDIM + k];
    }
    for (int idx = tid; idx < 128*16; idx += 512){
        int l = idx >> 4, n = idx & 15;
        const float* row = g_xdbl + (b*LSEQ + l)*KDIM;
        sB[l*16 + n] = row[64 + n];
        sC[l*16 + n] = row[80 + n];
    }
    for (int idx = tid; idx < 32*64; idx += 512){
        int dl = idx >> 6, r = idx & 63;
        sW[r*33 + dl] = dtw[(dt*32 + dl)*64 + r];
    }
    for (int idx = tid; idx < 128*32; idx += 512){
        int l = idx >> 5, dj = idx & 31;
        sUt[l*33 + dj] = g_u[(b*LSEQ + l)*P + dt*32 + dj];
    }
    __syncthreads();

    // delta GEMM: thread = (8 l's) x (dloc)
    {
        int dloc = tid & 31, lbase = (tid >> 5) << 3;
        float acc[8];
        #pragma unroll
        for (int l = 0; l < 8; l++) acc[l] = 0.f;
        #pragma unroll
        for (int k0 = 0; k0 < 64; k0 += 16){
            float wv[16];
            #pragma unroll
            for (int j = 0; j < 16; j++) wv[j] = sW[(k0+j)*33 + dloc];
            #pragma unroll
            for (int l = 0; l < 8; l++){
                const float4* row = (const float4*)(sXd + (lbase+l)*68 + k0);
                float4 x0 = row[0], x1 = row[1], x2 = row[2], x3 = row[3];
                float a = acc[l];
                a = fmaf(x0.x,wv[0],a);  a = fmaf(x0.y,wv[1],a);  a = fmaf(x0.z,wv[2],a);  a = fmaf(x0.w,wv[3],a);
                a = fmaf(x1.x,wv[4],a);  a = fmaf(x1.y,wv[5],a);  a = fmaf(x1.z,wv[6],a);  a = fmaf(x1.w,wv[7],a);
                a = fmaf(x2.x,wv[8],a);  a = fmaf(x2.y,wv[9],a);  a = fmaf(x2.z,wv[10],a); a = fmaf(x2.w,wv[11],a);
                a = fmaf(x3.x,wv[12],a); a = fmaf(x3.y,wv[13],a); a = fmaf(x3.z,wv[14],a); a = fmaf(x3.w,wv[15],a);
                acc[l] = a;
            }
        }
        float bias = dtb[dt*32 + dloc];
        #pragma unroll
        for (int l = 0; l < 8; l++){
            float xv = acc[l] + bias;
            sDelta[(lbase+l)*33 + dloc] = fmaxf(xv, 0.f) + __logf(1.f + __expf(-fabsf(xv)));
        }
    }
    __syncthreads();

    // scan: thread = (dl = tid>>4) x (n = tid&15)
    {
        int dl = tid >> 4;
        int n  = tid & 15;
        int d = dt*32 + dl;
        float An = -expf(alog[d*16 + n]);
        float Dd = dd[d];
        float cr = 0.f;
        #pragma unroll 4
        for (int l = 0; l < LSEQ; l++){
            float td = sDelta[l*33 + dl];
            float tu = sUt[l*33 + dl];
            float du = td * tu;
            cr = fmaf(__expf(td*An), cr, du*sB[l*16 + n]);
            float yv = cr * sC[l*16 + n];
            yv += __shfl_xor_sync(0xffffffffu, yv, 1);
            yv += __shfl_xor_sync(0xffffffffu, yv, 2);
            yv += __shfl_xor_sync(0xffffffffu, yv, 4);
            yv += __shfl_xor_sync(0xffffffffu, yv, 8);
            if (n == 0) sY[l*33 + dl] = fmaf(tu, Dd, yv);
        }
    }
    __syncthreads();

    // combine h += y*silu(res) and GN1 partial stats
    float s0 = 0.f, q0 = 0.f, s1 = 0.f, q1 = 0.f;
    for (int e = tid; e < 128*32; e += 512){
        int l = e >> 5, dj = e & 31;
        int idx = (b*LSEQ + l)*P + dt*32 + dj;
        float h = fmaf(sY[l*33 + dj], g_res[idx], g_h[idx]);
        g_h[idx] = h;
        if (l < 64){ s0 += h; q0 += h*h; } else { s1 += h; q1 += h*h; }
    }
    if (blk == 0){
        #pragma unroll
        for (int o = 16; o; o >>= 1){
            s0 += __shfl_xor_sync(0xffffffffu, s0, o);
            q0 += __shfl_xor_sync(0xffffffffu, q0, o);
            s1 += __shfl_xor_sync(0xffffffffu, s1, o);
            q1 += __shfl_xor_sync(0xffffffffu, q1, o);
        }
        int wid = tid >> 5;
        if ((tid & 31) == 0){
            sW[wid*4+0] = s0; sW[wid*4+1] = q0; sW[wid*4+2] = s1; sW[wid*4+3] = q1;
        }
        __syncthreads();
        if (tid == 0){
            float S0=0,Q0=0,S1=0,Q1=0;
            #pragma unroll
            for (int i = 0; i < 16; i++){ S0+=sW[i*4]; Q0+=sW[i*4+1]; S1+=sW[i*4+2]; Q1+=sW[i*4+3]; }
            g_gnp1[(b*2 + 0)*32 + dt] = make_float2(S0, Q0);
            g_gnp1[(b*2 + 1)*32 + dt] = make_float2(S1, Q1);
        }
    }
}

// ---------------- conv_out 1x1 grouped fused with x8 bilinear upsample ----------------
// grid (128 oc, 4 b), block 256
__global__ void k_convout_up(const float* __restrict__ wout, const float* __restrict__ bout,
                             float* __restrict__ out){
    int oc = blockIdx.x, b = blockIdx.y;
    int g = oc >> 2;
    int tid = threadIdx.x;
    __shared__ float sCo[1024];
    const float* hb = g_h + (size_t)(b*MID + 4*g)*P;
    float w0 = wout[oc*4], w1 = wout[oc*4+1], w2 = wout[oc*4+2], w3 = wout[oc*4+3];
    float bias = bout[oc];
    float4 a = ((const float4*)hb)[tid];
    float4 c1 = ((const float4*)(hb+P))[tid];
    float4 c2 = ((const float4*)(hb+2*P))[tid];
    float4 c3 = ((const float4*)(hb+3*P))[tid];
    float4 r;
    r.x = bias + a.x*w0 + c1.x*w1 + c2.x*w2 + c3.x*w3;
    r.y = bias + a.y*w0 + c1.y*w1 + c2.y*w2 + c3.y*w3;
    r.z = bias + a.z*w0 + c1.z*w1 + c2.z*w2 + c3.z*w3;
    r.w = bias + a.w*w0 + c1.w*w1 + c2.w*w2 + c3.w*w3;
    ((float4*)sCo)[tid] = r;
    __syncthreads();

    int rx = tid & 63, ry = tid >> 6;
    int ox0 = rx * 4;
    float fx[4]; int ix0[4], ix1[4];
    #pragma unroll
    for (int j = 0; j < 4; j++){
        float sx = (ox0 + j + 0.5f) * 0.125f - 0.5f;
        int i0 = (int)floorf(sx);
        fx[j] = sx - (float)i0;
        ix0[j] = i0 < 0 ? 0 : i0;
        ix1[j] = (i0 + 1 > 31) ? 31 : i0 + 1;
    }
    float* obase = out + ((size_t)(b*MID + oc))*256*256;
    #pragma unroll 4
    for (int t = 0; t < 64; t++){
        int oy = t*4 + ry;
        float sy = (oy + 0.5f) * 0.125f - 0.5f;
        int iy = (int)floorf(sy);
        float fy = sy - (float)iy;
        int iy0 = iy < 0 ? 0 : iy;
        int iy1 = (iy + 1 > 31) ? 31 : iy + 1;
        const float* r0 = sCo + iy0*32;
        const float* r1 = sCo + iy1*32;
        float4 v;
        float t0, t1;
        t0 = r0[ix0[0]] + (r0[ix1[0]] - r0[ix0[0]]) * fx[0];
        t1 = r1[ix0[0]] + (r1[ix1[0]] - r1[ix0[0]]) * fx[0];
        v.x = t0 + (t1 - t0) * fy;
        t0 = r0[ix0[1]] + (r0[ix1[1]] - r0[ix0[1]]) * fx[1];
        t1 = r1[ix0[1]] + (r1[ix1[1]] - r1[ix0[1]]) * fx[1];
        v.y = t0 + (t1 - t0) * fy;
        t0 = r0[ix0[2]] + (r0[ix1[2]] - r0[ix0[2]]) * fx[2];
        t1 = r1[ix0[2]] + (r1[ix1[2]] - r1[ix0[2]]) * fx[2];
        v.z = t0 + (t1 - t0) * fy;
        t0 = r0[ix0[3]] + (r0[ix1[3]] - r0[ix0[3]]) * fx[3];
        t1 = r1[ix0[3]] + (r1[ix1[3]] - r1[ix0[3]]) * fx[3];
        v.w = t0 + (t1 - t0) * fy;
        ((float4*)(obase + oy*256))[rx] = v;
    }
}

// ---------------- host orchestration ----------------
extern "C" void kernel_launch(void* const* d_in, const int* in_sizes, int n_in,
                              void* d_out, int out_size){
    const float* x     = (const float*)d_in[0];
    const float* w_in  = (const float*)d_in[1];
    const float* b_in  = (const float*)d_in[2];
    const float* w_out = (const float*)d_in[23];
    const float* b_out = (const float*)d_in[24];
    float* out = (float*)d_out;

    cudaFuncSetAttribute(k_scan, cudaFuncAttributeMaxDynamicSharedMemorySize, SCAN_SMEM_BYTES);

    k_downconv<<<dim3(32,4), dim3(32,32)>>>(x, w_in, b_in);

    // mamba block 0
    k_inproj<<<dim3(32,4), 1024>>>((const float*)d_in[5], (const float*)d_in[6],
                                   (const float*)d_in[7], (const float*)d_in[3],
                                   (const float*)d_in[4], (const float*)d_in[8], 0);
    k_scan<<<dim3(32,4), 512, SCAN_SMEM_BYTES>>>((const float*)d_in[9], (const float*)d_in[10],
                                                 (const float*)d_in[11], (const float*)d_in[12], 0);
    // mamba block 1
    k_inproj<<<dim3(32,4), 1024>>>((const float*)d_in[15], (const float*)d_in[16],
                                   (const float*)d_in[17], (const float*)d_in[13],
                                   (const float*)d_in[14], (const float*)d_in[18], 1);
    k_scan<<<dim3(32,4), 512, SCAN_SMEM_BYTES>>>((const float*)d_in[19], (const float*)d_in[20],
                                                 (const float*)d_in[21], (const float*)d_in[22], 1);

    k_convout_up<<<dim3(128,4), 256>>>(w_out, b_out, out);
}

// round 7
// speedup vs baseline: 3.3301x; 1.0158x over previous
#include <cuda_runtime.h>
#include <cuda_bf16.h>
#include <math.h>

// ---------------- problem constants ----------------
#define BATCH 4
#define CIN   64
#define HH    256
#define WW    256
#define MID   128
#define P     1024          // 32*32 spatial (= d_model for the scan)
#define LSEQ  128           // scan length (= MID channels)
#define NST   16
#define KDIM  96            // DTRANK(64) + 2*NST

// ---------------- device scratch ----------------
__device__ float  g_h[BATCH*MID*P];          // residual stream (b,c,p)
__device__ float  g_u[BATCH*MID*P];          // (b,l,d) post conv0+silu
__device__ float  g_res[BATCH*MID*P];        // silu(res)
__device__ __align__(16) float g_xdbl[BATCH*LSEQ*KDIM]; // direct-stored (no atomics)
__device__ float2 g_gnp0[BATCH*2*16];        // downconv GN partials (s, s2)
__device__ float2 g_gnp1[BATCH*2*32];        // scan GN partials

__device__ __forceinline__ float silu_f(float v){ return v / (1.f + __expf(-v)); }

// ---------------- K0: stride-8 8x8 grouped conv + GN0 partial stats ----------------
// grid (32 groups, 4 b), block (32,32)
__global__ void k_downconv(const float* __restrict__ x, const float* __restrict__ w_in,
                           const float* __restrict__ b_in){
    int g = blockIdx.x, b = blockIdx.y;
    int tx = threadIdx.x, ty = threadIdx.y;
    int tid = ty*32 + tx;
    __shared__ float sw[4][2][8][8];
    if (tid < 512){
        int oc4 = tid >> 7;
        int rem = tid & 127;
        sw[oc4][rem>>6][(rem>>3)&7][rem&7] = w_in[(4*g + oc4)*128 + rem];
    }
    __syncthreads();
    float acc0=0.f, acc1=0.f, acc2=0.f, acc3=0.f;
    #pragma unroll
    for (int ic = 0; ic < 2; ic++){
        const float* xb = x + (((size_t)b*CIN + 2*g + ic)*HH + ty*8)*WW + tx*8;
        #pragma unroll
        for (int ky = 0; ky < 8; ky++){
            const float4* r = (const float4*)(xb + ky*WW);
            float4 v0 = r[0], v1 = r[1];
            float xv[8] = {v0.x,v0.y,v0.z,v0.w,v1.x,v1.y,v1.z,v1.w};
            #pragma unroll
            for (int kx = 0; kx < 8; kx++){
                float xvv = xv[kx];
                acc0 = fmaf(xvv, sw[0][ic][ky][kx], acc0);
                acc1 = fmaf(xvv, sw[1][ic][ky][kx], acc1);
                acc2 = fmaf(xvv, sw[2][ic][ky][kx], acc2);
                acc3 = fmaf(xvv, sw[3][ic][ky][kx], acc3);
            }
        }
    }
    acc0 += b_in[4*g+0]; acc1 += b_in[4*g+1]; acc2 += b_in[4*g+2]; acc3 += b_in[4*g+3];
    int p = ty*32 + tx;
    g_h[(b*MID + 4*g + 0)*P + p] = acc0;
    g_h[(b*MID + 4*g + 1)*P + p] = acc1;
    g_h[(b*MID + 4*g + 2)*P + p] = acc2;
    g_h[(b*MID + 4*g + 3)*P + p] = acc3;
    float s  = acc0 + acc1 + acc2 + acc3;
    float s2 = acc0*acc0 + acc1*acc1 + acc2*acc2 + acc3*acc3;
    __shared__ float red[64];
    #pragma unroll
    for (int o = 16; o; o >>= 1){
        s  += __shfl_xor_sync(0xffffffffu, s,  o);
        s2 += __shfl_xor_sync(0xffffffffu, s2, o);
    }
    int wid = tid >> 5, lid = tid & 31;
    if (lid == 0){ red[wid] = s; red[32+wid] = s2; }
    __syncthreads();
    if (tid < 32){
        s = red[tid]; s2 = red[32+tid];
        #pragma unroll
        for (int o = 16; o; o >>= 1){
            s  += __shfl_xor_sync(0xffffffffu, s,  o);
            s2 += __shfl_xor_sync(0xffffffffu, s2, o);
        }
        if (tid == 0){
            int grp = g >> 4;
            g_gnp0[(b*2 + grp)*16 + (g & 15)] = make_float2(s, s2);
        }
    }
}

// ---------------- inproj (interleaved float4 + halo): xs + gate + x_dbl ----------------
// grid (32, 4b), block 1024. Planes packed as float4 (xs0, xs1, gate0, gate1) with zero halo.
__global__ void __launch_bounds__(1024, 1)
k_inproj(const float* __restrict__ w, const float* __restrict__ cw,
         const float* __restrict__ cb, const float* __restrict__ gamma,
         const float* __restrict__ beta, const float* __restrict__ xproj,
         int blk){
    int g = blockIdx.x, b = blockIdx.y;
    __shared__ __align__(16) float4 sP[34*34];
    __shared__ __align__(16) float  sU[4][P];
    __shared__ __align__(16) float4 sW4[9][4];
    __shared__ float sMI[4];
    int p = threadIdx.x;
    int wq = p >> 5, lane = p & 31;
    // prologue: warp 0 -> GN group 0 stats, warp 1 -> GN group 1 stats
    if (wq < 2){
        int npart = blk ? 32 : 16;
        float2 v = make_float2(0.f, 0.f);
        if (lane < npart) v = blk ? g_gnp1[(b*2+wq)*32 + lane] : g_gnp0[(b*2+wq)*16 + lane];
        float s = v.x, s2v = v.y;
        #pragma unroll
        for (int o = 16; o; o >>= 1){
            s   += __shfl_xor_sync(0xffffffffu, s,   o);
            s2v += __shfl_xor_sync(0xffffffffu, s2v, o);
        }
        if (lane == 0){
            float mean = s * (1.f/65536.f);
            float var  = s2v * (1.f/65536.f) - mean*mean;
            sMI[wq*2]   = mean;
            sMI[wq*2+1] = rsqrtf(var + 1e-5f);
        }
    }
    // weights packed: sW4[t][j] = (xs_j_ic0[t], xs_j_ic1[t], gate_j_ic0[t], gate_j_ic1[t])
    if (p >= 64 && p < 100){
        int idx = p - 64;           // 0..35
        int t = idx / 4, j = idx & 3;
        float4 wv;
        wv.x = w[(4*g + j)*18 +     t];
        wv.y = w[(4*g + j)*18 + 9 + t];
        wv.z = w[(128 + 4*g + j)*18 +     t];
        wv.w = w[(128 + 4*g + j)*18 + 9 + t];
        sW4[t][j] = wv;
    }
    // zero the halo (132 boundary cells of the 34x34 tile)
    if (p >= 128 && p < 260){
        int i = p - 128;
        int cell;
        if (i < 34)       cell = i;                       // top row
        else if (i < 68)  cell = 33*34 + (i - 34);        // bottom row
        else if (i < 100) cell = (i - 68 + 1)*34;         // left col
        else              cell = (i - 100 + 1)*34 + 33;   // right col
        sP[cell] = make_float4(0.f, 0.f, 0.f, 0.f);
    }
    __syncthreads();
    int y = p >> 5, x = p & 31;
    {
        float m0 = sMI[0], i0 = sMI[1], m1 = sMI[2], i1 = sMI[3];
        int cx0 = 2*g, cx1 = 2*g+1, cg0 = 64+2*g, cg1 = 65+2*g;
        float ga0 = gamma[cx0]*i0, be0 = beta[cx0] - m0*ga0;
        float ga1 = gamma[cx1]*i0, be1 = beta[cx1] - m0*ga1;
        float ga2 = gamma[cg0]*i1, be2 = beta[cg0] - m1*ga2;
        float ga3 = gamma[cg1]*i1, be3 = beta[cg1] - m1*ga3;
        float4 v;
        v.x = g_h[(b*MID + cx0)*P + p]*ga0 + be0;
        v.y = g_h[(b*MID + cx1)*P + p]*ga1 + be1;
        v.z = g_h[(b*MID + cg0)*P + p]*ga2 + be2;
        v.w = g_h[(b*MID + cg1)*P + p]*ga3 + be3;
        sP[(y+1)*34 + (x+1)] = v;
    }
    __syncthreads();
    float accx[4] = {0.f,0.f,0.f,0.f};
    float accg[4] = {0.f,0.f,0.f,0.f};
    #pragma unroll
    for (int ky = 0; ky < 3; ky++){
        #pragma unroll
        for (int kx = 0; kx < 3; kx++){
            float4 v = sP[(y+ky)*34 + (x+kx)];
            int t = ky*3 + kx;
            #pragma unroll
            for (int j = 0; j < 4; j++){
                float4 W = sW4[t][j];
                accx[j] = fmaf(v.x, W.x, fmaf(v.y, W.y, accx[j]));
                accg[j] = fmaf(v.z, W.z, fmaf(v.w, W.w, accg[j]));
            }
        }
    }
    // gate: silu -> res
    #pragma unroll
    for (int j = 0; j < 4; j++){
        int c = 4*g + j;
        g_res[(b*MID + c)*P + p] = silu_f(accg[j]);
    }
    // xs: conv0 (1x1 pairs) + SiLU -> u (global + smem)
    #pragma unroll
    for (int j = 0; j < 4; j++){
        int c = 4*g + j;
        float lo = (j < 2) ? accx[0] : accx[2];
        float hi = (j < 2) ? accx[1] : accx[3];
        float v = fmaf(lo, cw[c*2], fmaf(hi, cw[c*2+1], cb[c]));
        float uv = silu_f(v);
        g_u[(b*MID + c)*P + p] = uv;
        sU[j][p] = uv;
    }
    __syncthreads();
    // x_dbl rows 4g..4g+3: warp wq handles k = 3wq..3wq+2, float4-vectorized
    const float4* xp0 = (const float4*)(xproj + (wq*3 + 0)*P);
    const float4* xp1 = (const float4*)(xproj + (wq*3 + 1)*P);
    const float4* xp2 = (const float4*)(xproj + (wq*3 + 2)*P);
    const float4* u0p = (const float4*)sU[0];
    const float4* u1p = (const float4*)sU[1];
    const float4* u2p = (const float4*)sU[2];
    const float4* u3p = (const float4*)sU[3];
    float a00=0,a01=0,a02=0, a10=0,a11=0,a12=0, a20=0,a21=0,a22=0, a30=0,a31=0,a32=0;
    #pragma unroll
    for (int i = 0; i < 8; i++){
        int px = i*32 + lane;
        float4 w0 = xp0[px], w1 = xp1[px], w2 = xp2[px];
        float4 u0 = u0p[px], u1 = u1p[px], u2 = u2p[px], u3 = u3p[px];
        a00 = fmaf(u0.x,w0.x,a00); a00 = fmaf(u0.y,w0.y,a00); a00 = fmaf(u0.z,w0.z,a00); a00 = fmaf(u0.w,w0.w,a00);
        a01 = fmaf(u0.x,w1.x,a01); a01 = fmaf(u0.y,w1.y,a01); a01 = fmaf(u0.z,w1.z,a01); a01 = fmaf(u0.w,w1.w,a01);
        a02 = fmaf(u0.x,w2.x,a02); a02 = fmaf(u0.y,w2.y,a02); a02 = fmaf(u0.z,w2.z,a02); a02 = fmaf(u0.w,w2.w,a02);
        a10 = fmaf(u1.x,w0.x,a10); a10 = fmaf(u1.y,w0.y,a10); a10 = fmaf(u1.z,w0.z,a10); a10 = fmaf(u1.w,w0.w,a10);
        a11 = fmaf(u1.x,w1.x,a11); a11 = fmaf(u1.y,w1.y,a11); a11 = fmaf(u1.z,w1.z,a11); a11 = fmaf(u1.w,w1.w,a11);
        a12 = fmaf(u1.x,w2.x,a12); a12 = fmaf(u1.y,w2.y,a12); a12 = fmaf(u1.z,w2.z,a12); a12 = fmaf(u1.w,w2.w,a12);
        a20 = fmaf(u2.x,w0.x,a20); a20 = fmaf(u2.y,w0.y,a20); a20 = fmaf(u2.z,w0.z,a20); a20 = fmaf(u2.w,w0.w,a20);
        a21 = fmaf(u2.x,w1.x,a21); a21 = fmaf(u2.y,w1.y,a21); a21 = fmaf(u2.z,w1.z,a21); a21 = fmaf(u2.w,w1.w,a21);
        a22 = fmaf(u2.x,w2.x,a22); a22 = fmaf(u2.y,w2.y,a22); a22 = fmaf(u2.z,w2.z,a22); a22 = fmaf(u2.w,w2.w,a22);
        a30 = fmaf(u3.x,w0.x,a30); a30 = fmaf(u3.y,w0.y,a30); a30 = fmaf(u3.z,w0.z,a30); a30 = fmaf(u3.w,w0.w,a30);
        a31 = fmaf(u3.x,w1.x,a31); a31 = fmaf(u3.y,w1.y,a31); a31 = fmaf(u3.z,w1.z,a31); a31 = fmaf(u3.w,w1.w,a31);
        a32 = fmaf(u3.x,w2.x,a32); a32 = fmaf(u3.y,w2.y,a32); a32 = fmaf(u3.z,w2.z,a32); a32 = fmaf(u3.w,w2.w,a32);
    }
    #pragma unroll
    for (int o = 16; o; o >>= 1){
        a00 += __shfl_xor_sync(0xffffffffu, a00, o); a01 += __shfl_xor_sync(0xffffffffu, a01, o);
        a02 += __shfl_xor_sync(0xffffffffu, a02, o); a10 += __shfl_xor_sync(0xffffffffu, a10, o);
        a11 += __shfl_xor_sync(0xffffffffu, a11, o); a12 += __shfl_xor_sync(0xffffffffu, a12, o);
        a20 += __shfl_xor_sync(0xffffffffu, a20, o); a21 += __shfl_xor_sync(0xffffffffu, a21, o);
        a22 += __shfl_xor_sync(0xffffffffu, a22, o); a30 += __shfl_xor_sync(0xffffffffu, a30, o);
        a31 += __shfl_xor_sync(0xffffffffu, a31, o); a32 += __shfl_xor_sync(0xffffffffu, a32, o);
    }
    if (lane == 0){
        int k = wq*3;
        float* r0 = g_xdbl + (b*LSEQ + 4*g + 0)*KDIM + k;
        float* r1 = g_xdbl + (b*LSEQ + 4*g + 1)*KDIM + k;
        float* r2 = g_xdbl + (b*LSEQ + 4*g + 2)*KDIM + k;
        float* r3 = g_xdbl + (b*LSEQ + 4*g + 3)*KDIM + k;
        r0[0]=a00; r0[1]=a01; r0[2]=a02;
        r1[0]=a10; r1[1]=a11; r1[2]=a12;
        r2[0]=a20; r2[1]=a21; r2[2]=a22;
        r3[0]=a30; r3[1]=a31; r3[2]=a32;
    }
}

// ---------------- fused: delta GEMM + softplus + selective scan + combine + GN1 stats ----------------
// grid (32 dt, 4 b), block 512, dynamic smem. sY overlays sXd (dead after GEMM).
#define SCAN_SMEM_FLOATS 23360
#define SCAN_SMEM_BYTES  (SCAN_SMEM_FLOATS*4)
__global__ void __launch_bounds__(512, 1)
k_scan(const float* __restrict__ dtw, const float* __restrict__ dtb,
       const float* __restrict__ alog, const float* __restrict__ dd, int blk){
    extern __shared__ float sm[];
    float*  sXd = sm;                    // [128][68]; later sY [128][33]
    float*  sW  = sm + 8704;             // [64][33]; later GN scratch
    float*  sB  = sm + 10816;            // [128][16]
    float*  sC  = sm + 12864;            // [128][16]
    float*  sDelta = sm + 14912;         // [128][33]
    float*  sUt    = sm + 19136;         // [128][33]
    float*  sY     = sm;                 // overlay

    int dt = blockIdx.x, b = blockIdx.y;
    int tid = threadIdx.x;

    for (int idx = tid; idx < 128*64; idx += 512){
        int l = idx >> 6, k = idx & 63;
        sXd[l*68 + k] = g_xdbl[(b*LSEQ + l)*KDIM + k];
    }
    for (int idx = tid; idx < 128*16; idx += 512){
        int l = idx >> 4, n = idx & 15;
        const float* row = g_xdbl + (b*LSEQ + l)*KDIM;
        sB[l*16 + n] = row[64 + n];
        sC[l*16 + n] = row[80 + n];
    }
    for (int idx = tid; idx < 32*64; idx += 512){
        int dl = idx >> 6, r = idx & 63;
        sW[r*33 + dl] = dtw[(dt*32 + dl)*64 + r];
    }
    for (int idx = tid; idx < 128*32; idx += 512){
        int l = idx >> 5, dj = idx & 31;
        sUt[l*33 + dj] = g_u[(b*LSEQ + l)*P + dt*32 + dj];
    }
    __syncthreads();

    // delta GEMM: thread = (8 l's) x (dloc)
    {
        int dloc = tid & 31, lbase = (tid >> 5) << 3;
        float acc[8];
        #pragma unroll
        for (int l = 0; l < 8; l++) acc[l] = 0.f;
        #pragma unroll
        for (int k0 = 0; k0 < 64; k0 += 16){
            float wv[16];
            #pragma unroll
            for (int j = 0; j < 16; j++) wv[j] = sW[(k0+j)*33 + dloc];
            #pragma unroll
            for (int l = 0; l < 8; l++){
                const float4* row = (const float4*)(sXd + (lbase+l)*68 + k0);
                float4 x0 = row[0], x1 = row[1], x2 = row[2], x3 = row[3];
                float a = acc[l];
                a = fmaf(x0.x,wv[0],a);  a = fmaf(x0.y,wv[1],a);  a = fmaf(x0.z,wv[2],a);  a = fmaf(x0.w,wv[3],a);
                a = fmaf(x1.x,wv[4],a);  a = fmaf(x1.y,wv[5],a);  a = fmaf(x1.z,wv[6],a);  a = fmaf(x1.w,wv[7],a);
                a = fmaf(x2.x,wv[8],a);  a = fmaf(x2.y,wv[9],a);  a = fmaf(x2.z,wv[10],a); a = fmaf(x2.w,wv[11],a);
                a = fmaf(x3.x,wv[12],a); a = fmaf(x3.y,wv[13],a); a = fmaf(x3.z,wv[14],a); a = fmaf(x3.w,wv[15],a);
                acc[l] = a;
            }
        }
        float bias = dtb[dt*32 + dloc];
        #pragma unroll
        for (int l = 0; l < 8; l++){
            float xv = acc[l] + bias;
            sDelta[(lbase+l)*33 + dloc] = fmaxf(xv, 0.f) + __logf(1.f + __expf(-fabsf(xv)));
        }
    }
    __syncthreads();

    // scan: thread = (dl = tid>>4) x (n = tid&15)
    {
        int dl = tid >> 4;
        int n  = tid & 15;
        int d = dt*32 + dl;
        float An = -expf(alog[d*16 + n]);
        float Dd = dd[d];
        float cr = 0.f;
        #pragma unroll 4
        for (int l = 0; l < LSEQ; l++){
            float td = sDelta[l*33 + dl];
            float tu = sUt[l*33 + dl];
            float du = td * tu;
            cr = fmaf(__expf(td*An), cr, du*sB[l*16 + n]);
            float yv = cr * sC[l*16 + n];
            yv += __shfl_xor_sync(0xffffffffu, yv, 1);
            yv += __shfl_xor_sync(0xffffffffu, yv, 2);
            yv += __shfl_xor_sync(0xffffffffu, yv, 4);
            yv += __shfl_xor_sync(0xffffffffu, yv, 8);
            if (n == 0) sY[l*33 + dl] = fmaf(tu, Dd, yv);
        }
    }
    __syncthreads();

    // combine h += y*silu(res) and GN1 partial stats
    float s0 = 0.f, q0 = 0.f, s1 = 0.f, q1 = 0.f;
    for (int e = tid; e < 128*32; e += 512){
        int l = e >> 5, dj = e & 31;
        int idx = (b*LSEQ + l)*P + dt*32 + dj;
        float h = fmaf(sY[l*33 + dj], g_res[idx], g_h[idx]);
        g_h[idx] = h;
        if (l < 64){ s0 += h; q0 += h*h; } else { s1 += h; q1 += h*h; }
    }
    if (blk == 0){
        #pragma unroll
        for (int o = 16; o; o >>= 1){
            s0 += __shfl_xor_sync(0xffffffffu, s0, o);
            q0 += __shfl_xor_sync(0xffffffffu, q0, o);
            s1 += __shfl_xor_sync(0xffffffffu, s1, o);
            q1 += __shfl_xor_sync(0xffffffffu, q1, o);
        }
        int wid = tid >> 5;
        if ((tid & 31) == 0){
            sW[wid*4+0] = s0; sW[wid*4+1] = q0; sW[wid*4+2] = s1; sW[wid*4+3] = q1;
        }
        __syncthreads();
        if (tid == 0){
            float S0=0,Q0=0,S1=0,Q1=0;
            #pragma unroll
            for (int i = 0; i < 16; i++){ S0+=sW[i*4]; Q0+=sW[i*4+1]; S1+=sW[i*4+2]; Q1+=sW[i*4+3]; }
            g_gnp1[(b*2 + 0)*32 + dt] = make_float2(S0, Q0);
            g_gnp1[(b*2 + 1)*32 + dt] = make_float2(S1, Q1);
        }
    }
}

// ---------------- conv_out 1x1 grouped fused with x8 bilinear upsample ----------------
// grid (128 oc, 4 b), block 256
__global__ void k_convout_up(const float* __restrict__ wout, const float* __restrict__ bout,
                             float* __restrict__ out){
    int oc = blockIdx.x, b = blockIdx.y;
    int g = oc >> 2;
    int tid = threadIdx.x;
    __shared__ float sCo[1024];
    const float* hb = g_h + (size_t)(b*MID + 4*g)*P;
    float w0 = wout[oc*4], w1 = wout[oc*4+1], w2 = wout[oc*4+2], w3 = wout[oc*4+3];
    float bias = bout[oc];
    float4 a = ((const float4*)hb)[tid];
    float4 c1 = ((const float4*)(hb+P))[tid];
    float4 c2 = ((const float4*)(hb+2*P))[tid];
    float4 c3 = ((const float4*)(hb+3*P))[tid];
    float4 r;
    r.x = bias + a.x*w0 + c1.x*w1 + c2.x*w2 + c3.x*w3;
    r.y = bias + a.y*w0 + c1.y*w1 + c2.y*w2 + c3.y*w3;
    r.z = bias + a.z*w0 + c1.z*w1 + c2.z*w2 + c3.z*w3;
    r.w = bias + a.w*w0 + c1.w*w1 + c2.w*w2 + c3.w*w3;
    ((float4*)sCo)[tid] = r;
    __syncthreads();

    int rx = tid & 63, ry = tid >> 6;
    int ox0 = rx * 4;
    float fx[4]; int ix0[4], ix1[4];
    #pragma unroll
    for (int j = 0; j < 4; j++){
        float sx = (ox0 + j + 0.5f) * 0.125f - 0.5f;
        int i0 = (int)floorf(sx);
        fx[j] = sx - (float)i0;
        ix0[j] = i0 < 0 ? 0 : i0;
        ix1[j] = (i0 + 1 > 31) ? 31 : i0 + 1;
    }
    float* obase = out + ((size_t)(b*MID + oc))*256*256;
    #pragma unroll 4
    for (int t = 0; t < 64; t++){
        int oy = t*4 + ry;
        float sy = (oy + 0.5f) * 0.125f - 0.5f;
        int iy = (int)floorf(sy);
        float fy = sy - (float)iy;
        int iy0 = iy < 0 ? 0 : iy;
        int iy1 = (iy + 1 > 31) ? 31 : iy + 1;
        const float* r0 = sCo + iy0*32;
        const float* r1 = sCo + iy1*32;
        float4 v;
        float t0, t1;
        t0 = r0[ix0[0]] + (r0[ix1[0]] - r0[ix0[0]]) * fx[0];
        t1 = r1[ix0[0]] + (r1[ix1[0]] - r1[ix0[0]]) * fx[0];
        v.x = t0 + (t1 - t0) * fy;
        t0 = r0[ix0[1]] + (r0[ix1[1]] - r0[ix0[1]]) * fx[1];
        t1 = r1[ix0[1]] + (r1[ix1[1]] - r1[ix0[1]]) * fx[1];
        v.y = t0 + (t1 - t0) * fy;
        t0 = r0[ix0[2]] + (r0[ix1[2]] - r0[ix0[2]]) * fx[2];
        t1 = r1[ix0[2]] + (r1[ix1[2]] - r1[ix0[2]]) * fx[2];
        v.z = t0 + (t1 - t0) * fy;
        t0 = r0[ix0[3]] + (r0[ix1[3]] - r0[ix0[3]]) * fx[3];
        t1 = r1[ix0[3]] + (r1[ix1[3]] - r1[ix0[3]]) * fx[3];
        v.w = t0 + (t1 - t0) * fy;
        ((float4*)(obase + oy*256))[rx] = v;
    }
}

// ---------------- host orchestration ----------------
extern "C" void kernel_launch(void* const* d_in, const int* in_sizes, int n_in,
                              void* d_out, int out_size){
    const float* x     = (const float*)d_in[0];
    const float* w_in  = (const float*)d_in[1];
    const float* b_in  = (const float*)d_in[2];
    const float* w_out = (const float*)d_in[23];
    const float* b_out = (const float*)d_in[24];
    float* out = (float*)d_out;

    cudaFuncSetAttribute(k_scan, cudaFuncAttributeMaxDynamicSharedMemorySize, SCAN_SMEM_BYTES);

    k_downconv<<<dim3(32,4), dim3(32,32)>>>(x, w_in, b_in);

    // mamba block 0
    k_inproj<<<dim3(32,4), 1024>>>((const float*)d_in[5], (const float*)d_in[6],
                                   (const float*)d_in[7], (const float*)d_in[3],
                                   (const float*)d_in[4], (const float*)d_in[8], 0);
    k_scan<<<dim3(32,4), 512, SCAN_SMEM_BYTES>>>((const float*)d_in[9], (const float*)d_in[10],
                                                 (const float*)d_in[11], (const float*)d_in[12], 0);
    // mamba block 1
    k_inproj<<<dim3(32,4), 1024>>>((const float*)d_in[15], (const float*)d_in[16],
                                   (const float*)d_in[17], (const float*)d_in[13],
                                   (const float*)d_in[14], (const float*)d_in[18], 1);
    k_scan<<<dim3(32,4), 512, SCAN_SMEM_BYTES>>>((const float*)d_in[19], (const float*)d_in[20],
                                                 (const float*)d_in[21], (const float*)d_in[22], 1);

    k_convout_up<<<dim3(128,4), 256>>>(w_out, b_out, out);
}

// round 8
// speedup vs baseline: 3.5731x; 1.0730x over previous
#include <cuda_runtime.h>
#include <cuda_bf16.h>
#include <math.h>

// ---------------- problem constants ----------------
#define BATCH 4
#define CIN   64
#define HH    256
#define WW    256
#define MID   128
#define P     1024
#define LSEQ  128
#define NST   16
#define KDIM  96
#define NBLK  128

// ---------------- device scratch ----------------
__device__ float  g_h[BATCH*MID*P];
__device__ float  g_u[BATCH*MID*P];
__device__ float  g_res[BATCH*MID*P];
__device__ __align__(16) float g_xdbl[BATCH*LSEQ*KDIM];
__device__ float2 g_gnp0[BATCH*2*16];
__device__ float2 g_gnp1[BATCH*2*32];

// grid barrier state (generation-based; monotonic across graph replays)
__device__ volatile unsigned g_gen = 0;
__device__ unsigned g_cnt = 0;

__device__ __forceinline__ void grid_bar(){
    __syncthreads();
    if (threadIdx.x == 0){
        __threadfence();
        unsigned old = g_gen;
        unsigned rank = atomicAdd(&g_cnt, 1u);
        if (rank == NBLK - 1){
            g_cnt = 0;
            __threadfence();
            atomicAdd((unsigned*)&g_gen, 1u);
        } else {
            while (g_gen == old) { }
        }
        __threadfence();
    }
    __syncthreads();
}

__device__ __forceinline__ float silu_f(float v){ return v / (1.f + __expf(-v)); }

#define SCAN_SMEM_FLOATS 23360
#define SCAN_SMEM_BYTES  (SCAN_SMEM_FLOATS*4)

// =========================== MEGA KERNEL ===========================
__global__ void __launch_bounds__(1024, 1)
k_mega(const float* __restrict__ x, const float* __restrict__ w_in, const float* __restrict__ b_in,
       const float* __restrict__ gn0g, const float* __restrict__ gn0b, const float* __restrict__ ip0w,
       const float* __restrict__ c0w,  const float* __restrict__ c0b,  const float* __restrict__ xp0,
       const float* __restrict__ dt0w, const float* __restrict__ dt0b, const float* __restrict__ al0,
       const float* __restrict__ dd0,
       const float* __restrict__ gn1g, const float* __restrict__ gn1b, const float* __restrict__ ip1w,
       const float* __restrict__ c1w,  const float* __restrict__ c1b,  const float* __restrict__ xp1,
       const float* __restrict__ dt1w, const float* __restrict__ dt1b, const float* __restrict__ al1,
       const float* __restrict__ dd1,
       const float* __restrict__ wout, const float* __restrict__ bout, float* __restrict__ out)
{
    extern __shared__ float sm[];   // scan workspace (93 KB)
    __shared__ __align__(16) float4 sP[34*34];
    __shared__ __align__(16) float  sU[4][P];
    __shared__ __align__(16) float4 sW4[9][4];
    __shared__ float sMI[4];
    __shared__ float swdc[4][2][8][8];
    __shared__ float red[64];
    __shared__ __align__(16) float sCo[1024];

    int bid = blockIdx.x;
    int b = bid >> 5, q = bid & 31;     // q = group/dtile index
    int tid = threadIdx.x;

    // ================= phase 0: downconv (8x8 stride 8) + GN0 stats =================
    {
        int g = q;
        int ty = tid >> 5, tx = tid & 31;
        if (tid < 512){
            int oc4 = tid >> 7, rem = tid & 127;
            swdc[oc4][rem>>6][(rem>>3)&7][rem&7] = w_in[(4*g + oc4)*128 + rem];
        }
        __syncthreads();
        float acc0=0.f, acc1=0.f, acc2=0.f, acc3=0.f;
        #pragma unroll
        for (int ic = 0; ic < 2; ic++){
            const float* xb = x + (((size_t)b*CIN + 2*g + ic)*HH + ty*8)*WW + tx*8;
            #pragma unroll
            for (int ky = 0; ky < 8; ky++){
                const float4* r = (const float4*)(xb + ky*WW);
                float4 v0 = r[0], v1 = r[1];
                float xv[8] = {v0.x,v0.y,v0.z,v0.w,v1.x,v1.y,v1.z,v1.w};
                #pragma unroll
                for (int kx = 0; kx < 8; kx++){
                    float xvv = xv[kx];
                    acc0 = fmaf(xvv, swdc[0][ic][ky][kx], acc0);
                    acc1 = fmaf(xvv, swdc[1][ic][ky][kx], acc1);
                    acc2 = fmaf(xvv, swdc[2][ic][ky][kx], acc2);
                    acc3 = fmaf(xvv, swdc[3][ic][ky][kx], acc3);
                }
            }
        }
        acc0 += b_in[4*g+0]; acc1 += b_in[4*g+1]; acc2 += b_in[4*g+2]; acc3 += b_in[4*g+3];
        int p = ty*32 + tx;
        g_h[(b*MID + 4*g + 0)*P + p] = acc0;
        g_h[(b*MID + 4*g + 1)*P + p] = acc1;
        g_h[(b*MID + 4*g + 2)*P + p] = acc2;
        g_h[(b*MID + 4*g + 3)*P + p] = acc3;
        float s  = acc0 + acc1 + acc2 + acc3;
        float s2 = acc0*acc0 + acc1*acc1 + acc2*acc2 + acc3*acc3;
        #pragma unroll
        for (int o = 16; o; o >>= 1){
            s  += __shfl_xor_sync(0xffffffffu, s,  o);
            s2 += __shfl_xor_sync(0xffffffffu, s2, o);
        }
        int wid = tid >> 5, lid = tid & 31;
        if (lid == 0){ red[wid] = s; red[32+wid] = s2; }
        __syncthreads();
        if (tid < 32){
            s = red[tid]; s2 = red[32+tid];
            #pragma unroll
            for (int o = 16; o; o >>= 1){
                s  += __shfl_xor_sync(0xffffffffu, s,  o);
                s2 += __shfl_xor_sync(0xffffffffu, s2, o);
            }
            if (tid == 0){
                int grp = g >> 4;
                g_gnp0[(b*2 + grp)*16 + (g & 15)] = make_float2(s, s2);
            }
        }
    }
    grid_bar();

    // ================= mamba blocks =================
    #pragma unroll 1
    for (int blk = 0; blk < 2; blk++){
        const float* w     = blk ? ip1w : ip0w;
        const float* cw    = blk ? c1w  : c0w;
        const float* cb    = blk ? c1b  : c0b;
        const float* gamma = blk ? gn1g : gn0g;
        const float* beta  = blk ? gn1b : gn0b;
        const float* xproj = blk ? xp1  : xp0;
        const float* dtw   = blk ? dt1w : dt0w;
        const float* dtb   = blk ? dt1b : dt0b;
        const float* alog  = blk ? al1  : al0;
        const float* dd    = blk ? dd1  : dd0;

        // ---------- inproj: GN + 3x3 conv + conv0+SiLU + gate + x_dbl ----------
        {
            int g = q;
            int p = tid;
            int wq = p >> 5, lane = p & 31;
            if (wq < 2){
                int npart = blk ? 32 : 16;
                float2 v = make_float2(0.f, 0.f);
                if (lane < npart) v = blk ? g_gnp1[(b*2+wq)*32 + lane] : g_gnp0[(b*2+wq)*16 + lane];
                float s = v.x, s2v = v.y;
                #pragma unroll
                for (int o = 16; o; o >>= 1){
                    s   += __shfl_xor_sync(0xffffffffu, s,   o);
                    s2v += __shfl_xor_sync(0xffffffffu, s2v, o);
                }
                if (lane == 0){
                    float mean = s * (1.f/65536.f);
                    float var  = s2v * (1.f/65536.f) - mean*mean;
                    sMI[wq*2]   = mean;
                    sMI[wq*2+1] = rsqrtf(var + 1e-5f);
                }
            }
            if (p >= 64 && p < 100){
                int idx = p - 64;
                int t = idx / 4, j = idx & 3;
                float4 wv;
                wv.x = w[(4*g + j)*18 +     t];
                wv.y = w[(4*g + j)*18 + 9 + t];
                wv.z = w[(128 + 4*g + j)*18 +     t];
                wv.w = w[(128 + 4*g + j)*18 + 9 + t];
                sW4[t][j] = wv;
            }
            if (p >= 128 && p < 260){
                int i = p - 128;
                int cell;
                if (i < 34)       cell = i;
                else if (i < 68)  cell = 33*34 + (i - 34);
                else if (i < 100) cell = (i - 68 + 1)*34;
                else              cell = (i - 100 + 1)*34 + 33;
                sP[cell] = make_float4(0.f, 0.f, 0.f, 0.f);
            }
            __syncthreads();
            int y = p >> 5, xx0 = p & 31;
            {
                float m0 = sMI[0], i0 = sMI[1], m1 = sMI[2], i1 = sMI[3];
                int cx0 = 2*g, cx1 = 2*g+1, cg0 = 64+2*g, cg1 = 65+2*g;
                float ga0 = gamma[cx0]*i0, be0 = beta[cx0] - m0*ga0;
                float ga1 = gamma[cx1]*i0, be1 = beta[cx1] - m0*ga1;
                float ga2 = gamma[cg0]*i1, be2 = beta[cg0] - m1*ga2;
                float ga3 = gamma[cg1]*i1, be3 = beta[cg1] - m1*ga3;
                float4 v;
                v.x = g_h[(b*MID + cx0)*P + p]*ga0 + be0;
                v.y = g_h[(b*MID + cx1)*P + p]*ga1 + be1;
                v.z = g_h[(b*MID + cg0)*P + p]*ga2 + be2;
                v.w = g_h[(b*MID + cg1)*P + p]*ga3 + be3;
                sP[(y+1)*34 + (xx0+1)] = v;
            }
            __syncthreads();
            float accx[4] = {0.f,0.f,0.f,0.f};
            float accg[4] = {0.f,0.f,0.f,0.f};
            #pragma unroll
            for (int ky = 0; ky < 3; ky++){
                #pragma unroll
                for (int kx = 0; kx < 3; kx++){
                    float4 v = sP[(y+ky)*34 + (xx0+kx)];
                    int t = ky*3 + kx;
                    #pragma unroll
                    for (int j = 0; j < 4; j++){
                        float4 W = sW4[t][j];
                        accx[j] = fmaf(v.x, W.x, fmaf(v.y, W.y, accx[j]));
                        accg[j] = fmaf(v.z, W.z, fmaf(v.w, W.w, accg[j]));
                    }
                }
            }
            #pragma unroll
            for (int j = 0; j < 4; j++){
                int c = 4*g + j;
                g_res[(b*MID + c)*P + p] = silu_f(accg[j]);
            }
            #pragma unroll
            for (int j = 0; j < 4; j++){
                int c = 4*g + j;
                float lo = (j < 2) ? accx[0] : accx[2];
                float hi = (j < 2) ? accx[1] : accx[3];
                float v = fmaf(lo, cw[c*2], fmaf(hi, cw[c*2+1], cb[c]));
                float uv = silu_f(v);
                g_u[(b*MID + c)*P + p] = uv;
                sU[j][p] = uv;
            }
            __syncthreads();
            const float4* xpr0 = (const float4*)(xproj + (wq*3 + 0)*P);
            const float4* xpr1 = (const float4*)(xproj + (wq*3 + 1)*P);
            const float4* xpr2 = (const float4*)(xproj + (wq*3 + 2)*P);
            const float4* u0p = (const float4*)sU[0];
            const float4* u1p = (const float4*)sU[1];
            const float4* u2p = (const float4*)sU[2];
            const float4* u3p = (const float4*)sU[3];
            float a00=0,a01=0,a02=0, a10=0,a11=0,a12=0, a20=0,a21=0,a22=0, a30=0,a31=0,a32=0;
            #pragma unroll
            for (int i = 0; i < 8; i++){
                int px = i*32 + lane;
                float4 w0 = xpr0[px], w1 = xpr1[px], w2 = xpr2[px];
                float4 u0 = u0p[px], u1 = u1p[px], u2 = u2p[px], u3 = u3p[px];
                a00 = fmaf(u0.x,w0.x,a00); a00 = fmaf(u0.y,w0.y,a00); a00 = fmaf(u0.z,w0.z,a00); a00 = fmaf(u0.w,w0.w,a00);
                a01 = fmaf(u0.x,w1.x,a01); a01 = fmaf(u0.y,w1.y,a01); a01 = fmaf(u0.z,w1.z,a01); a01 = fmaf(u0.w,w1.w,a01);
                a02 = fmaf(u0.x,w2.x,a02); a02 = fmaf(u0.y,w2.y,a02); a02 = fmaf(u0.z,w2.z,a02); a02 = fmaf(u0.w,w2.w,a02);
                a10 = fmaf(u1.x,w0.x,a10); a10 = fmaf(u1.y,w0.y,a10); a10 = fmaf(u1.z,w0.z,a10); a10 = fmaf(u1.w,w0.w,a10);
                a11 = fmaf(u1.x,w1.x,a11); a11 = fmaf(u1.y,w1.y,a11); a11 = fmaf(u1.z,w1.z,a11); a11 = fmaf(u1.w,w1.w,a11);
                a12 = fmaf(u1.x,w2.x,a12); a12 = fmaf(u1.y,w2.y,a12); a12 = fmaf(u1.z,w2.z,a12); a12 = fmaf(u1.w,w2.w,a12);
                a20 = fmaf(u2.x,w0.x,a20); a20 = fmaf(u2.y,w0.y,a20); a20 = fmaf(u2.z,w0.z,a20); a20 = fmaf(u2.w,w0.w,a20);
                a21 = fmaf(u2.x,w1.x,a21); a21 = fmaf(u2.y,w1.y,a21); a21 = fmaf(u2.z,w1.z,a21); a21 = fmaf(u2.w,w1.w,a21);
                a22 = fmaf(u2.x,w2.x,a22); a22 = fmaf(u2.y,w2.y,a22); a22 = fmaf(u2.z,w2.z,a22); a22 = fmaf(u2.w,w2.w,a22);
                a30 = fmaf(u3.x,w0.x,a30); a30 = fmaf(u3.y,w0.y,a30); a30 = fmaf(u3.z,w0.z,a30); a30 = fmaf(u3.w,w0.w,a30);
                a31 = fmaf(u3.x,w1.x,a31); a31 = fmaf(u3.y,w1.y,a31); a31 = fmaf(u3.z,w1.z,a31); a31 = fmaf(u3.w,w1.w,a31);
                a32 = fmaf(u3.x,w2.x,a32); a32 = fmaf(u3.y,w2.y,a32); a32 = fmaf(u3.z,w2.z,a32); a32 = fmaf(u3.w,w2.w,a32);
            }
            #pragma unroll
            for (int o = 16; o; o >>= 1){
                a00 += __shfl_xor_sync(0xffffffffu, a00, o); a01 += __shfl_xor_sync(0xffffffffu, a01, o);
                a02 += __shfl_xor_sync(0xffffffffu, a02, o); a10 += __shfl_xor_sync(0xffffffffu, a10, o);
                a11 += __shfl_xor_sync(0xffffffffu, a11, o); a12 += __shfl_xor_sync(0xffffffffu, a12, o);
                a20 += __shfl_xor_sync(0xffffffffu, a20, o); a21 += __shfl_xor_sync(0xffffffffu, a21, o);
                a22 += __shfl_xor_sync(0xffffffffu, a22, o); a30 += __shfl_xor_sync(0xffffffffu, a30, o);
                a31 += __shfl_xor_sync(0xffffffffu, a31, o); a32 += __shfl_xor_sync(0xffffffffu, a32, o);
            }
            if (lane == 0){
                int k = wq*3;
                float* r0 = g_xdbl + (b*LSEQ + 4*g + 0)*KDIM + k;
                float* r1 = g_xdbl + (b*LSEQ + 4*g + 1)*KDIM + k;
                float* r2 = g_xdbl + (b*LSEQ + 4*g + 2)*KDIM + k;
                float* r3 = g_xdbl + (b*LSEQ + 4*g + 3)*KDIM + k;
                r0[0]=a00; r0[1]=a01; r0[2]=a02;
                r1[0]=a10; r1[1]=a11; r1[2]=a12;
                r2[0]=a20; r2[1]=a21; r2[2]=a22;
                r3[0]=a30; r3[1]=a31; r3[2]=a32;
            }
        }
        grid_bar();

        // ---------- scan: delta GEMM + softplus + selective scan + combine + GN1 ----------
        {
            int dt = q;
            float*  sXd = sm;                    // [128][68]; later sY overlay
            float*  sWs = sm + 8704;             // [64][33]; later GN scratch
            float*  sB  = sm + 10816;            // [128][16]
            float*  sC  = sm + 12864;            // [128][16]
            float*  sDelta = sm + 14912;         // [128][33]
            float*  sUt    = sm + 19136;         // [128][33]
            float*  sY     = sm;                 // overlay

            for (int idx = tid; idx < 128*64; idx += 1024){
                int l = idx >> 6, k = idx & 63;
                sXd[l*68 + k] = g_xdbl[(b*LSEQ + l)*KDIM + k];
            }
            for (int idx = tid; idx < 128*16; idx += 1024){
                int l = idx >> 4, n = idx & 15;
                const float* row = g_xdbl + (b*LSEQ + l)*KDIM;
                sB[l*16 + n] = row[64 + n];
                sC[l*16 + n] = row[80 + n];
            }
            for (int idx = tid; idx < 32*64; idx += 1024){
                int dl = idx >> 6, r = idx & 63;
                sWs[r*33 + dl] = dtw[(dt*32 + dl)*64 + r];
            }
            for (int idx = tid; idx < 128*32; idx += 1024){
                int l = idx >> 5, dj = idx & 31;
                sUt[l*33 + dj] = g_u[(b*LSEQ + l)*P + dt*32 + dj];
            }
            __syncthreads();

            // delta GEMM: thread = (4 l's) x (dloc)
            {
                int dloc = tid & 31, lbase = (tid >> 5) << 2;
                float acc[4] = {0.f,0.f,0.f,0.f};
                #pragma unroll
                for (int k0 = 0; k0 < 64; k0 += 16){
                    float wv[16];
                    #pragma unroll
                    for (int j = 0; j < 16; j++) wv[j] = sWs[(k0+j)*33 + dloc];
                    #pragma unroll
                    for (int l = 0; l < 4; l++){
                        const float4* row = (const float4*)(sXd + (lbase+l)*68 + k0);
                        float4 x0 = row[0], x1 = row[1], x2 = row[2], x3 = row[3];
                        float a = acc[l];
                        a = fmaf(x0.x,wv[0],a);  a = fmaf(x0.y,wv[1],a);  a = fmaf(x0.z,wv[2],a);  a = fmaf(x0.w,wv[3],a);
                        a = fmaf(x1.x,wv[4],a);  a = fmaf(x1.y,wv[5],a);  a = fmaf(x1.z,wv[6],a);  a = fmaf(x1.w,wv[7],a);
                        a = fmaf(x2.x,wv[8],a);  a = fmaf(x2.y,wv[9],a);  a = fmaf(x2.z,wv[10],a); a = fmaf(x2.w,wv[11],a);
                        a = fmaf(x3.x,wv[12],a); a = fmaf(x3.y,wv[13],a); a = fmaf(x3.z,wv[14],a); a = fmaf(x3.w,wv[15],a);
                        acc[l] = a;
                    }
                }
                float bias = dtb[dt*32 + dloc];
                #pragma unroll
                for (int l = 0; l < 4; l++){
                    float xv = acc[l] + bias;
                    sDelta[(lbase+l)*33 + dloc] = fmaxf(xv, 0.f) + __logf(1.f + __expf(-fabsf(xv)));
                }
            }
            __syncthreads();

            // scan: first 512 threads: (dl = tid>>4) x (n = tid&15)
            if (tid < 512){
                int dl = tid >> 4;
                int n  = tid & 15;
                int d = dt*32 + dl;
                float An = -expf(alog[d*16 + n]);
                float Dd = dd[d];
                float cr = 0.f;
                #pragma unroll 4
                for (int l = 0; l < LSEQ; l++){
                    float td = sDelta[l*33 + dl];
                    float tu = sUt[l*33 + dl];
                    float du = td * tu;
                    cr = fmaf(__expf(td*An), cr, du*sB[l*16 + n]);
                    float yv = cr * sC[l*16 + n];
                    yv += __shfl_xor_sync(0xffffffffu, yv, 1);
                    yv += __shfl_xor_sync(0xffffffffu, yv, 2);
                    yv += __shfl_xor_sync(0xffffffffu, yv, 4);
                    yv += __shfl_xor_sync(0xffffffffu, yv, 8);
                    if (n == 0) sY[l*33 + dl] = fmaf(tu, Dd, yv);
                }
            }
            __syncthreads();

            // combine h += y*silu(res) and GN1 partial stats
            float s0 = 0.f, q0 = 0.f, s1 = 0.f, q1 = 0.f;
            for (int e = tid; e < 128*32; e += 1024){
                int l = e >> 5, dj = e & 31;
                int idx = (b*LSEQ + l)*P + dt*32 + dj;
                float h = fmaf(sY[l*33 + dj], g_res[idx], g_h[idx]);
                g_h[idx] = h;
                if (l < 64){ s0 += h; q0 += h*h; } else { s1 += h; q1 += h*h; }
            }
            if (blk == 0){
                #pragma unroll
                for (int o = 16; o; o >>= 1){
                    s0 += __shfl_xor_sync(0xffffffffu, s0, o);
                    q0 += __shfl_xor_sync(0xffffffffu, q0, o);
                    s1 += __shfl_xor_sync(0xffffffffu, s1, o);
                    q1 += __shfl_xor_sync(0xffffffffu, q1, o);
                }
                int wid = tid >> 5;
                __syncthreads();
                if ((tid & 31) == 0){
                    sWs[wid*4+0] = s0; sWs[wid*4+1] = q0; sWs[wid*4+2] = s1; sWs[wid*4+3] = q1;
                }
                __syncthreads();
                if (tid == 0){
                    float S0=0,Q0=0,S1=0,Q1=0;
                    #pragma unroll
                    for (int i = 0; i < 32; i++){ S0+=sWs[i*4]; Q0+=sWs[i*4+1]; S1+=sWs[i*4+2]; Q1+=sWs[i*4+3]; }
                    g_gnp1[(b*2 + 0)*32 + dt] = make_float2(S0, Q0);
                    g_gnp1[(b*2 + 1)*32 + dt] = make_float2(S1, Q1);
                }
            }
        }
        grid_bar();
    }

    // ================= conv_out + x8 bilinear upsample (4 planes per block) =================
    {
        #pragma unroll 1
        for (int i = 0; i < 4; i++){
            int plane = bid*4 + i;
            int pb = plane >> 7, oc = plane & 127;
            int g = oc >> 2;
            const float* hb = g_h + (size_t)(pb*MID + 4*g)*P;
            if (tid < 256){
                float w0 = wout[oc*4], w1 = wout[oc*4+1], w2 = wout[oc*4+2], w3 = wout[oc*4+3];
                float bias = bout[oc];
                float4 a  = ((const float4*)hb)[tid];
                float4 c1 = ((const float4*)(hb+P))[tid];
                float4 c2 = ((const float4*)(hb+2*P))[tid];
                float4 c3 = ((const float4*)(hb+3*P))[tid];
                float4 r;
                r.x = bias + a.x*w0 + c1.x*w1 + c2.x*w2 + c3.x*w3;
                r.y = bias + a.y*w0 + c1.y*w1 + c2.y*w2 + c3.y*w3;
                r.z = bias + a.z*w0 + c1.z*w1 + c2.z*w2 + c3.z*w3;
                r.w = bias + a.w*w0 + c1.w*w1 + c2.w*w2 + c3.w*w3;
                ((float4*)sCo)[tid] = r;
            }
            __syncthreads();
            int rx = tid & 63, ry = tid >> 6;   // ry 0..15
            int ox0 = rx * 4;
            float fx[4]; int ix0[4], ix1[4];
            #pragma unroll
            for (int j = 0; j < 4; j++){
                float sx = (ox0 + j + 0.5f) * 0.125f - 0.5f;
                int i0 = (int)floorf(sx);
                fx[j] = sx - (float)i0;
                ix0[j] = i0 < 0 ? 0 : i0;
                ix1[j] = (i0 + 1 > 31) ? 31 : i0 + 1;
            }
            float* obase = out + ((size_t)(pb*MID + oc))*256*256;
            #pragma unroll 4
            for (int t = 0; t < 16; t++){
                int oy = t*16 + ry;
                float sy = (oy + 0.5f) * 0.125f - 0.5f;
                int iy = (int)floorf(sy);
                float fy = sy - (float)iy;
                int iy0 = iy < 0 ? 0 : iy;
                int iy1 = (iy + 1 > 31) ? 31 : iy + 1;
                const float* r0 = sCo + iy0*32;
                const float* r1 = sCo + iy1*32;
                float4 v;
                float t0, t1;
                t0 = r0[ix0[0]] + (r0[ix1[0]] - r0[ix0[0]]) * fx[0];
                t1 = r1[ix0[0]] + (r1[ix1[0]] - r1[ix0[0]]) * fx[0];
                v.x = t0 + (t1 - t0) * fy;
                t0 = r0[ix0[1]] + (r0[ix1[1]] - r0[ix0[1]]) * fx[1];
                t1 = r1[ix0[1]] + (r1[ix1[1]] - r1[ix0[1]]) * fx[1];
                v.y = t0 + (t1 - t0) * fy;
                t0 = r0[ix0[2]] + (r0[ix1[2]] - r0[ix0[2]]) * fx[2];
                t1 = r1[ix0[2]] + (r1[ix1[2]] - r1[ix0[2]]) * fx[2];
                v.z = t0 + (t1 - t0) * fy;
                t0 = r0[ix0[3]] + (r0[ix1[3]] - r0[ix0[3]]) * fx[3];
                t1 = r1[ix0[3]] + (r1[ix1[3]] - r1[ix0[3]]) * fx[3];
                v.w = t0 + (t1 - t0) * fy;
                ((float4*)(obase + oy*256))[rx] = v;
            }
            __syncthreads();
        }
    }
}

// ---------------- host orchestration ----------------
extern "C" void kernel_launch(void* const* d_in, const int* in_sizes, int n_in,
                              void* d_out, int out_size){
    cudaFuncSetAttribute(k_mega, cudaFuncAttributeMaxDynamicSharedMemorySize, SCAN_SMEM_BYTES);

    k_mega<<<NBLK, 1024, SCAN_SMEM_BYTES>>>(
        (const float*)d_in[0],  (const float*)d_in[1],  (const float*)d_in[2],
        (const float*)d_in[3],  (const float*)d_in[4],  (const float*)d_in[5],
        (const float*)d_in[6],  (const float*)d_in[7],  (const float*)d_in[8],
        (const float*)d_in[9],  (const float*)d_in[10], (const float*)d_in[11],
        (const float*)d_in[12],
        (const float*)d_in[13], (const float*)d_in[14], (const float*)d_in[15],
        (const float*)d_in[16], (const float*)d_in[17], (const float*)d_in[18],
        (const float*)d_in[19], (const float*)d_in[20], (const float*)d_in[21],
        (const float*)d_in[22],
        (const float*)d_in[23], (const float*)d_in[24], (float*)d_out);
}

// round 9
// speedup vs baseline: 4.0510x; 1.1337x over previous
#include <cuda_runtime.h>
#include <cuda_bf16.h>
#include <math.h>

// ---------------- problem constants ----------------
#define BATCH 4
#define CIN   64
#define HH    256
#define WW    256
#define MID   128
#define P     1024
#define LSEQ  128
#define NST   16
#define KDIM  96
#define NBLK  128

// ---------------- device scratch ----------------
__device__ float  g_h[BATCH*MID*P];
__device__ float  g_u[BATCH*MID*P];
__device__ float  g_res[BATCH*MID*P];
__device__ __align__(16) float g_xdbl[BATCH*LSEQ*KDIM];
__device__ float2 g_gnp0[BATCH*2*16];
__device__ float2 g_gnp1[BATCH*2*32];

// grid barrier state (generation-based; monotonic across graph replays)
__device__ volatile unsigned g_gen = 0;
__device__ unsigned g_cnt = 0;

__device__ __forceinline__ void grid_bar(){
    __syncthreads();
    if (threadIdx.x == 0){
        __threadfence();
        unsigned old = g_gen;
        unsigned rank = atomicAdd(&g_cnt, 1u);
        if (rank == NBLK - 1){
            g_cnt = 0;
            __threadfence();
            atomicAdd((unsigned*)&g_gen, 1u);
        } else {
            while (g_gen == old) { }
        }
        __threadfence();
    }
    __syncthreads();
}

__device__ __forceinline__ float silu_f(float v){ return v / (1.f + __expf(-v)); }

#define SCAN_SMEM_FLOATS 23360
#define SCAN_SMEM_BYTES  (SCAN_SMEM_FLOATS*4)

// =========================== MEGA KERNEL ===========================
__global__ void __launch_bounds__(1024, 1)
k_mega(const float* __restrict__ x, const float* __restrict__ w_in, const float* __restrict__ b_in,
       const float* __restrict__ gn0g, const float* __restrict__ gn0b, const float* __restrict__ ip0w,
       const float* __restrict__ c0w,  const float* __restrict__ c0b,  const float* __restrict__ xp0,
       const float* __restrict__ dt0w, const float* __restrict__ dt0b, const float* __restrict__ al0,
       const float* __restrict__ dd0,
       const float* __restrict__ gn1g, const float* __restrict__ gn1b, const float* __restrict__ ip1w,
       const float* __restrict__ c1w,  const float* __restrict__ c1b,  const float* __restrict__ xp1,
       const float* __restrict__ dt1w, const float* __restrict__ dt1b, const float* __restrict__ al1,
       const float* __restrict__ dd1,
       const float* __restrict__ wout, const float* __restrict__ bout, float* __restrict__ out)
{
    extern __shared__ float sm[];   // scan workspace (93 KB)
    __shared__ __align__(16) float4 sP[34*34];
    __shared__ __align__(16) float  sU[4][P];
    __shared__ __align__(16) float4 sW4[9][4];
    __shared__ float sMI[4];
    __shared__ float swdc[4][2][8][8];
    __shared__ float red[64];
    __shared__ __align__(16) float sCo[1024];

    int bid = blockIdx.x;
    int b = bid >> 5, q = bid & 31;     // q = group/dtile index
    int tid = threadIdx.x;

    // ================= phase 0: downconv (8x8 stride 8) + GN0 stats =================
    {
        int g = q;
        int ty = tid >> 5, tx = tid & 31;
        if (tid < 512){
            int oc4 = tid >> 7, rem = tid & 127;
            swdc[oc4][rem>>6][(rem>>3)&7][rem&7] = w_in[(4*g + oc4)*128 + rem];
        }
        __syncthreads();
        float acc0=0.f, acc1=0.f, acc2=0.f, acc3=0.f;
        #pragma unroll
        for (int ic = 0; ic < 2; ic++){
            const float* xb = x + (((size_t)b*CIN + 2*g + ic)*HH + ty*8)*WW + tx*8;
            #pragma unroll
            for (int ky = 0; ky < 8; ky++){
                const float4* r = (const float4*)(xb + ky*WW);
                float4 v0 = r[0], v1 = r[1];
                float xv[8] = {v0.x,v0.y,v0.z,v0.w,v1.x,v1.y,v1.z,v1.w};
                #pragma unroll
                for (int kx = 0; kx < 8; kx++){
                    float xvv = xv[kx];
                    acc0 = fmaf(xvv, swdc[0][ic][ky][kx], acc0);
                    acc1 = fmaf(xvv, swdc[1][ic][ky][kx], acc1);
                    acc2 = fmaf(xvv, swdc[2][ic][ky][kx], acc2);
                    acc3 = fmaf(xvv, swdc[3][ic][ky][kx], acc3);
                }
            }
        }
        acc0 += b_in[4*g+0]; acc1 += b_in[4*g+1]; acc2 += b_in[4*g+2]; acc3 += b_in[4*g+3];
        int p = ty*32 + tx;
        g_h[(b*MID + 4*g + 0)*P + p] = acc0;
        g_h[(b*MID + 4*g + 1)*P + p] = acc1;
        g_h[(b*MID + 4*g + 2)*P + p] = acc2;
        g_h[(b*MID + 4*g + 3)*P + p] = acc3;
        float s  = acc0 + acc1 + acc2 + acc3;
        float s2 = acc0*acc0 + acc1*acc1 + acc2*acc2 + acc3*acc3;
        #pragma unroll
        for (int o = 16; o; o >>= 1){
            s  += __shfl_xor_sync(0xffffffffu, s,  o);
            s2 += __shfl_xor_sync(0xffffffffu, s2, o);
        }
        int wid = tid >> 5, lid = tid & 31;
        if (lid == 0){ red[wid] = s; red[32+wid] = s2; }
        __syncthreads();
        if (tid < 32){
            s = red[tid]; s2 = red[32+tid];
            #pragma unroll
            for (int o = 16; o; o >>= 1){
                s  += __shfl_xor_sync(0xffffffffu, s,  o);
                s2 += __shfl_xor_sync(0xffffffffu, s2, o);
            }
            if (tid == 0){
                int grp = g >> 4;
                g_gnp0[(b*2 + grp)*16 + (g & 15)] = make_float2(s, s2);
            }
        }
    }
    grid_bar();

    // ================= mamba blocks =================
    #pragma unroll 1
    for (int blk = 0; blk < 2; blk++){
        const float* w     = blk ? ip1w : ip0w;
        const float* cw    = blk ? c1w  : c0w;
        const float* cb    = blk ? c1b  : c0b;
        const float* gamma = blk ? gn1g : gn0g;
        const float* beta  = blk ? gn1b : gn0b;
        const float* xproj = blk ? xp1  : xp0;
        const float* dtw   = blk ? dt1w : dt0w;
        const float* dtb   = blk ? dt1b : dt0b;
        const float* alog  = blk ? al1  : al0;
        const float* dd    = blk ? dd1  : dd0;

        // ---------- inproj: GN + 3x3 conv + conv0+SiLU + gate + x_dbl ----------
        {
            int g = q;
            int p = tid;
            int wq = p >> 5, lane = p & 31;
            int cx0 = 2*g, cx1 = 2*g+1, cg0 = 64+2*g, cg1 = 65+2*g;
            // prefetch residual loads (independent of stats)
            float hv0 = g_h[(b*MID + cx0)*P + p];
            float hv1 = g_h[(b*MID + cx1)*P + p];
            float hv2 = g_h[(b*MID + cg0)*P + p];
            float hv3 = g_h[(b*MID + cg1)*P + p];
            if (wq < 2){
                int npart = blk ? 32 : 16;
                float2 v = make_float2(0.f, 0.f);
                if (lane < npart) v = blk ? g_gnp1[(b*2+wq)*32 + lane] : g_gnp0[(b*2+wq)*16 + lane];
                float s = v.x, s2v = v.y;
                #pragma unroll
                for (int o = 16; o; o >>= 1){
                    s   += __shfl_xor_sync(0xffffffffu, s,   o);
                    s2v += __shfl_xor_sync(0xffffffffu, s2v, o);
                }
                if (lane == 0){
                    float mean = s * (1.f/65536.f);
                    float var  = s2v * (1.f/65536.f) - mean*mean;
                    sMI[wq*2]   = mean;
                    sMI[wq*2+1] = rsqrtf(var + 1e-5f);
                }
            }
            if (p >= 64 && p < 100){
                int idx = p - 64;
                int t = idx / 4, j = idx & 3;
                float4 wv;
                wv.x = w[(4*g + j)*18 +     t];
                wv.y = w[(4*g + j)*18 + 9 + t];
                wv.z = w[(128 + 4*g + j)*18 +     t];
                wv.w = w[(128 + 4*g + j)*18 + 9 + t];
                sW4[t][j] = wv;
            }
            if (p >= 128 && p < 260){
                int i = p - 128;
                int cell;
                if (i < 34)       cell = i;
                else if (i < 68)  cell = 33*34 + (i - 34);
                else if (i < 100) cell = (i - 68 + 1)*34;
                else              cell = (i - 100 + 1)*34 + 33;
                sP[cell] = make_float4(0.f, 0.f, 0.f, 0.f);
            }
            __syncthreads();
            int y = p >> 5, xx0 = p & 31;
            {
                float m0 = sMI[0], i0 = sMI[1], m1 = sMI[2], i1 = sMI[3];
                float ga0 = gamma[cx0]*i0, be0 = beta[cx0] - m0*ga0;
                float ga1 = gamma[cx1]*i0, be1 = beta[cx1] - m0*ga1;
                float ga2 = gamma[cg0]*i1, be2 = beta[cg0] - m1*ga2;
                float ga3 = gamma[cg1]*i1, be3 = beta[cg1] - m1*ga3;
                float4 v;
                v.x = hv0*ga0 + be0;
                v.y = hv1*ga1 + be1;
                v.z = hv2*ga2 + be2;
                v.w = hv3*ga3 + be3;
                sP[(y+1)*34 + (xx0+1)] = v;
            }
            __syncthreads();
            float accx[4] = {0.f,0.f,0.f,0.f};
            float accg[4] = {0.f,0.f,0.f,0.f};
            #pragma unroll
            for (int ky = 0; ky < 3; ky++){
                #pragma unroll
                for (int kx = 0; kx < 3; kx++){
                    float4 v = sP[(y+ky)*34 + (xx0+kx)];
                    int t = ky*3 + kx;
                    #pragma unroll
                    for (int j = 0; j < 4; j++){
                        float4 W = sW4[t][j];
                        accx[j] = fmaf(v.x, W.x, fmaf(v.y, W.y, accx[j]));
                        accg[j] = fmaf(v.z, W.z, fmaf(v.w, W.w, accg[j]));
                    }
                }
            }
            #pragma unroll
            for (int j = 0; j < 4; j++){
                int c = 4*g + j;
                g_res[(b*MID + c)*P + p] = silu_f(accg[j]);
            }
            #pragma unroll
            for (int j = 0; j < 4; j++){
                int c = 4*g + j;
                float lo = (j < 2) ? accx[0] : accx[2];
                float hi = (j < 2) ? accx[1] : accx[3];
                float v = fmaf(lo, cw[c*2], fmaf(hi, cw[c*2+1], cb[c]));
                float uv = silu_f(v);
                g_u[(b*MID + c)*P + p] = uv;
                sU[j][p] = uv;
            }
            __syncthreads();
            const float4* xpr0 = (const float4*)(xproj + (wq*3 + 0)*P);
            const float4* xpr1 = (const float4*)(xproj + (wq*3 + 1)*P);
            const float4* xpr2 = (const float4*)(xproj + (wq*3 + 2)*P);
            const float4* u0p = (const float4*)sU[0];
            const float4* u1p = (const float4*)sU[1];
            const float4* u2p = (const float4*)sU[2];
            const float4* u3p = (const float4*)sU[3];
            float a00=0,a01=0,a02=0, a10=0,a11=0,a12=0, a20=0,a21=0,a22=0, a30=0,a31=0,a32=0;
            #pragma unroll
            for (int i = 0; i < 8; i++){
                int px = i*32 + lane;
                float4 w0 = xpr0[px], w1 = xpr1[px], w2 = xpr2[px];
                float4 u0 = u0p[px], u1 = u1p[px], u2 = u2p[px], u3 = u3p[px];
                a00 = fmaf(u0.x,w0.x,a00); a00 = fmaf(u0.y,w0.y,a00); a00 = fmaf(u0.z,w0.z,a00); a00 = fmaf(u0.w,w0.w,a00);
                a01 = fmaf(u0.x,w1.x,a01); a01 = fmaf(u0.y,w1.y,a01); a01 = fmaf(u0.z,w1.z,a01); a01 = fmaf(u0.w,w1.w,a01);
                a02 = fmaf(u0.x,w2.x,a02); a02 = fmaf(u0.y,w2.y,a02); a02 = fmaf(u0.z,w2.z,a02); a02 = fmaf(u0.w,w2.w,a02);
                a10 = fmaf(u1.x,w0.x,a10); a10 = fmaf(u1.y,w0.y,a10); a10 = fmaf(u1.z,w0.z,a10); a10 = fmaf(u1.w,w0.w,a10);
                a11 = fmaf(u1.x,w1.x,a11); a11 = fmaf(u1.y,w1.y,a11); a11 = fmaf(u1.z,w1.z,a11); a11 = fmaf(u1.w,w1.w,a11);
                a12 = fmaf(u1.x,w2.x,a12); a12 = fmaf(u1.y,w2.y,a12); a12 = fmaf(u1.z,w2.z,a12); a12 = fmaf(u1.w,w2.w,a12);
                a20 = fmaf(u2.x,w0.x,a20); a20 = fmaf(u2.y,w0.y,a20); a20 = fmaf(u2.z,w0.z,a20); a20 = fmaf(u2.w,w0.w,a20);
                a21 = fmaf(u2.x,w1.x,a21); a21 = fmaf(u2.y,w1.y,a21); a21 = fmaf(u2.z,w1.z,a21); a21 = fmaf(u2.w,w1.w,a21);
                a22 = fmaf(u2.x,w2.x,a22); a22 = fmaf(u2.y,w2.y,a22); a22 = fmaf(u2.z,w2.z,a22); a22 = fmaf(u2.w,w2.w,a22);
                a30 = fmaf(u3.x,w0.x,a30); a30 = fmaf(u3.y,w0.y,a30); a30 = fmaf(u3.z,w0.z,a30); a30 = fmaf(u3.w,w0.w,a30);
                a31 = fmaf(u3.x,w1.x,a31); a31 = fmaf(u3.y,w1.y,a31); a31 = fmaf(u3.z,w1.z,a31); a31 = fmaf(u3.w,w1.w,a31);
                a32 = fmaf(u3.x,w2.x,a32); a32 = fmaf(u3.y,w2.y,a32); a32 = fmaf(u3.z,w2.z,a32); a32 = fmaf(u3.w,w2.w,a32);
            }
            #pragma unroll
            for (int o = 16; o; o >>= 1){
                a00 += __shfl_xor_sync(0xffffffffu, a00, o); a01 += __shfl_xor_sync(0xffffffffu, a01, o);
                a02 += __shfl_xor_sync(0xffffffffu, a02, o); a10 += __shfl_xor_sync(0xffffffffu, a10, o);
                a11 += __shfl_xor_sync(0xffffffffu, a11, o); a12 += __shfl_xor_sync(0xffffffffu, a12, o);
                a20 += __shfl_xor_sync(0xffffffffu, a20, o); a21 += __shfl_xor_sync(0xffffffffu, a21, o);
                a22 += __shfl_xor_sync(0xffffffffu, a22, o); a30 += __shfl_xor_sync(0xffffffffu, a30, o);
                a31 += __shfl_xor_sync(0xffffffffu, a31, o); a32 += __shfl_xor_sync(0xffffffffu, a32, o);
            }
            if (lane == 0){
                int k = wq*3;
                float* r0 = g_xdbl + (b*LSEQ + 4*g + 0)*KDIM + k;
                float* r1 = g_xdbl + (b*LSEQ + 4*g + 1)*KDIM + k;
                float* r2 = g_xdbl + (b*LSEQ + 4*g + 2)*KDIM + k;
                float* r3 = g_xdbl + (b*LSEQ + 4*g + 3)*KDIM + k;
                r0[0]=a00; r0[1]=a01; r0[2]=a02;
                r1[0]=a10; r1[1]=a11; r1[2]=a12;
                r2[0]=a20; r2[1]=a21; r2[2]=a22;
                r3[0]=a30; r3[1]=a31; r3[2]=a32;
            }
        }
        grid_bar();

        // ---------- scan: delta GEMM + softplus + selective scan + combine + GN1 ----------
        {
            int dt = q;
            float*  sXd = sm;                    // [128][68]; later sY overlay
            float*  sWs = sm + 8704;             // [64][33]; later GN scratch
            float*  sB  = sm + 10816;            // [128][16]
            float*  sC  = sm + 12864;            // [128][16]
            float*  sDelta = sm + 14912;         // [128][33]
            float*  sUt    = sm + 19136;         // [128][33]
            float*  sY     = sm;                 // overlay

            for (int idx = tid; idx < 128*64; idx += 1024){
                int l = idx >> 6, k = idx & 63;
                sXd[l*68 + k] = g_xdbl[(b*LSEQ + l)*KDIM + k];
            }
            for (int idx = tid; idx < 128*16; idx += 1024){
                int l = idx >> 4, n = idx & 15;
                const float* row = g_xdbl + (b*LSEQ + l)*KDIM;
                sB[l*16 + n] = row[64 + n];
                sC[l*16 + n] = row[80 + n];
            }
            for (int idx = tid; idx < 32*64; idx += 1024){
                int dl = idx >> 6, r = idx & 63;
                sWs[r*33 + dl] = dtw[(dt*32 + dl)*64 + r];
            }
            for (int idx = tid; idx < 128*32; idx += 1024){
                int l = idx >> 5, dj = idx & 31;
                sUt[l*33 + dj] = g_u[(b*LSEQ + l)*P + dt*32 + dj];
            }
            __syncthreads();

            // delta GEMM: thread = (4 l's) x (dloc)
            {
                int dloc = tid & 31, lbase = (tid >> 5) << 2;
                float acc[4] = {0.f,0.f,0.f,0.f};
                #pragma unroll
                for (int k0 = 0; k0 < 64; k0 += 16){
                    float wv[16];
                    #pragma unroll
                    for (int j = 0; j < 16; j++) wv[j] = sWs[(k0+j)*33 + dloc];
                    #pragma unroll
                    for (int l = 0; l < 4; l++){
                        const float4* row = (const float4*)(sXd + (lbase+l)*68 + k0);
                        float4 x0 = row[0], x1 = row[1], x2 = row[2], x3 = row[3];
                        float a = acc[l];
                        a = fmaf(x0.x,wv[0],a);  a = fmaf(x0.y,wv[1],a);  a = fmaf(x0.z,wv[2],a);  a = fmaf(x0.w,wv[3],a);
                        a = fmaf(x1.x,wv[4],a);  a = fmaf(x1.y,wv[5],a);  a = fmaf(x1.z,wv[6],a);  a = fmaf(x1.w,wv[7],a);
                        a = fmaf(x2.x,wv[8],a);  a = fmaf(x2.y,wv[9],a);  a = fmaf(x2.z,wv[10],a); a = fmaf(x2.w,wv[11],a);
                        a = fmaf(x3.x,wv[12],a); a = fmaf(x3.y,wv[13],a); a = fmaf(x3.z,wv[14],a); a = fmaf(x3.w,wv[15],a);
                        acc[l] = a;
                    }
                }
                float bias = dtb[dt*32 + dloc];
                #pragma unroll
                for (int l = 0; l < 4; l++){
                    float xv = acc[l] + bias;
                    sDelta[(lbase+l)*33 + dloc] = fmaxf(xv, 0.f) + __logf(1.f + __expf(-fabsf(xv)));
                }
            }
            __syncthreads();

            // scan: 128 threads, thread = (dl = tid>>2) x (n-quad = (tid&3)*4)
            if (tid < 128){
                int dl = tid >> 2;
                int nq = (tid & 3) * 4;
                int d = dt*32 + dl;
                float An0 = -expf(alog[d*16 + nq + 0]);
                float An1 = -expf(alog[d*16 + nq + 1]);
                float An2 = -expf(alog[d*16 + nq + 2]);
                float An3 = -expf(alog[d*16 + nq + 3]);
                float Dd = dd[d];
                float cr0 = 0.f, cr1 = 0.f, cr2 = 0.f, cr3 = 0.f;
                #pragma unroll 4
                for (int l = 0; l < LSEQ; l++){
                    float td = sDelta[l*33 + dl];
                    float tu = sUt[l*33 + dl];
                    float du = td * tu;
                    float4 B4 = *(const float4*)&sB[l*16 + nq];
                    float4 C4 = *(const float4*)&sC[l*16 + nq];
                    cr0 = fmaf(__expf(td*An0), cr0, du*B4.x);
                    cr1 = fmaf(__expf(td*An1), cr1, du*B4.y);
                    cr2 = fmaf(__expf(td*An2), cr2, du*B4.z);
                    cr3 = fmaf(__expf(td*An3), cr3, du*B4.w);
                    float yv = fmaf(cr0, C4.x, fmaf(cr1, C4.y, fmaf(cr2, C4.z, cr3*C4.w)));
                    yv += __shfl_xor_sync(0xffffffffu, yv, 1);
                    yv += __shfl_xor_sync(0xffffffffu, yv, 2);
                    if ((tid & 3) == 0) sY[l*33 + dl] = fmaf(tu, Dd, yv);
                }
            }
            __syncthreads();

            // combine h += y*silu(res) and GN1 partial stats
            float s0 = 0.f, q0 = 0.f, s1 = 0.f, q1 = 0.f;
            for (int e = tid; e < 128*32; e += 1024){
                int l = e >> 5, dj = e & 31;
                int idx = (b*LSEQ + l)*P + dt*32 + dj;
                float h = fmaf(sY[l*33 + dj], g_res[idx], g_h[idx]);
                g_h[idx] = h;
                if (l < 64){ s0 += h; q0 += h*h; } else { s1 += h; q1 += h*h; }
            }
            if (blk == 0){
                #pragma unroll
                for (int o = 16; o; o >>= 1){
                    s0 += __shfl_xor_sync(0xffffffffu, s0, o);
                    q0 += __shfl_xor_sync(0xffffffffu, q0, o);
                    s1 += __shfl_xor_sync(0xffffffffu, s1, o);
                    q1 += __shfl_xor_sync(0xffffffffu, q1, o);
                }
                int wid = tid >> 5;
                __syncthreads();
                if ((tid & 31) == 0){
                    sWs[wid*4+0] = s0; sWs[wid*4+1] = q0; sWs[wid*4+2] = s1; sWs[wid*4+3] = q1;
                }
                __syncthreads();
                if (tid == 0){
                    float S0=0,Q0=0,S1=0,Q1=0;
                    #pragma unroll
                    for (int i = 0; i < 32; i++){ S0+=sWs[i*4]; Q0+=sWs[i*4+1]; S1+=sWs[i*4+2]; Q1+=sWs[i*4+3]; }
                    g_gnp1[(b*2 + 0)*32 + dt] = make_float2(S0, Q0);
                    g_gnp1[(b*2 + 1)*32 + dt] = make_float2(S1, Q1);
                }
            }
        }
        grid_bar();
    }

    // ================= conv_out + x8 bilinear upsample (4 planes per block) =================
    {
        // thread = one output float4 per row-slot: lane64 = float4 col, ry2 = row slot
        int lane64 = tid & 63;
        int ry2 = tid >> 6;                 // 0..15
        int ii = lane64 >> 1;               // source col 0..31
        int jh = lane64 & 1;                // which half of the 8-wide output group
        int ca = jh ? ii : (ii > 0 ? ii - 1 : 0);
        int cbx = jh ? (ii < 31 ? ii + 1 : 31) : ii;
        float wxa = jh ? 0.0625f : 0.5625f;
        #pragma unroll 1
        for (int i = 0; i < 4; i++){
            int plane = bid*4 + i;
            int pb = plane >> 7, oc = plane & 127;
            int g = oc >> 2;
            const float* hb = g_h + (size_t)(pb*MID + 4*g)*P;
            if (tid < 256){
                float w0 = wout[oc*4], w1 = wout[oc*4+1], w2 = wout[oc*4+2], w3 = wout[oc*4+3];
                float bias = bout[oc];
                float4 a  = ((const float4*)hb)[tid];
                float4 c1 = ((const float4*)(hb+P))[tid];
                float4 c2 = ((const float4*)(hb+2*P))[tid];
                float4 c3 = ((const float4*)(hb+3*P))[tid];
                float4 r;
                r.x = bias + a.x*w0 + c1.x*w1 + c2.x*w2 + c3.x*w3;
                r.y = bias + a.y*w0 + c1.y*w1 + c2.y*w2 + c3.y*w3;
                r.z = bias + a.z*w0 + c1.z*w1 + c2.z*w2 + c3.z*w3;
                r.w = bias + a.w*w0 + c1.w*w1 + c2.w*w2 + c3.w*w3;
                ((float4*)sCo)[tid] = r;
            }
            __syncthreads();
            float* obase = out + ((size_t)(pb*MID + oc))*256*256;
            #pragma unroll 4
            for (int t = 0; t < 16; t++){
                int oy = t*16 + ry2;
                float sy = (oy + 0.5f) * 0.125f - 0.5f;
                int iy = (int)floorf(sy);
                float fy = sy - (float)iy;
                int iy0 = iy < 0 ? 0 : iy;
                int iy1 = (iy + 1 > 31) ? 31 : iy + 1;
                const float* r0 = sCo + iy0*32;
                const float* r1 = sCo + iy1*32;
                float a0 = r0[ca], a1 = r1[ca];
                float b0 = r0[cbx], b1 = r1[cbx];
                float va = a0 + (a1 - a0) * fy;
                float vb = b0 + (b1 - b0) * fy;
                float dab = vb - va;
                float4 v;
                v.x = fmaf(dab, wxa,            va);
                v.y = fmaf(dab, wxa + 0.125f,   va);
                v.z = fmaf(dab, wxa + 0.25f,    va);
                v.w = fmaf(dab, wxa + 0.375f,   va);
                ((float4*)(obase + oy*256))[lane64] = v;
            }
            __syncthreads();
        }
    }
}

// ---------------- host orchestration ----------------
extern "C" void kernel_launch(void* const* d_in, const int* in_sizes, int n_in,
                              void* d_out, int out_size){
    cudaFuncSetAttribute(k_mega, cudaFuncAttributeMaxDynamicSharedMemorySize, SCAN_SMEM_BYTES);

    k_mega<<<NBLK, 1024, SCAN_SMEM_BYTES>>>(
        (const float*)d_in[0],  (const float*)d_in[1],  (const float*)d_in[2],
        (const float*)d_in[3],  (const float*)d_in[4],  (const float*)d_in[5],
        (const float*)d_in[6],  (const float*)d_in[7],  (const float*)d_in[8],
        (const float*)d_in[9],  (const float*)d_in[10], (const float*)d_in[11],
        (const float*)d_in[12],
        (const float*)d_in[13], (const float*)d_in[14], (const float*)d_in[15],
        (const float*)d_in[16], (const float*)d_in[17], (const float*)d_in[18],
        (const float*)d_in[19], (const float*)d_in[20], (const float*)d_in[21],
        (const float*)d_in[22],
        (const float*)d_in[23], (const float*)d_in[24], (float*)d_out);
}